// round 1
// baseline (speedup 1.0000x reference)
#include <cuda_runtime.h>
#include <cuda_bf16.h>

// Problem constants
static constexpr int Bq    = 2;
static constexpr int Nseq  = 2048;
static constexpr int Dm    = 1024;
static constexpr int Hh    = 16;
static constexpr int HDim  = 64;      // head dim
static constexpr int Mrows = Bq * Nseq;  // 4096
static constexpr float EPSf = 1e-5f;

// Scratch (allocation-free rule: device globals)
__device__ float g_Q[Mrows * Dm];
__device__ float g_K[Mrows * Dm];
__device__ float g_V[Mrows * Dm];
__device__ float g_C[Mrows * Dm];

// ---------------------------------------------------------------------------
// SGEMM (NT): C[M,Nn] = X[M,K] @ W[Nn,K]^T + bias[Nn]
// 128x128 tile, BK=8, 256 threads, 8x8 per-thread microtile.
// All dims are multiples of 128 in this problem; no bounds checks.
// ---------------------------------------------------------------------------
__global__ void __launch_bounds__(256) sgemm_nt_bias(
    const float* __restrict__ X, const float* __restrict__ W,
    const float* __restrict__ bias, float* __restrict__ C,
    int M, int Nn, int K)
{
    __shared__ float As[8][128];
    __shared__ float Bs[8][128];

    const int tid  = threadIdx.x;
    const int tx   = tid & 15;
    const int ty   = tid >> 4;
    const int lrow = tid >> 1;          // 0..127
    const int lc4  = (tid & 1) << 2;    // 0 or 4

    const float* Xg = X + (size_t)(blockIdx.y * 128 + lrow) * K + lc4;
    const float* Wg = W + (size_t)(blockIdx.x * 128 + lrow) * K + lc4;

    float acc[8][8];
#pragma unroll
    for (int i = 0; i < 8; i++)
#pragma unroll
        for (int j = 0; j < 8; j++) acc[i][j] = 0.f;

    for (int k0 = 0; k0 < K; k0 += 8) {
        float4 xa = *(const float4*)(Xg + k0);
        float4 wb = *(const float4*)(Wg + k0);
        As[lc4 + 0][lrow] = xa.x; As[lc4 + 1][lrow] = xa.y;
        As[lc4 + 2][lrow] = xa.z; As[lc4 + 3][lrow] = xa.w;
        Bs[lc4 + 0][lrow] = wb.x; Bs[lc4 + 1][lrow] = wb.y;
        Bs[lc4 + 2][lrow] = wb.z; Bs[lc4 + 3][lrow] = wb.w;
        __syncthreads();
#pragma unroll
        for (int kk = 0; kk < 8; kk++) {
            float4 a0 = *(const float4*)&As[kk][ty * 4];
            float4 a1 = *(const float4*)&As[kk][ty * 4 + 64];
            float4 b0 = *(const float4*)&Bs[kk][tx * 4];
            float4 b1 = *(const float4*)&Bs[kk][tx * 4 + 64];
            float a[8] = {a0.x, a0.y, a0.z, a0.w, a1.x, a1.y, a1.z, a1.w};
            float b[8] = {b0.x, b0.y, b0.z, b0.w, b1.x, b1.y, b1.z, b1.w};
#pragma unroll
            for (int i = 0; i < 8; i++)
#pragma unroll
                for (int j = 0; j < 8; j++)
                    acc[i][j] = fmaf(a[i], b[j], acc[i][j]);
        }
        __syncthreads();
    }

#pragma unroll
    for (int i = 0; i < 8; i++) {
        int row = blockIdx.y * 128 + ((i < 4) ? (ty * 4 + i) : (64 + ty * 4 + i - 4));
#pragma unroll
        for (int jj = 0; jj < 2; jj++) {
            int col = blockIdx.x * 128 + ((jj == 0) ? (tx * 4) : (64 + tx * 4));
            float4 o;
            o.x = acc[i][jj * 4 + 0] + bias[col + 0];
            o.y = acc[i][jj * 4 + 1] + bias[col + 1];
            o.z = acc[i][jj * 4 + 2] + bias[col + 2];
            o.w = acc[i][jj * 4 + 3] + bias[col + 3];
            *(float4*)&C[(size_t)row * Nn + col] = o;
        }
    }
}

// ---------------------------------------------------------------------------
// Per-head LayerNorm over HD=64 contiguous elements, in place.
// One warp per (row, head). Biased variance (jnp.var, ddof=0).
// ---------------------------------------------------------------------------
__global__ void __launch_bounds__(256) ln_heads(
    float* __restrict__ X, const float* __restrict__ gamma,
    const float* __restrict__ beta, int total_groups)
{
    int wid  = (blockIdx.x * blockDim.x + threadIdx.x) >> 5;
    int lane = threadIdx.x & 31;
    if (wid >= total_groups) return;
    int row = wid >> 4;   // / Hh
    int h   = wid & 15;
    float* p = X + (size_t)row * Dm + h * HDim;

    float x0 = p[lane];
    float x1 = p[lane + 32];
    float s  = x0 + x1;
    float ss = x0 * x0 + x1 * x1;
#pragma unroll
    for (int o = 16; o > 0; o >>= 1) {
        s  += __shfl_xor_sync(0xffffffffu, s,  o);
        ss += __shfl_xor_sync(0xffffffffu, ss, o);
    }
    float mean = s * (1.f / 64.f);
    float var  = ss * (1.f / 64.f) - mean * mean;
    float r    = rsqrtf(var + EPSf);
    p[lane]      = (x0 - mean) * r * gamma[lane]      + beta[lane];
    p[lane + 32] = (x1 - mean) * r * gamma[lane + 32] + beta[lane + 32];
}

// ---------------------------------------------------------------------------
// Flash-style attention, fp32. Block = one (b,h) x 64-query tile.
// Iterates 64-key tiles with online softmax. 256 threads, 4x4 per-thread
// microtiles for both S=QK^T and O+=PV.
// Dynamic smem: Qs/Ks/Vs/Ss [64][68] + m/l/alpha [64] each = 70400 B.
// ---------------------------------------------------------------------------
static constexpr int ATTN_LD   = 68;
static constexpr int ATTN_SMEM = (4 * 64 * ATTN_LD + 3 * 64) * (int)sizeof(float);

__global__ void __launch_bounds__(256) attn_kernel(
    const float* __restrict__ Q, const float* __restrict__ K,
    const float* __restrict__ V, float* __restrict__ O)
{
    extern __shared__ float sm[];
    float (*Qs)[ATTN_LD] = (float(*)[ATTN_LD])(sm);
    float (*Ks)[ATTN_LD] = (float(*)[ATTN_LD])(sm + 1 * 64 * ATTN_LD);
    float (*Vs)[ATTN_LD] = (float(*)[ATTN_LD])(sm + 2 * 64 * ATTN_LD);
    float (*Ss)[ATTN_LD] = (float(*)[ATTN_LD])(sm + 3 * 64 * ATTN_LD);
    float* m_s  = sm + 4 * 64 * ATTN_LD;
    float* l_s  = m_s + 64;
    float* al_s = l_s + 64;

    const int tid = threadIdx.x;
    const int tx  = tid & 15;
    const int ty  = tid >> 4;
    const int bh  = blockIdx.y;
    const int b   = bh >> 4;
    const int h   = bh & 15;
    const int q0  = blockIdx.x * 64;
    const size_t headoff = (size_t)b * Nseq * Dm + (size_t)h * HDim;
    const float scale = 0.125f;  // 1/sqrt(64)

    // Load Q tile [64][64]
    for (int i = tid; i < 64 * 16; i += 256) {
        int r  = i >> 4;
        int c4 = (i & 15) << 2;
        *(float4*)&Qs[r][c4] = *(const float4*)&Q[headoff + (size_t)(q0 + r) * Dm + c4];
    }
    if (tid < 64) { m_s[tid] = -1e30f; l_s[tid] = 0.f; }

    float acc[4][4];
#pragma unroll
    for (int i = 0; i < 4; i++)
#pragma unroll
        for (int j = 0; j < 4; j++) acc[i][j] = 0.f;

    __syncthreads();

    for (int kt = 0; kt < Nseq; kt += 64) {
        // Load K,V tiles [64][64]
        for (int i = tid; i < 64 * 16; i += 256) {
            int r  = i >> 4;
            int c4 = (i & 15) << 2;
            *(float4*)&Ks[r][c4] = *(const float4*)&K[headoff + (size_t)(kt + r) * Dm + c4];
            *(float4*)&Vs[r][c4] = *(const float4*)&V[headoff + (size_t)(kt + r) * Dm + c4];
        }
        __syncthreads();

        // S = scale * Qs @ Ks^T : thread (ty,tx) owns rows ty*4.. cols tx*4..
        {
            float s[4][4];
#pragma unroll
            for (int i = 0; i < 4; i++)
#pragma unroll
                for (int j = 0; j < 4; j++) s[i][j] = 0.f;

#pragma unroll
            for (int d = 0; d < 64; d += 4) {
                float4 qa[4], kb[4];
#pragma unroll
                for (int i = 0; i < 4; i++) qa[i] = *(const float4*)&Qs[ty * 4 + i][d];
#pragma unroll
                for (int j = 0; j < 4; j++) kb[j] = *(const float4*)&Ks[tx * 4 + j][d];
#pragma unroll
                for (int i = 0; i < 4; i++)
#pragma unroll
                    for (int j = 0; j < 4; j++) {
                        s[i][j] = fmaf(qa[i].x, kb[j].x, s[i][j]);
                        s[i][j] = fmaf(qa[i].y, kb[j].y, s[i][j]);
                        s[i][j] = fmaf(qa[i].z, kb[j].z, s[i][j]);
                        s[i][j] = fmaf(qa[i].w, kb[j].w, s[i][j]);
                    }
            }
#pragma unroll
            for (int i = 0; i < 4; i++) {
                float4 o;
                o.x = s[i][0] * scale; o.y = s[i][1] * scale;
                o.z = s[i][2] * scale; o.w = s[i][3] * scale;
                *(float4*)&Ss[ty * 4 + i][tx * 4] = o;
            }
        }
        __syncthreads();

        // Online softmax update: 4 threads per query row
        {
            int q    = tid >> 2;
            int part = tid & 3;
            float* row = &Ss[q][0];
            float mx = -1e30f;
#pragma unroll
            for (int j = 0; j < 16; j++) mx = fmaxf(mx, row[part * 16 + j]);
            mx = fmaxf(mx, __shfl_xor_sync(0xffffffffu, mx, 1));
            mx = fmaxf(mx, __shfl_xor_sync(0xffffffffu, mx, 2));
            float mold = m_s[q];
            float mnew = fmaxf(mold, mx);
            float lsum = 0.f;
#pragma unroll
            for (int j = 0; j < 16; j++) {
                float p = __expf(row[part * 16 + j] - mnew);
                row[part * 16 + j] = p;
                lsum += p;
            }
            lsum += __shfl_xor_sync(0xffffffffu, lsum, 1);
            lsum += __shfl_xor_sync(0xffffffffu, lsum, 2);
            if (part == 0) {
                float alpha = __expf(mold - mnew);
                m_s[q]  = mnew;
                l_s[q]  = l_s[q] * alpha + lsum;
                al_s[q] = alpha;
            }
        }
        __syncthreads();

        // Rescale accumulators, then O += P @ V
#pragma unroll
        for (int i = 0; i < 4; i++) {
            float al = al_s[ty * 4 + i];
#pragma unroll
            for (int j = 0; j < 4; j++) acc[i][j] *= al;
        }
#pragma unroll
        for (int j4 = 0; j4 < 64; j4 += 4) {
            float4 p4[4], v4[4];
#pragma unroll
            for (int i = 0; i < 4; i++) p4[i] = *(const float4*)&Ss[ty * 4 + i][j4];
#pragma unroll
            for (int t = 0; t < 4; t++) v4[t] = *(const float4*)&Vs[j4 + t][tx * 4];
#pragma unroll
            for (int i = 0; i < 4; i++) {
                acc[i][0] = fmaf(p4[i].x, v4[0].x, acc[i][0]);
                acc[i][0] = fmaf(p4[i].y, v4[1].x, acc[i][0]);
                acc[i][0] = fmaf(p4[i].z, v4[2].x, acc[i][0]);
                acc[i][0] = fmaf(p4[i].w, v4[3].x, acc[i][0]);
                acc[i][1] = fmaf(p4[i].x, v4[0].y, acc[i][1]);
                acc[i][1] = fmaf(p4[i].y, v4[1].y, acc[i][1]);
                acc[i][1] = fmaf(p4[i].z, v4[2].y, acc[i][1]);
                acc[i][1] = fmaf(p4[i].w, v4[3].y, acc[i][1]);
                acc[i][2] = fmaf(p4[i].x, v4[0].z, acc[i][2]);
                acc[i][2] = fmaf(p4[i].y, v4[1].z, acc[i][2]);
                acc[i][2] = fmaf(p4[i].z, v4[2].z, acc[i][2]);
                acc[i][2] = fmaf(p4[i].w, v4[3].z, acc[i][2]);
                acc[i][3] = fmaf(p4[i].x, v4[0].w, acc[i][3]);
                acc[i][3] = fmaf(p4[i].y, v4[1].w, acc[i][3]);
                acc[i][3] = fmaf(p4[i].z, v4[2].w, acc[i][3]);
                acc[i][3] = fmaf(p4[i].w, v4[3].w, acc[i][3]);
            }
        }
        __syncthreads();
    }

    // Final normalize and write context [B,N,D] with heads interleaved
#pragma unroll
    for (int i = 0; i < 4; i++) {
        int q = ty * 4 + i;
        float inv = 1.f / l_s[q];
        float4 o;
        o.x = acc[i][0] * inv; o.y = acc[i][1] * inv;
        o.z = acc[i][2] * inv; o.w = acc[i][3] * inv;
        *(float4*)&O[headoff + (size_t)(q0 + q) * Dm + tx * 4] = o;
    }
}

// ---------------------------------------------------------------------------
// Launch
// ---------------------------------------------------------------------------
extern "C" void kernel_launch(void* const* d_in, const int* in_sizes, int n_in,
                              void* d_out, int out_size)
{
    const float* x  = (const float*)d_in[0];
    const float* Wq = (const float*)d_in[1];
    const float* bq = (const float*)d_in[2];
    const float* Wk = (const float*)d_in[3];
    const float* bk = (const float*)d_in[4];
    const float* Wv = (const float*)d_in[5];
    const float* bv = (const float*)d_in[6];
    const float* Wp = (const float*)d_in[7];
    const float* bp = (const float*)d_in[8];
    const float* qg = (const float*)d_in[9];
    const float* qb = (const float*)d_in[10];
    const float* kg = (const float*)d_in[11];
    const float* kb_ = (const float*)d_in[12];
    float* out = (float*)d_out;

    float *Qp, *Kp, *Vp, *Cp;
    cudaGetSymbolAddress((void**)&Qp, g_Q);
    cudaGetSymbolAddress((void**)&Kp, g_K);
    cudaGetSymbolAddress((void**)&Vp, g_V);
    cudaGetSymbolAddress((void**)&Cp, g_C);

    cudaFuncSetAttribute(attn_kernel,
                         cudaFuncAttributeMaxDynamicSharedMemorySize, ATTN_SMEM);

    dim3 gg(Dm / 128, Mrows / 128);  // (8, 32)

    sgemm_nt_bias<<<gg, 256>>>(x, Wq, bq, Qp, Mrows, Dm, Dm);
    sgemm_nt_bias<<<gg, 256>>>(x, Wk, bk, Kp, Mrows, Dm, Dm);
    sgemm_nt_bias<<<gg, 256>>>(x, Wv, bv, Vp, Mrows, Dm, Dm);

    int groups = Mrows * Hh;                 // 65536 (row,head) pairs
    int ln_blocks = groups / 8;              // 8 warps per block
    ln_heads<<<ln_blocks, 256>>>(Qp, qg, qb, groups);
    ln_heads<<<ln_blocks, 256>>>(Kp, kg, kb_, groups);

    attn_kernel<<<dim3(Nseq / 64, Bq * Hh), 256, ATTN_SMEM>>>(Qp, Kp, Vp, Cp);

    sgemm_nt_bias<<<gg, 256>>>(Cp, Wp, bp, out, Mrows, Dm, Dm);
}

// round 3
// speedup vs baseline: 1.2073x; 1.2073x over previous
#include <cuda_runtime.h>
#include <cuda_bf16.h>
#include <cstdint>

// Problem constants
static constexpr int Bq    = 2;
static constexpr int Nseq  = 2048;
static constexpr int Dm    = 1024;
static constexpr int Hh    = 16;
static constexpr int HDim  = 64;
static constexpr int Mrows = Bq * Nseq;  // 4096
static constexpr float EPSf = 1e-5f;

// Scratch (allocation-free rule: device globals)
__device__ float g_Q[Mrows * Dm];
__device__ float g_K[Mrows * Dm];
__device__ float g_V[Mrows * Dm];
__device__ float g_C[Mrows * Dm];

// ===========================================================================
// Helpers (base-target PTX only: ldmatrix + mma.sync, both sm_80/75+)
// ===========================================================================
__device__ __forceinline__ uint32_t smem_u32(const void* p) {
    uint32_t a;
    asm("{ .reg .u64 t; cvta.to.shared.u64 t, %1; cvt.u32.u64 %0, t; }"
        : "=r"(a) : "l"(p));
    return a;
}

#define LDSM4(r0, r1, r2, r3, addr) \
    asm volatile("ldmatrix.sync.aligned.m8n8.x4.shared.b16 {%0,%1,%2,%3}, [%4];" \
        : "=r"(r0), "=r"(r1), "=r"(r2), "=r"(r3) : "r"(addr))

#define MMA16816(c, a, b0v, b1v) \
    asm volatile("mma.sync.aligned.m16n8k16.row.col.f32.bf16.bf16.f32 " \
        "{%0,%1,%2,%3}, {%4,%5,%6,%7}, {%8,%9}, {%0,%1,%2,%3};" \
        : "+f"((c)[0]), "+f"((c)[1]), "+f"((c)[2]), "+f"((c)[3]) \
        : "r"((a)[0]), "r"((a)[1]), "r"((a)[2]), "r"((a)[3]), \
          "r"(b0v), "r"(b1v))

__device__ __forceinline__ void split_pack2(float x, float y, uint32_t& hi, uint32_t& lo) {
    __nv_bfloat162 h = __floats2bfloat162_rn(x, y);
    float hx = __bfloat162float(h.x), hy = __bfloat162float(h.y);
    __nv_bfloat162 l = __floats2bfloat162_rn(x - hx, y - hy);
    hi = *(uint32_t*)&h;
    lo = *(uint32_t*)&l;
}

// ===========================================================================
// Split-bf16 mma.sync GEMM (NT): C[M,1024] = X[M,1024] @ W[1024,1024]^T + bias
// CTA tile 128x64, BK=32, 8 warps (4x2), warp tile 32x32.
// Smem rows padded to 80 B for conflict-free ldmatrix.
// ===========================================================================
static constexpr int BM = 128, BN = 64, BK = 32;
static constexpr int ROWB = 80;                     // bytes per smem row (32 bf16 + pad)
static constexpr int OFF_AHI = 0;                   // 128*80 = 10240
static constexpr int OFF_ALO = 10240;
static constexpr int OFF_BHI = 20480;               // 64*80 = 5120
static constexpr int OFF_BLO = 25600;
static constexpr int BUF_B   = 30720;
static constexpr int GEMM_SMEM = 2 * BUF_B;         // 61440

__global__ void __launch_bounds__(256, 2) gemm_mma_bias(
    const float* __restrict__ X, const float* __restrict__ W,
    const float* __restrict__ bias, float* __restrict__ C)
{
    extern __shared__ char sm[];
    const uint32_t sb = smem_u32(sm);
    const int tid  = threadIdx.x;
    const int lane = tid & 31;
    const int warp = tid >> 5;
    const int wm   = warp >> 1;   // 0..3
    const int wn   = warp & 1;    // 0..1

    const float* Ag = X + (size_t)(blockIdx.y * BM) * Dm;
    const float* Bg = W + (size_t)(blockIdx.x * BN) * Dm;

    // global staging mapping
    const int arow = tid >> 1, ahalf = tid & 1;   // 128 rows x 2 halves of 16 f32
    const int brow = tid >> 2, bq = tid & 3;      // 64 rows x 4 quarters of 8 f32

    float4 aR[4], bR[2];

    float acc[2][4][4];
#pragma unroll
    for (int t = 0; t < 2; t++)
#pragma unroll
        for (int n = 0; n < 4; n++)
#pragma unroll
            for (int j = 0; j < 4; j++) acc[t][n][j] = 0.f;

    // ldmatrix base offsets (lane-dependent, chunk-independent)
    const uint32_t aLM = (uint32_t)((wm * 32 + (lane & 15)) * ROWB + ((lane >> 4) * 8) * 2);
    const uint32_t bLM = (uint32_t)((wn * 32 + (lane & 7) + ((lane >> 4) & 1) * 8) * ROWB
                                    + (((lane >> 3) & 1) * 8) * 2);

    // prefetch chunk 0
    {
        const float* ap = Ag + (size_t)arow * Dm + ahalf * 16;
        aR[0] = *(const float4*)ap;       aR[1] = *(const float4*)(ap + 4);
        aR[2] = *(const float4*)(ap + 8); aR[3] = *(const float4*)(ap + 12);
        const float* bp = Bg + (size_t)brow * Dm + bq * 8;
        bR[0] = *(const float4*)bp;       bR[1] = *(const float4*)(bp + 4);
    }

    const int NCHUNK = Dm / BK;  // 32
    for (int c = 0; c < NCHUNK; c++) {
        const int buf = c & 1;
        char* base = sm + buf * BUF_B;

        // store staged chunk (split hi/lo)
        {
            uint4 H, L;
            split_pack2(aR[0].x, aR[0].y, H.x, L.x);
            split_pack2(aR[0].z, aR[0].w, H.y, L.y);
            split_pack2(aR[1].x, aR[1].y, H.z, L.z);
            split_pack2(aR[1].z, aR[1].w, H.w, L.w);
            *(uint4*)(base + OFF_AHI + arow * ROWB + ahalf * 32) = H;
            *(uint4*)(base + OFF_ALO + arow * ROWB + ahalf * 32) = L;
            split_pack2(aR[2].x, aR[2].y, H.x, L.x);
            split_pack2(aR[2].z, aR[2].w, H.y, L.y);
            split_pack2(aR[3].x, aR[3].y, H.z, L.z);
            split_pack2(aR[3].z, aR[3].w, H.w, L.w);
            *(uint4*)(base + OFF_AHI + arow * ROWB + ahalf * 32 + 16) = H;
            *(uint4*)(base + OFF_ALO + arow * ROWB + ahalf * 32 + 16) = L;
            split_pack2(bR[0].x, bR[0].y, H.x, L.x);
            split_pack2(bR[0].z, bR[0].w, H.y, L.y);
            split_pack2(bR[1].x, bR[1].y, H.z, L.z);
            split_pack2(bR[1].z, bR[1].w, H.w, L.w);
            *(uint4*)(base + OFF_BHI + brow * ROWB + bq * 16) = H;
            *(uint4*)(base + OFF_BLO + brow * ROWB + bq * 16) = L;
        }

        // prefetch next chunk
        if (c + 1 < NCHUNK) {
            const int k0 = (c + 1) * BK;
            const float* ap = Ag + (size_t)arow * Dm + k0 + ahalf * 16;
            aR[0] = *(const float4*)ap;       aR[1] = *(const float4*)(ap + 4);
            aR[2] = *(const float4*)(ap + 8); aR[3] = *(const float4*)(ap + 12);
            const float* bp = Bg + (size_t)brow * Dm + k0 + bq * 8;
            bR[0] = *(const float4*)bp;       bR[1] = *(const float4*)(bp + 4);
        }
        __syncthreads();

        // compute on this buffer
        const uint32_t aHiB = sb + buf * BUF_B + OFF_AHI;
        const uint32_t aLoB = sb + buf * BUF_B + OFF_ALO;
        const uint32_t bHiB = sb + buf * BUF_B + OFF_BHI;
        const uint32_t bLoB = sb + buf * BUF_B + OFF_BLO;

#pragma unroll
        for (int kk = 0; kk < BK; kk += 16) {
            uint32_t ah[2][4], al[2][4], bh[2][4], bl[2][4];
#pragma unroll
            for (int t = 0; t < 2; t++) {
                uint32_t off = aLM + (uint32_t)(t * 16 * ROWB + kk * 2);
                LDSM4(ah[t][0], ah[t][1], ah[t][2], ah[t][3], aHiB + off);
                LDSM4(al[t][0], al[t][1], al[t][2], al[t][3], aLoB + off);
            }
#pragma unroll
            for (int g = 0; g < 2; g++) {
                uint32_t off = bLM + (uint32_t)(g * 16 * ROWB + kk * 2);
                LDSM4(bh[g][0], bh[g][1], bh[g][2], bh[g][3], bHiB + off);
                LDSM4(bl[g][0], bl[g][1], bl[g][2], bl[g][3], bLoB + off);
            }
#pragma unroll
            for (int t = 0; t < 2; t++)
#pragma unroll
                for (int g = 0; g < 2; g++) {
                    MMA16816(acc[t][g * 2 + 0], ah[t], bh[g][0], bh[g][1]);
                    MMA16816(acc[t][g * 2 + 1], ah[t], bh[g][2], bh[g][3]);
                    MMA16816(acc[t][g * 2 + 0], ah[t], bl[g][0], bl[g][1]);
                    MMA16816(acc[t][g * 2 + 1], ah[t], bl[g][2], bl[g][3]);
                    MMA16816(acc[t][g * 2 + 0], al[t], bh[g][0], bh[g][1]);
                    MMA16816(acc[t][g * 2 + 1], al[t], bh[g][2], bh[g][3]);
                }
        }
        __syncthreads();
    }

    // epilogue: c-fragment layout, add bias, store f32
    const int rbase = blockIdx.y * BM + wm * 32 + (lane >> 2);
    const int cbase = blockIdx.x * BN + wn * 32 + (lane & 3) * 2;
#pragma unroll
    for (int t = 0; t < 2; t++)
#pragma unroll
        for (int n = 0; n < 4; n++) {
            int col = cbase + n * 8;
            float b0 = bias[col], b1 = bias[col + 1];
            int r0 = rbase + t * 16;
            float2 o0 = make_float2(acc[t][n][0] + b0, acc[t][n][1] + b1);
            float2 o1 = make_float2(acc[t][n][2] + b0, acc[t][n][3] + b1);
            *(float2*)&C[(size_t)r0 * Dm + col]       = o0;
            *(float2*)&C[(size_t)(r0 + 8) * Dm + col] = o1;
        }
}

// ---------------------------------------------------------------------------
// Per-head LayerNorm over HD=64, in place
// ---------------------------------------------------------------------------
__global__ void __launch_bounds__(256) ln_heads(
    float* __restrict__ X, const float* __restrict__ gamma,
    const float* __restrict__ beta, int total_groups)
{
    int wid  = (blockIdx.x * blockDim.x + threadIdx.x) >> 5;
    int lane = threadIdx.x & 31;
    if (wid >= total_groups) return;
    int row = wid >> 4;
    int h   = wid & 15;
    float* p = X + (size_t)row * Dm + h * HDim;

    float x0 = p[lane];
    float x1 = p[lane + 32];
    float s  = x0 + x1;
    float ss = x0 * x0 + x1 * x1;
#pragma unroll
    for (int o = 16; o > 0; o >>= 1) {
        s  += __shfl_xor_sync(0xffffffffu, s,  o);
        ss += __shfl_xor_sync(0xffffffffu, ss, o);
    }
    float mean = s * (1.f / 64.f);
    float var  = ss * (1.f / 64.f) - mean * mean;
    float r    = rsqrtf(var + EPSf);
    p[lane]      = (x0 - mean) * r * gamma[lane]      + beta[lane];
    p[lane + 32] = (x1 - mean) * r * gamma[lane + 32] + beta[lane + 32];
}

// ---------------------------------------------------------------------------
// Flash-style attention, fp32 (unchanged — proven correct)
// ---------------------------------------------------------------------------
static constexpr int ATTN_LD   = 68;
static constexpr int ATTN_SMEM = (4 * 64 * ATTN_LD + 3 * 64) * (int)sizeof(float);

__global__ void __launch_bounds__(256) attn_kernel(
    const float* __restrict__ Q, const float* __restrict__ K,
    const float* __restrict__ V, float* __restrict__ O)
{
    extern __shared__ float smf[];
    float (*Qs)[ATTN_LD] = (float(*)[ATTN_LD])(smf);
    float (*Ks)[ATTN_LD] = (float(*)[ATTN_LD])(smf + 1 * 64 * ATTN_LD);
    float (*Vs)[ATTN_LD] = (float(*)[ATTN_LD])(smf + 2 * 64 * ATTN_LD);
    float (*Ss)[ATTN_LD] = (float(*)[ATTN_LD])(smf + 3 * 64 * ATTN_LD);
    float* m_s  = smf + 4 * 64 * ATTN_LD;
    float* l_s  = m_s + 64;
    float* al_s = l_s + 64;

    const int tid = threadIdx.x;
    const int tx  = tid & 15;
    const int ty  = tid >> 4;
    const int bh  = blockIdx.y;
    const int b   = bh >> 4;
    const int h   = bh & 15;
    const int q0  = blockIdx.x * 64;
    const size_t headoff = (size_t)b * Nseq * Dm + (size_t)h * HDim;
    const float scale = 0.125f;

    for (int i = tid; i < 64 * 16; i += 256) {
        int r  = i >> 4;
        int c4 = (i & 15) << 2;
        *(float4*)&Qs[r][c4] = *(const float4*)&Q[headoff + (size_t)(q0 + r) * Dm + c4];
    }
    if (tid < 64) { m_s[tid] = -1e30f; l_s[tid] = 0.f; }

    float acc[4][4];
#pragma unroll
    for (int i = 0; i < 4; i++)
#pragma unroll
        for (int j = 0; j < 4; j++) acc[i][j] = 0.f;

    __syncthreads();

    for (int kt = 0; kt < Nseq; kt += 64) {
        for (int i = tid; i < 64 * 16; i += 256) {
            int r  = i >> 4;
            int c4 = (i & 15) << 2;
            *(float4*)&Ks[r][c4] = *(const float4*)&K[headoff + (size_t)(kt + r) * Dm + c4];
            *(float4*)&Vs[r][c4] = *(const float4*)&V[headoff + (size_t)(kt + r) * Dm + c4];
        }
        __syncthreads();

        {
            float s[4][4];
#pragma unroll
            for (int i = 0; i < 4; i++)
#pragma unroll
                for (int j = 0; j < 4; j++) s[i][j] = 0.f;

#pragma unroll
            for (int d = 0; d < 64; d += 4) {
                float4 qa[4], kb[4];
#pragma unroll
                for (int i = 0; i < 4; i++) qa[i] = *(const float4*)&Qs[ty * 4 + i][d];
#pragma unroll
                for (int j = 0; j < 4; j++) kb[j] = *(const float4*)&Ks[tx * 4 + j][d];
#pragma unroll
                for (int i = 0; i < 4; i++)
#pragma unroll
                    for (int j = 0; j < 4; j++) {
                        s[i][j] = fmaf(qa[i].x, kb[j].x, s[i][j]);
                        s[i][j] = fmaf(qa[i].y, kb[j].y, s[i][j]);
                        s[i][j] = fmaf(qa[i].z, kb[j].z, s[i][j]);
                        s[i][j] = fmaf(qa[i].w, kb[j].w, s[i][j]);
                    }
            }
#pragma unroll
            for (int i = 0; i < 4; i++) {
                float4 o;
                o.x = s[i][0] * scale; o.y = s[i][1] * scale;
                o.z = s[i][2] * scale; o.w = s[i][3] * scale;
                *(float4*)&Ss[ty * 4 + i][tx * 4] = o;
            }
        }
        __syncthreads();

        {
            int q    = tid >> 2;
            int part = tid & 3;
            float* row = &Ss[q][0];
            float mx = -1e30f;
#pragma unroll
            for (int j = 0; j < 16; j++) mx = fmaxf(mx, row[part * 16 + j]);
            mx = fmaxf(mx, __shfl_xor_sync(0xffffffffu, mx, 1));
            mx = fmaxf(mx, __shfl_xor_sync(0xffffffffu, mx, 2));
            float mold = m_s[q];
            float mnew = fmaxf(mold, mx);
            float lsum = 0.f;
#pragma unroll
            for (int j = 0; j < 16; j++) {
                float p = __expf(row[part * 16 + j] - mnew);
                row[part * 16 + j] = p;
                lsum += p;
            }
            lsum += __shfl_xor_sync(0xffffffffu, lsum, 1);
            lsum += __shfl_xor_sync(0xffffffffu, lsum, 2);
            if (part == 0) {
                float alpha = __expf(mold - mnew);
                m_s[q]  = mnew;
                l_s[q]  = l_s[q] * alpha + lsum;
                al_s[q] = alpha;
            }
        }
        __syncthreads();

#pragma unroll
        for (int i = 0; i < 4; i++) {
            float al = al_s[ty * 4 + i];
#pragma unroll
            for (int j = 0; j < 4; j++) acc[i][j] *= al;
        }
#pragma unroll
        for (int j4 = 0; j4 < 64; j4 += 4) {
            float4 p4[4], v4[4];
#pragma unroll
            for (int i = 0; i < 4; i++) p4[i] = *(const float4*)&Ss[ty * 4 + i][j4];
#pragma unroll
            for (int t = 0; t < 4; t++) v4[t] = *(const float4*)&Vs[j4 + t][tx * 4];
#pragma unroll
            for (int i = 0; i < 4; i++) {
                acc[i][0] = fmaf(p4[i].x, v4[0].x, acc[i][0]);
                acc[i][0] = fmaf(p4[i].y, v4[1].x, acc[i][0]);
                acc[i][0] = fmaf(p4[i].z, v4[2].x, acc[i][0]);
                acc[i][0] = fmaf(p4[i].w, v4[3].x, acc[i][0]);
                acc[i][1] = fmaf(p4[i].x, v4[0].y, acc[i][1]);
                acc[i][1] = fmaf(p4[i].y, v4[1].y, acc[i][1]);
                acc[i][1] = fmaf(p4[i].z, v4[2].y, acc[i][1]);
                acc[i][1] = fmaf(p4[i].w, v4[3].y, acc[i][1]);
                acc[i][2] = fmaf(p4[i].x, v4[0].z, acc[i][2]);
                acc[i][2] = fmaf(p4[i].y, v4[1].z, acc[i][2]);
                acc[i][2] = fmaf(p4[i].z, v4[2].z, acc[i][2]);
                acc[i][2] = fmaf(p4[i].w, v4[3].z, acc[i][2]);
                acc[i][3] = fmaf(p4[i].x, v4[0].w, acc[i][3]);
                acc[i][3] = fmaf(p4[i].y, v4[1].w, acc[i][3]);
                acc[i][3] = fmaf(p4[i].z, v4[2].w, acc[i][3]);
                acc[i][3] = fmaf(p4[i].w, v4[3].w, acc[i][3]);
            }
        }
        __syncthreads();
    }

#pragma unroll
    for (int i = 0; i < 4; i++) {
        int q = ty * 4 + i;
        float inv = 1.f / l_s[q];
        float4 o;
        o.x = acc[i][0] * inv; o.y = acc[i][1] * inv;
        o.z = acc[i][2] * inv; o.w = acc[i][3] * inv;
        *(float4*)&O[headoff + (size_t)(q0 + q) * Dm + tx * 4] = o;
    }
}

// ---------------------------------------------------------------------------
// Launch
// ---------------------------------------------------------------------------
extern "C" void kernel_launch(void* const* d_in, const int* in_sizes, int n_in,
                              void* d_out, int out_size)
{
    const float* x  = (const float*)d_in[0];
    const float* Wq = (const float*)d_in[1];
    const float* bq = (const float*)d_in[2];
    const float* Wk = (const float*)d_in[3];
    const float* bk = (const float*)d_in[4];
    const float* Wv = (const float*)d_in[5];
    const float* bv = (const float*)d_in[6];
    const float* Wp = (const float*)d_in[7];
    const float* bp = (const float*)d_in[8];
    const float* qg = (const float*)d_in[9];
    const float* qb = (const float*)d_in[10];
    const float* kg = (const float*)d_in[11];
    const float* kb_ = (const float*)d_in[12];
    float* out = (float*)d_out;

    float *Qp, *Kp, *Vp, *Cp;
    cudaGetSymbolAddress((void**)&Qp, g_Q);
    cudaGetSymbolAddress((void**)&Kp, g_K);
    cudaGetSymbolAddress((void**)&Vp, g_V);
    cudaGetSymbolAddress((void**)&Cp, g_C);

    cudaFuncSetAttribute(attn_kernel,
                         cudaFuncAttributeMaxDynamicSharedMemorySize, ATTN_SMEM);
    cudaFuncSetAttribute(gemm_mma_bias,
                         cudaFuncAttributeMaxDynamicSharedMemorySize, GEMM_SMEM);

    dim3 gg(Dm / BN, Mrows / BM);  // (16, 32) = 512 CTAs

    gemm_mma_bias<<<gg, 256, GEMM_SMEM>>>(x, Wq, bq, Qp);
    gemm_mma_bias<<<gg, 256, GEMM_SMEM>>>(x, Wk, bk, Kp);
    gemm_mma_bias<<<gg, 256, GEMM_SMEM>>>(x, Wv, bv, Vp);

    int groups = Mrows * Hh;
    int ln_blocks = groups / 8;
    ln_heads<<<ln_blocks, 256>>>(Qp, qg, qb, groups);
    ln_heads<<<ln_blocks, 256>>>(Kp, kg, kb_, groups);

    attn_kernel<<<dim3(Nseq / 64, Bq * Hh), 256, ATTN_SMEM>>>(Qp, Kp, Vp, Cp);

    gemm_mma_bias<<<gg, 256, GEMM_SMEM>>>(Cp, Wp, bp, out);
}

// round 4
// speedup vs baseline: 2.5983x; 2.1522x over previous
#include <cuda_runtime.h>
#include <cuda_bf16.h>
#include <cstdint>

// Problem constants
static constexpr int Bq    = 2;
static constexpr int Nseq  = 2048;
static constexpr int Dm    = 1024;
static constexpr int Hh    = 16;
static constexpr int HDim  = 64;
static constexpr int Mrows = Bq * Nseq;  // 4096
static constexpr float EPSf = 1e-5f;

// ---------------------------------------------------------------------------
// Device-global scratch (allocation-free rule)
// ---------------------------------------------------------------------------
__device__ float g_Q[Mrows * Dm];
__device__ float g_K[Mrows * Dm];
__device__ float g_V[Mrows * Dm];

__device__ __nv_bfloat16 g_Xh[Mrows * Dm], g_Xl[Mrows * Dm];
__device__ __nv_bfloat16 g_Wh[4][Dm * Dm], g_Wl[4][Dm * Dm];
__device__ __nv_bfloat16 g_Qh[Mrows * Dm], g_Ql[Mrows * Dm];   // [BH][N][64]
__device__ __nv_bfloat16 g_Kh[Mrows * Dm], g_Kl[Mrows * Dm];   // [BH][N][64]
__device__ __nv_bfloat16 g_VTh[Mrows * Dm], g_VTl[Mrows * Dm]; // [BH][64][N]
__device__ __nv_bfloat16 g_Ch[Mrows * Dm], g_Cl[Mrows * Dm];   // [B*N][D]

// ===========================================================================
// Helpers (base-target PTX only: ldmatrix + mma.sync)
// ===========================================================================
__device__ __forceinline__ uint32_t smem_u32(const void* p) {
    uint32_t a;
    asm("{ .reg .u64 t; cvta.to.shared.u64 t, %1; cvt.u32.u64 %0, t; }"
        : "=r"(a) : "l"(p));
    return a;
}

#define LDSM4(r0, r1, r2, r3, addr) \
    asm volatile("ldmatrix.sync.aligned.m8n8.x4.shared.b16 {%0,%1,%2,%3}, [%4];" \
        : "=r"(r0), "=r"(r1), "=r"(r2), "=r"(r3) : "r"(addr))

#define MMA16816(c, a, b0v, b1v) \
    asm volatile("mma.sync.aligned.m16n8k16.row.col.f32.bf16.bf16.f32 " \
        "{%0,%1,%2,%3}, {%4,%5,%6,%7}, {%8,%9}, {%0,%1,%2,%3};" \
        : "+f"((c)[0]), "+f"((c)[1]), "+f"((c)[2]), "+f"((c)[3]) \
        : "r"((a)[0]), "r"((a)[1]), "r"((a)[2]), "r"((a)[3]), \
          "r"(b0v), "r"(b1v))

__device__ __forceinline__ void split_pack2(float x, float y, uint32_t& hi, uint32_t& lo) {
    __nv_bfloat162 h = __floats2bfloat162_rn(x, y);
    float hx = __bfloat162float(h.x), hy = __bfloat162float(h.y);
    __nv_bfloat162 l = __floats2bfloat162_rn(x - hx, y - hy);
    hi = *(uint32_t*)&h;
    lo = *(uint32_t*)&l;
}

// ===========================================================================
// Elementwise split: f32 -> (hi, lo) bf16
// ===========================================================================
__global__ void __launch_bounds__(256) split_f32(
    const float* __restrict__ s, __nv_bfloat16* __restrict__ hi,
    __nv_bfloat16* __restrict__ lo, int n4)
{
    int i = blockIdx.x * blockDim.x + threadIdx.x;
    if (i >= n4) return;
    float4 v = ((const float4*)s)[i];
    uint32_t h0, l0, h1, l1;
    split_pack2(v.x, v.y, h0, l0);
    split_pack2(v.z, v.w, h1, l1);
    ((uint2*)hi)[i] = make_uint2(h0, h1);
    ((uint2*)lo)[i] = make_uint2(l0, l1);
}

// ===========================================================================
// Split-bf16 mma.sync GEMM (NT), pre-split inputs:
// C[M,1024] = (Ah+Al)[M,1024] @ (Bh+Bl)[1024,1024]^T + bias
// Tile 128x64, BK=32, 8 warps (4x2), warp tile 32x32. ROWB=80 pad.
// ===========================================================================
static constexpr int BM = 128, BN = 64, BK = 32;
static constexpr int ROWB = 80;
static constexpr int OFF_AHI = 0;
static constexpr int OFF_ALO = 10240;
static constexpr int OFF_BHI = 20480;
static constexpr int OFF_BLO = 25600;
static constexpr int BUF_B   = 30720;
static constexpr int GEMM_SMEM = 2 * BUF_B;

__global__ void __launch_bounds__(256, 2) gemm_mma_bias(
    const __nv_bfloat16* __restrict__ Ah, const __nv_bfloat16* __restrict__ Al,
    const __nv_bfloat16* __restrict__ Bh, const __nv_bfloat16* __restrict__ Bl,
    const float* __restrict__ bias, float* __restrict__ C)
{
    extern __shared__ char sm[];
    const uint32_t sb = smem_u32(sm);
    const int tid  = threadIdx.x;
    const int lane = tid & 31;
    const int warp = tid >> 5;
    const int wm   = warp >> 1;
    const int wn   = warp & 1;

    const size_t aoff0 = (size_t)(blockIdx.y * BM) * Dm;
    const size_t boff0 = (size_t)(blockIdx.x * BN) * Dm;

    // staging maps: A 128 rows x 4 segs(16B), two items/thread; B 64 x 4, one.
    const int ar0 = tid >> 2, aseg = tid & 3;          // + second item at +64 rows
    const int br  = tid >> 2, bseg = tid & 3;

    uint4 aHr[2], aLr[2], bHr, bLr;

    float acc[2][4][4];
#pragma unroll
    for (int t = 0; t < 2; t++)
#pragma unroll
        for (int n = 0; n < 4; n++)
#pragma unroll
            for (int j = 0; j < 4; j++) acc[t][n][j] = 0.f;

    const uint32_t aLM = (uint32_t)((wm * 32 + (lane & 15)) * ROWB + ((lane >> 4) * 8) * 2);
    const uint32_t bLM = (uint32_t)((wn * 32 + (lane & 7) + ((lane >> 4) & 1) * 8) * ROWB
                                    + (((lane >> 3) & 1) * 8) * 2);

    // prefetch chunk 0
    {
        const size_t a0 = aoff0 + (size_t)ar0 * Dm + aseg * 8;
        const size_t a1 = aoff0 + (size_t)(ar0 + 64) * Dm + aseg * 8;
        aHr[0] = *(const uint4*)(Ah + a0); aHr[1] = *(const uint4*)(Ah + a1);
        aLr[0] = *(const uint4*)(Al + a0); aLr[1] = *(const uint4*)(Al + a1);
        const size_t b0 = boff0 + (size_t)br * Dm + bseg * 8;
        bHr = *(const uint4*)(Bh + b0);
        bLr = *(const uint4*)(Bl + b0);
    }

    const int NCHUNK = Dm / BK;  // 32
    for (int c = 0; c < NCHUNK; c++) {
        const int buf = c & 1;
        char* base = sm + buf * BUF_B;

        *(uint4*)(base + OFF_AHI + ar0 * ROWB + aseg * 16)        = aHr[0];
        *(uint4*)(base + OFF_AHI + (ar0 + 64) * ROWB + aseg * 16) = aHr[1];
        *(uint4*)(base + OFF_ALO + ar0 * ROWB + aseg * 16)        = aLr[0];
        *(uint4*)(base + OFF_ALO + (ar0 + 64) * ROWB + aseg * 16) = aLr[1];
        *(uint4*)(base + OFF_BHI + br * ROWB + bseg * 16)         = bHr;
        *(uint4*)(base + OFF_BLO + br * ROWB + bseg * 16)         = bLr;

        if (c + 1 < NCHUNK) {
            const int k0 = (c + 1) * BK;
            const size_t a0 = aoff0 + (size_t)ar0 * Dm + k0 + aseg * 8;
            const size_t a1 = aoff0 + (size_t)(ar0 + 64) * Dm + k0 + aseg * 8;
            aHr[0] = *(const uint4*)(Ah + a0); aHr[1] = *(const uint4*)(Ah + a1);
            aLr[0] = *(const uint4*)(Al + a0); aLr[1] = *(const uint4*)(Al + a1);
            const size_t b0 = boff0 + (size_t)br * Dm + k0 + bseg * 8;
            bHr = *(const uint4*)(Bh + b0);
            bLr = *(const uint4*)(Bl + b0);
        }
        __syncthreads();

        const uint32_t aHiB = sb + buf * BUF_B + OFF_AHI;
        const uint32_t aLoB = sb + buf * BUF_B + OFF_ALO;
        const uint32_t bHiB = sb + buf * BUF_B + OFF_BHI;
        const uint32_t bLoB = sb + buf * BUF_B + OFF_BLO;

#pragma unroll
        for (int kk = 0; kk < BK; kk += 16) {
            uint32_t ah[2][4], al[2][4], bh4[2][4], bl4[2][4];
#pragma unroll
            for (int t = 0; t < 2; t++) {
                uint32_t off = aLM + (uint32_t)(t * 16 * ROWB + kk * 2);
                LDSM4(ah[t][0], ah[t][1], ah[t][2], ah[t][3], aHiB + off);
                LDSM4(al[t][0], al[t][1], al[t][2], al[t][3], aLoB + off);
            }
#pragma unroll
            for (int g = 0; g < 2; g++) {
                uint32_t off = bLM + (uint32_t)(g * 16 * ROWB + kk * 2);
                LDSM4(bh4[g][0], bh4[g][1], bh4[g][2], bh4[g][3], bHiB + off);
                LDSM4(bl4[g][0], bl4[g][1], bl4[g][2], bl4[g][3], bLoB + off);
            }
#pragma unroll
            for (int t = 0; t < 2; t++)
#pragma unroll
                for (int g = 0; g < 2; g++) {
                    MMA16816(acc[t][g * 2 + 0], ah[t], bh4[g][0], bh4[g][1]);
                    MMA16816(acc[t][g * 2 + 1], ah[t], bh4[g][2], bh4[g][3]);
                    MMA16816(acc[t][g * 2 + 0], ah[t], bl4[g][0], bl4[g][1]);
                    MMA16816(acc[t][g * 2 + 1], ah[t], bl4[g][2], bl4[g][3]);
                    MMA16816(acc[t][g * 2 + 0], al[t], bh4[g][0], bh4[g][1]);
                    MMA16816(acc[t][g * 2 + 1], al[t], bh4[g][2], bh4[g][3]);
                }
        }
        __syncthreads();
    }

    const int rbase = blockIdx.y * BM + wm * 32 + (lane >> 2);
    const int cbase = blockIdx.x * BN + wn * 32 + (lane & 3) * 2;
#pragma unroll
    for (int t = 0; t < 2; t++)
#pragma unroll
        for (int n = 0; n < 4; n++) {
            int col = cbase + n * 8;
            float b0 = bias[col], b1 = bias[col + 1];
            int r0 = rbase + t * 16;
            float2 o0 = make_float2(acc[t][n][0] + b0, acc[t][n][1] + b1);
            float2 o1 = make_float2(acc[t][n][2] + b0, acc[t][n][3] + b1);
            *(float2*)&C[(size_t)r0 * Dm + col]       = o0;
            *(float2*)&C[(size_t)(r0 + 8) * Dm + col] = o1;
        }
}

// ===========================================================================
// LN per head + split to head-major bf16 hi/lo: [BH][N][64]
// ===========================================================================
__global__ void __launch_bounds__(256) ln_split(
    const float* __restrict__ X, const float* __restrict__ gamma,
    const float* __restrict__ beta,
    __nv_bfloat16* __restrict__ Oh, __nv_bfloat16* __restrict__ Ol)
{
    int wid  = (blockIdx.x * blockDim.x + threadIdx.x) >> 5;
    int lane = threadIdx.x & 31;
    int row = wid >> 4;
    int h   = wid & 15;
    const float* p = X + (size_t)row * Dm + h * HDim;

    float x0 = p[lane];
    float x1 = p[lane + 32];
    float s  = x0 + x1;
    float ss = x0 * x0 + x1 * x1;
#pragma unroll
    for (int o = 16; o > 0; o >>= 1) {
        s  += __shfl_xor_sync(0xffffffffu, s,  o);
        ss += __shfl_xor_sync(0xffffffffu, ss, o);
    }
    float mean = s * (1.f / 64.f);
    float var  = ss * (1.f / 64.f) - mean * mean;
    float r    = rsqrtf(var + EPSf);
    float y0 = (x0 - mean) * r * gamma[lane]      + beta[lane];
    float y1 = (x1 - mean) * r * gamma[lane + 32] + beta[lane + 32];

    int b = row >> 11, n = row & 2047;
    size_t o = ((size_t)(b * Hh + h) * Nseq + n) * HDim;
    __nv_bfloat16 h0 = __float2bfloat16(y0);
    __nv_bfloat16 h1 = __float2bfloat16(y1);
    Oh[o + lane]      = h0;
    Oh[o + lane + 32] = h1;
    Ol[o + lane]      = __float2bfloat16(y0 - __bfloat162float(h0));
    Ol[o + lane + 32] = __float2bfloat16(y1 - __bfloat162float(h1));
}

// ===========================================================================
// V transpose + split: g_V [B,N,D] -> VT [BH][64(d)][N] bf16 hi/lo
// Block = (ntile, bh); 64x64 tile through smem.
// ===========================================================================
__global__ void __launch_bounds__(256) v_splitT(
    const float* __restrict__ V,
    __nv_bfloat16* __restrict__ VTh, __nv_bfloat16* __restrict__ VTl)
{
    __shared__ float st[64][68];
    const int tid = threadIdx.x;
    const int bh = blockIdx.y;
    const int n0 = blockIdx.x * 64;
    const int b = bh >> 4, h = bh & 15;

    int j = tid >> 2, dseg = tid & 3;
    const float* gp = V + (size_t)(b * Nseq + n0 + j) * Dm + h * HDim + dseg * 16;
#pragma unroll
    for (int q = 0; q < 4; q++)
        *(float4*)&st[j][dseg * 16 + q * 4] = *(const float4*)(gp + q * 4);
    __syncthreads();

    int d = tid >> 2, nseg = tid & 3;
    size_t o = ((size_t)bh * HDim + d) * Nseq + n0 + nseg * 16;
#pragma unroll
    for (int jj = 0; jj < 16; jj++) {
        float v = st[nseg * 16 + jj][d];
        __nv_bfloat16 hv = __float2bfloat16(v);
        VTh[o + jj] = hv;
        VTl[o + jj] = __float2bfloat16(v - __bfloat162float(hv));
    }
}

// ===========================================================================
// Flash attention, split-bf16 mma.sync. Block = (qtile 64, bh). 8 warps.
// Q/K head-major [BH][N][64]; V transposed [BH][64][N].
// Writes context split-bf16 into Ch/Cl [B*N][1024] (heads interleaved).
// ===========================================================================
static constexpr int AROWB = 144;       // 64 bf16 = 128B + 16 pad
static constexpr int A_QH = 0;
static constexpr int A_QL = A_QH + 64 * AROWB;   //  9216
static constexpr int A_KH = A_QL + 64 * AROWB;   // 18432
static constexpr int A_KL = A_KH + 64 * AROWB;   // 27648
static constexpr int A_VH = A_KL + 64 * AROWB;   // 36864
static constexpr int A_VL = A_VH + 64 * AROWB;   // 46080
static constexpr int A_PH = A_VL + 64 * AROWB;   // 55296
static constexpr int A_PL = A_PH + 64 * AROWB;   // 64512
static constexpr int A_SS = A_PL + 64 * AROWB;   // 73728 (64 x 68 f32)
static constexpr int A_MS = A_SS + 64 * 68 * 4;  // 91136
static constexpr int A_LS = A_MS + 256;
static constexpr int A_AL = A_LS + 256;
static constexpr int ATTN_SMEM = A_AL + 256;     // 91904

__global__ void __launch_bounds__(256, 2) attn_mma(
    const __nv_bfloat16* __restrict__ Qh, const __nv_bfloat16* __restrict__ Ql,
    const __nv_bfloat16* __restrict__ Kh, const __nv_bfloat16* __restrict__ Kl,
    const __nv_bfloat16* __restrict__ Vh, const __nv_bfloat16* __restrict__ Vl,
    __nv_bfloat16* __restrict__ Ch, __nv_bfloat16* __restrict__ Cl)
{
    extern __shared__ char sm[];
    const uint32_t sb = smem_u32(sm);
    const int tid  = threadIdx.x;
    const int lane = tid & 31;
    const int warp = tid >> 5;
    const int wm   = warp >> 1;   // 0..3 -> rows wm*16
    const int wn   = warp & 1;    // 0..1 -> cols wn*32
    const int bh = blockIdx.y;
    const int q0 = blockIdx.x * 64;
    const float scale = 0.125f;

    float* m_s  = (float*)(sm + A_MS);
    float* l_s  = (float*)(sm + A_LS);
    float* al_s = (float*)(sm + A_AL);

    // Load Q tile (hi/lo)
    {
        const size_t qb = ((size_t)bh * Nseq + q0) * HDim;
#pragma unroll
        for (int it = 0; it < 2; it++) {
            int idx = tid + it * 256;
            int r = idx >> 3, seg = idx & 7;
            *(uint4*)(sm + A_QH + r * AROWB + seg * 16) = *(const uint4*)(Qh + qb + r * 64 + seg * 8);
            *(uint4*)(sm + A_QL + r * AROWB + seg * 16) = *(const uint4*)(Ql + qb + r * 64 + seg * 8);
        }
    }
    if (tid < 64) { m_s[tid] = -1e30f; l_s[tid] = 0.f; }
    __syncthreads();

    // Q fragments (constant across key tiles)
    uint32_t qfh[4][4], qfl[4][4];
    {
        uint32_t aoff = sb + A_QH + (uint32_t)((wm * 16 + (lane & 15)) * AROWB + (lane >> 4) * 16);
#pragma unroll
        for (int ks = 0; ks < 4; ks++) {
            LDSM4(qfh[ks][0], qfh[ks][1], qfh[ks][2], qfh[ks][3], aoff + ks * 32);
            LDSM4(qfl[ks][0], qfl[ks][1], qfl[ks][2], qfl[ks][3], aoff + (A_QL - A_QH) + ks * 32);
        }
    }

    float acc[4][4];
#pragma unroll
    for (int n = 0; n < 4; n++)
#pragma unroll
        for (int j = 0; j < 4; j++) acc[n][j] = 0.f;

    const uint32_t bfrag = (uint32_t)((wn * 32 + (lane & 7) + ((lane >> 4) & 1) * 8) * AROWB
                                      + ((lane >> 3) & 1) * 16);
    const int r0 = wm * 16 + (lane >> 2);
    const int c0 = wn * 32 + (lane & 3) * 2;
    float* Ss = (float*)(sm + A_SS);

    for (int kt = 0; kt < Nseq; kt += 64) {
        // Load K (hi/lo) and V^T (hi/lo) tiles
        {
            const size_t kb = ((size_t)bh * Nseq + kt) * HDim;
#pragma unroll
            for (int it = 0; it < 2; it++) {
                int idx = tid + it * 256;
                int r = idx >> 3, seg = idx & 7;
                *(uint4*)(sm + A_KH + r * AROWB + seg * 16) = *(const uint4*)(Kh + kb + r * 64 + seg * 8);
                *(uint4*)(sm + A_KL + r * AROWB + seg * 16) = *(const uint4*)(Kl + kb + r * 64 + seg * 8);
                const size_t vb = ((size_t)bh * HDim + r) * Nseq + kt;
                *(uint4*)(sm + A_VH + r * AROWB + seg * 16) = *(const uint4*)(Vh + vb + seg * 8);
                *(uint4*)(sm + A_VL + r * AROWB + seg * 16) = *(const uint4*)(Vl + vb + seg * 8);
            }
        }
        __syncthreads();

        // S = Q K^T (split: hh + hl + lh), fp32 accum
        float sacc[4][4];
#pragma unroll
        for (int n = 0; n < 4; n++)
#pragma unroll
            for (int j = 0; j < 4; j++) sacc[n][j] = 0.f;

#pragma unroll
        for (int ks = 0; ks < 4; ks++) {
            uint32_t kh4[2][4], kl4[2][4];
#pragma unroll
            for (int g = 0; g < 2; g++) {
                uint32_t off = bfrag + (uint32_t)(g * 16 * AROWB + ks * 32);
                LDSM4(kh4[g][0], kh4[g][1], kh4[g][2], kh4[g][3], sb + A_KH + off);
                LDSM4(kl4[g][0], kl4[g][1], kl4[g][2], kl4[g][3], sb + A_KL + off);
            }
#pragma unroll
            for (int g = 0; g < 2; g++) {
                MMA16816(sacc[g * 2 + 0], qfh[ks], kh4[g][0], kh4[g][1]);
                MMA16816(sacc[g * 2 + 1], qfh[ks], kh4[g][2], kh4[g][3]);
                MMA16816(sacc[g * 2 + 0], qfh[ks], kl4[g][0], kl4[g][1]);
                MMA16816(sacc[g * 2 + 1], qfh[ks], kl4[g][2], kl4[g][3]);
                MMA16816(sacc[g * 2 + 0], qfl[ks], kh4[g][0], kh4[g][1]);
                MMA16816(sacc[g * 2 + 1], qfl[ks], kh4[g][2], kh4[g][3]);
            }
        }
        // store S * scale to smem
#pragma unroll
        for (int n = 0; n < 4; n++) {
            int col = c0 + n * 8;
            Ss[r0 * 68 + col]           = sacc[n][0] * scale;
            Ss[r0 * 68 + col + 1]       = sacc[n][1] * scale;
            Ss[(r0 + 8) * 68 + col]     = sacc[n][2] * scale;
            Ss[(r0 + 8) * 68 + col + 1] = sacc[n][3] * scale;
        }
        __syncthreads();

        // Online softmax (4 threads per row); write P as bf16 hi/lo
        {
            int q    = tid >> 2;
            int part = tid & 3;
            float* row = Ss + q * 68 + part * 16;
            float mx = -1e30f;
#pragma unroll
            for (int j = 0; j < 16; j++) mx = fmaxf(mx, row[j]);
            mx = fmaxf(mx, __shfl_xor_sync(0xffffffffu, mx, 1));
            mx = fmaxf(mx, __shfl_xor_sync(0xffffffffu, mx, 2));
            float mold = m_s[q];
            float mnew = fmaxf(mold, mx);
            float lsum = 0.f;
            uint32_t* phw = (uint32_t*)(sm + A_PH + q * AROWB + part * 32);
            uint32_t* plw = (uint32_t*)(sm + A_PL + q * AROWB + part * 32);
#pragma unroll
            for (int j = 0; j < 8; j++) {
                float p0 = __expf(row[2 * j]     - mnew);
                float p1 = __expf(row[2 * j + 1] - mnew);
                lsum += p0 + p1;
                uint32_t hw, lw;
                split_pack2(p0, p1, hw, lw);
                phw[j] = hw;
                plw[j] = lw;
            }
            lsum += __shfl_xor_sync(0xffffffffu, lsum, 1);
            lsum += __shfl_xor_sync(0xffffffffu, lsum, 2);
            if (part == 0) {
                float alpha = __expf(mold - mnew);
                m_s[q]  = mnew;
                l_s[q]  = l_s[q] * alpha + lsum;
                al_s[q] = alpha;
            }
        }
        __syncthreads();

        // rescale accumulators
        {
            float al0 = al_s[r0];
            float al1 = al_s[r0 + 8];
#pragma unroll
            for (int n = 0; n < 4; n++) {
                acc[n][0] *= al0; acc[n][1] *= al0;
                acc[n][2] *= al1; acc[n][3] *= al1;
            }
        }

        // O += P @ V  (split: PhVh + PhVl + PlVh)
        {
            uint32_t poff = sb + A_PH + (uint32_t)((wm * 16 + (lane & 15)) * AROWB + (lane >> 4) * 16);
#pragma unroll
            for (int ks = 0; ks < 4; ks++) {
                uint32_t pf[4], pfl[4];
                LDSM4(pf[0], pf[1], pf[2], pf[3], poff + ks * 32);
                LDSM4(pfl[0], pfl[1], pfl[2], pfl[3], poff + (A_PL - A_PH) + ks * 32);
                uint32_t vh4[2][4], vl4[2][4];
#pragma unroll
                for (int g = 0; g < 2; g++) {
                    uint32_t off = bfrag + (uint32_t)(g * 16 * AROWB + ks * 32);
                    LDSM4(vh4[g][0], vh4[g][1], vh4[g][2], vh4[g][3], sb + A_VH + off);
                    LDSM4(vl4[g][0], vl4[g][1], vl4[g][2], vl4[g][3], sb + A_VL + off);
                }
#pragma unroll
                for (int g = 0; g < 2; g++) {
                    MMA16816(acc[g * 2 + 0], pf,  vh4[g][0], vh4[g][1]);
                    MMA16816(acc[g * 2 + 1], pf,  vh4[g][2], vh4[g][3]);
                    MMA16816(acc[g * 2 + 0], pf,  vl4[g][0], vl4[g][1]);
                    MMA16816(acc[g * 2 + 1], pf,  vl4[g][2], vl4[g][3]);
                    MMA16816(acc[g * 2 + 0], pfl, vh4[g][0], vh4[g][1]);
                    MMA16816(acc[g * 2 + 1], pfl, vh4[g][2], vh4[g][3]);
                }
            }
        }
        __syncthreads();
    }

    // Epilogue: normalize, split to bf16, write context [B*N][1024]
    {
        float inv0 = 1.f / l_s[r0];
        float inv1 = 1.f / l_s[r0 + 8];
        const int b = bh >> 4, h = bh & 15;
        const size_t rowA = (size_t)(b * Nseq + q0 + r0) * Dm;
        const size_t rowB = (size_t)(b * Nseq + q0 + r0 + 8) * Dm;
#pragma unroll
        for (int n = 0; n < 4; n++) {
            int col = h * HDim + c0 + n * 8;
            uint32_t hw, lw;
            split_pack2(acc[n][0] * inv0, acc[n][1] * inv0, hw, lw);
            *(uint32_t*)&Ch[rowA + col] = hw;
            *(uint32_t*)&Cl[rowA + col] = lw;
            split_pack2(acc[n][2] * inv1, acc[n][3] * inv1, hw, lw);
            *(uint32_t*)&Ch[rowB + col] = hw;
            *(uint32_t*)&Cl[rowB + col] = lw;
        }
    }
}

// ---------------------------------------------------------------------------
// Launch
// ---------------------------------------------------------------------------
extern "C" void kernel_launch(void* const* d_in, const int* in_sizes, int n_in,
                              void* d_out, int out_size)
{
    const float* x  = (const float*)d_in[0];
    const float* Wq = (const float*)d_in[1];
    const float* bq = (const float*)d_in[2];
    const float* Wk = (const float*)d_in[3];
    const float* bk = (const float*)d_in[4];
    const float* Wv = (const float*)d_in[5];
    const float* bv = (const float*)d_in[6];
    const float* Wp = (const float*)d_in[7];
    const float* bp = (const float*)d_in[8];
    const float* qg = (const float*)d_in[9];
    const float* qb = (const float*)d_in[10];
    const float* kg = (const float*)d_in[11];
    const float* kb_ = (const float*)d_in[12];
    float* out = (float*)d_out;

    float *Qp, *Kp, *Vp;
    cudaGetSymbolAddress((void**)&Qp, g_Q);
    cudaGetSymbolAddress((void**)&Kp, g_K);
    cudaGetSymbolAddress((void**)&Vp, g_V);
    __nv_bfloat16 *Xh, *Xl, *Wh, *Wl, *Qhp, *Qlp, *Khp, *Klp, *VTh, *VTl, *Chp, *Clp;
    cudaGetSymbolAddress((void**)&Xh, g_Xh);
    cudaGetSymbolAddress((void**)&Xl, g_Xl);
    cudaGetSymbolAddress((void**)&Wh, g_Wh);
    cudaGetSymbolAddress((void**)&Wl, g_Wl);
    cudaGetSymbolAddress((void**)&Qhp, g_Qh);
    cudaGetSymbolAddress((void**)&Qlp, g_Ql);
    cudaGetSymbolAddress((void**)&Khp, g_Kh);
    cudaGetSymbolAddress((void**)&Klp, g_Kl);
    cudaGetSymbolAddress((void**)&VTh, g_VTh);
    cudaGetSymbolAddress((void**)&VTl, g_VTl);
    cudaGetSymbolAddress((void**)&Chp, g_Ch);
    cudaGetSymbolAddress((void**)&Clp, g_Cl);

    cudaFuncSetAttribute(gemm_mma_bias,
                         cudaFuncAttributeMaxDynamicSharedMemorySize, GEMM_SMEM);
    cudaFuncSetAttribute(attn_mma,
                         cudaFuncAttributeMaxDynamicSharedMemorySize, ATTN_SMEM);

    const int WW = Dm * Dm;  // 1M elements per weight matrix

    // Pre-split inputs to bf16 hi/lo
    split_f32<<<(Mrows * Dm / 4 + 255) / 256, 256>>>(x,  Xh, Xl, Mrows * Dm / 4);
    split_f32<<<(WW / 4 + 255) / 256, 256>>>(Wq, Wh + 0 * WW, Wl + 0 * WW, WW / 4);
    split_f32<<<(WW / 4 + 255) / 256, 256>>>(Wk, Wh + 1 * WW, Wl + 1 * WW, WW / 4);
    split_f32<<<(WW / 4 + 255) / 256, 256>>>(Wv, Wh + 2 * WW, Wl + 2 * WW, WW / 4);
    split_f32<<<(WW / 4 + 255) / 256, 256>>>(Wp, Wh + 3 * WW, Wl + 3 * WW, WW / 4);

    dim3 gg(Dm / BN, Mrows / BM);  // (16, 32)
    gemm_mma_bias<<<gg, 256, GEMM_SMEM>>>(Xh, Xl, Wh + 0 * WW, Wl + 0 * WW, bq, Qp);
    gemm_mma_bias<<<gg, 256, GEMM_SMEM>>>(Xh, Xl, Wh + 1 * WW, Wl + 1 * WW, bk, Kp);
    gemm_mma_bias<<<gg, 256, GEMM_SMEM>>>(Xh, Xl, Wh + 2 * WW, Wl + 2 * WW, bv, Vp);

    // LN + split to head-major; V transpose + split
    ln_split<<<Mrows * Hh / 8, 256>>>(Qp, qg, qb, Qhp, Qlp);
    ln_split<<<Mrows * Hh / 8, 256>>>(Kp, kg, kb_, Khp, Klp);
    v_splitT<<<dim3(Nseq / 64, Bq * Hh), 256>>>(Vp, VTh, VTl);

    // Attention (writes split context Ch/Cl)
    attn_mma<<<dim3(Nseq / 64, Bq * Hh), 256, ATTN_SMEM>>>(
        Qhp, Qlp, Khp, Klp, VTh, VTl, Chp, Clp);

    // Output projection
    gemm_mma_bias<<<gg, 256, GEMM_SMEM>>>(Chp, Clp, Wh + 3 * WW, Wl + 3 * WW, bp, out);
}

// round 5
// speedup vs baseline: 2.9462x; 1.1339x over previous
#include <cuda_runtime.h>
#include <cuda_bf16.h>
#include <cstdint>

// Problem constants
static constexpr int Bq    = 2;
static constexpr int Nseq  = 2048;
static constexpr int Dm    = 1024;
static constexpr int Hh    = 16;
static constexpr int HDim  = 64;
static constexpr int Mrows = Bq * Nseq;  // 4096
static constexpr float EPSf = 1e-5f;
static constexpr int WW = Dm * Dm;

// ---------------------------------------------------------------------------
// Device-global scratch (allocation-free rule)
// ---------------------------------------------------------------------------
__device__ float g_Q[Mrows * Dm];
__device__ float g_K[Mrows * Dm];
__device__ float g_V[Mrows * Dm];

__device__ __nv_bfloat16 g_Xh[Mrows * Dm], g_Xl[Mrows * Dm];
__device__ __nv_bfloat16 g_Wh[4][WW], g_Wl[4][WW];
__device__ __nv_bfloat16 g_Qh[Mrows * Dm], g_Ql[Mrows * Dm];   // [BH][N][64]
__device__ __nv_bfloat16 g_Kh[Mrows * Dm], g_Kl[Mrows * Dm];   // [BH][N][64]
__device__ __nv_bfloat16 g_VTh[Mrows * Dm], g_VTl[Mrows * Dm]; // [BH][64][N]
__device__ __nv_bfloat16 g_Ch[Mrows * Dm], g_Cl[Mrows * Dm];   // [B*N][D]

// ===========================================================================
// Helpers (base-target PTX only: ldmatrix + mma.sync + cp.async)
// ===========================================================================
__device__ __forceinline__ uint32_t smem_u32(const void* p) {
    uint32_t a;
    asm("{ .reg .u64 t; cvta.to.shared.u64 t, %1; cvt.u32.u64 %0, t; }"
        : "=r"(a) : "l"(p));
    return a;
}

#define LDSM4(r0, r1, r2, r3, addr) \
    asm volatile("ldmatrix.sync.aligned.m8n8.x4.shared.b16 {%0,%1,%2,%3}, [%4];" \
        : "=r"(r0), "=r"(r1), "=r"(r2), "=r"(r3) : "r"(addr))

#define MMA16816(c, a, b0v, b1v) \
    asm volatile("mma.sync.aligned.m16n8k16.row.col.f32.bf16.bf16.f32 " \
        "{%0,%1,%2,%3}, {%4,%5,%6,%7}, {%8,%9}, {%0,%1,%2,%3};" \
        : "+f"((c)[0]), "+f"((c)[1]), "+f"((c)[2]), "+f"((c)[3]) \
        : "r"((a)[0]), "r"((a)[1]), "r"((a)[2]), "r"((a)[3]), \
          "r"(b0v), "r"(b1v))

#define CP_ASYNC16(dst, src) \
    asm volatile("cp.async.cg.shared.global [%0], [%1], 16;" :: "r"(dst), "l"(src))
#define CP_COMMIT()  asm volatile("cp.async.commit_group;" ::: "memory")
#define CP_WAIT1()   asm volatile("cp.async.wait_group 1;" ::: "memory")
#define CP_WAIT0()   asm volatile("cp.async.wait_group 0;" ::: "memory")

__device__ __forceinline__ void split_pack2(float x, float y, uint32_t& hi, uint32_t& lo) {
    __nv_bfloat162 h = __floats2bfloat162_rn(x, y);
    float hx = __bfloat162float(h.x), hy = __bfloat162float(h.y);
    __nv_bfloat162 l = __floats2bfloat162_rn(x - hx, y - hy);
    hi = *(uint32_t*)&h;
    lo = *(uint32_t*)&l;
}

// ===========================================================================
// Elementwise splits
// ===========================================================================
__global__ void __launch_bounds__(256) split_f32(
    const float* __restrict__ s, __nv_bfloat16* __restrict__ hi,
    __nv_bfloat16* __restrict__ lo, int n4)
{
    int i = blockIdx.x * blockDim.x + threadIdx.x;
    if (i >= n4) return;
    float4 v = ((const float4*)s)[i];
    uint32_t h0, l0, h1, l1;
    split_pack2(v.x, v.y, h0, l0);
    split_pack2(v.z, v.w, h1, l1);
    ((uint2*)hi)[i] = make_uint2(h0, h1);
    ((uint2*)lo)[i] = make_uint2(l0, l1);
}

struct SplitSrcs { const float *s0, *s1, *s2, *s3; };

__global__ void __launch_bounds__(256) split_w(
    SplitSrcs ss, __nv_bfloat16* __restrict__ hi, __nv_bfloat16* __restrict__ lo)
{
    int m = blockIdx.y;
    const float* s = (m == 0) ? ss.s0 : (m == 1) ? ss.s1 : (m == 2) ? ss.s2 : ss.s3;
    int i = blockIdx.x * blockDim.x + threadIdx.x;   // n4 = WW/4
    float4 v = ((const float4*)s)[i];
    uint32_t h0, l0, h1, l1;
    split_pack2(v.x, v.y, h0, l0);
    split_pack2(v.z, v.w, h1, l1);
    size_t o = (size_t)m * (WW / 4) + i;
    ((uint2*)hi)[o] = make_uint2(h0, h1);
    ((uint2*)lo)[o] = make_uint2(l0, l1);
}

// ===========================================================================
// Split-bf16 mma.sync GEMM (NT), cp.async double-buffered:
// C[M,1024] = (Ah+Al)[M,1024] @ (Bh+Bl)[1024,1024]^T + bias
// Tile 128x128, BK=32, 8 warps (2x4), warp tile 64x32. ROWB=80 pad.
// blockIdx.z selects weight/bias/output (fused QKV).
// ===========================================================================
static constexpr int BM = 128, BN = 128, BK = 32;
static constexpr int ROWB = 80;
static constexpr int MATB = 128 * ROWB;        // 10240 per matrix (128 rows)
static constexpr int OFF_AH = 0;
static constexpr int OFF_AL = MATB;
static constexpr int OFF_BH = 2 * MATB;
static constexpr int OFF_BL = 3 * MATB;
static constexpr int BUF_B  = 4 * MATB;        // 40960
static constexpr int GEMM_SMEM = 2 * BUF_B;    // 81920
static constexpr int NCHUNK = Dm / BK;         // 32

struct GemmPtrs {
    const float* bias0; const float* bias1; const float* bias2;
    float* out0; float* out1; float* out2;
    int w0, w1, w2;
};

__global__ void __launch_bounds__(256, 2) gemm_mma_bias(
    const __nv_bfloat16* __restrict__ Ah, const __nv_bfloat16* __restrict__ Al,
    const __nv_bfloat16* __restrict__ WhB, const __nv_bfloat16* __restrict__ WlB,
    GemmPtrs gp)
{
    extern __shared__ char sm[];
    const uint32_t sb = smem_u32(sm);
    const int tid  = threadIdx.x;
    const int lane = tid & 31;
    const int warp = tid >> 5;
    const int wm   = warp >> 2;   // 0..1 -> rows wm*64
    const int wn   = warp & 3;    // 0..3 -> cols wn*32

    const int z = blockIdx.z;
    const int widx = (z == 0) ? gp.w0 : (z == 1) ? gp.w1 : gp.w2;
    const float* bias = (z == 0) ? gp.bias0 : (z == 1) ? gp.bias1 : gp.bias2;
    float* C = (z == 0) ? gp.out0 : (z == 1) ? gp.out1 : gp.out2;
    const __nv_bfloat16* Bh = WhB + (size_t)widx * WW;
    const __nv_bfloat16* Bl = WlB + (size_t)widx * WW;

    const size_t aoff0 = (size_t)(blockIdx.y * BM) * Dm;
    const size_t boff0 = (size_t)(blockIdx.x * BN) * Dm;

    // cp.async slot mapping: 2048 slots/chunk (4 matrices x 128 rows x 4 segs)
    auto issue_chunk = [&](int c) {
        const int k0 = c * BK;
        const uint32_t bufb = sb + (c & 1) * BUF_B;
#pragma unroll
        for (int s = 0; s < 8; s++) {
            int idx = tid + s * 256;
            int mat = idx >> 9;
            int rr  = (idx & 511) >> 2;
            int seg = idx & 3;
            const __nv_bfloat16* src;
            if (mat == 0)      src = Ah + aoff0 + (size_t)rr * Dm + k0 + seg * 8;
            else if (mat == 1) src = Al + aoff0 + (size_t)rr * Dm + k0 + seg * 8;
            else if (mat == 2) src = Bh + boff0 + (size_t)rr * Dm + k0 + seg * 8;
            else               src = Bl + boff0 + (size_t)rr * Dm + k0 + seg * 8;
            uint32_t dst = bufb + mat * MATB + rr * ROWB + seg * 16;
            CP_ASYNC16(dst, src);
        }
        CP_COMMIT();
    };

    float acc[4][4][4];
#pragma unroll
    for (int t = 0; t < 4; t++)
#pragma unroll
        for (int n = 0; n < 4; n++)
#pragma unroll
            for (int j = 0; j < 4; j++) acc[t][n][j] = 0.f;

    const uint32_t aLM = (uint32_t)((wm * 64 + (lane & 15)) * ROWB + (lane >> 4) * 16);
    const uint32_t bLM = (uint32_t)((wn * 32 + (lane & 7) + ((lane >> 4) & 1) * 8) * ROWB
                                    + ((lane >> 3) & 1) * 16);

    issue_chunk(0);

    for (int c = 0; c < NCHUNK; c++) {
        if (c + 1 < NCHUNK) { issue_chunk(c + 1); CP_WAIT1(); }
        else                { CP_WAIT0(); }
        __syncthreads();

        const uint32_t bufb = sb + (c & 1) * BUF_B;
        const uint32_t aHiB = bufb + OFF_AH + aLM;
        const uint32_t aLoB = bufb + OFF_AL + aLM;
        const uint32_t bHiB = bufb + OFF_BH + bLM;
        const uint32_t bLoB = bufb + OFF_BL + bLM;

#pragma unroll
        for (int kk = 0; kk < BK; kk += 16) {
            uint32_t bh4[2][4], bl4[2][4];
#pragma unroll
            for (int g = 0; g < 2; g++) {
                uint32_t off = (uint32_t)(g * 16 * ROWB + kk * 2);
                LDSM4(bh4[g][0], bh4[g][1], bh4[g][2], bh4[g][3], bHiB + off);
                LDSM4(bl4[g][0], bl4[g][1], bl4[g][2], bl4[g][3], bLoB + off);
            }
#pragma unroll
            for (int t = 0; t < 4; t++) {
                uint32_t ah[4], al[4];
                uint32_t off = (uint32_t)(t * 16 * ROWB + kk * 2);
                LDSM4(ah[0], ah[1], ah[2], ah[3], aHiB + off);
                LDSM4(al[0], al[1], al[2], al[3], aLoB + off);
#pragma unroll
                for (int g = 0; g < 2; g++) {
                    MMA16816(acc[t][g * 2 + 0], ah, bh4[g][0], bh4[g][1]);
                    MMA16816(acc[t][g * 2 + 1], ah, bh4[g][2], bh4[g][3]);
                    MMA16816(acc[t][g * 2 + 0], ah, bl4[g][0], bl4[g][1]);
                    MMA16816(acc[t][g * 2 + 1], ah, bl4[g][2], bl4[g][3]);
                    MMA16816(acc[t][g * 2 + 0], al, bh4[g][0], bh4[g][1]);
                    MMA16816(acc[t][g * 2 + 1], al, bh4[g][2], bh4[g][3]);
                }
            }
        }
        __syncthreads();
    }

    // Epilogue
#pragma unroll
    for (int t = 0; t < 4; t++) {
        const int r0 = blockIdx.y * BM + wm * 64 + t * 16 + (lane >> 2);
#pragma unroll
        for (int n = 0; n < 4; n++) {
            int col = blockIdx.x * BN + wn * 32 + (lane & 3) * 2 + n * 8;
            float b0 = bias[col], b1 = bias[col + 1];
            float2 o0 = make_float2(acc[t][n][0] + b0, acc[t][n][1] + b1);
            float2 o1 = make_float2(acc[t][n][2] + b0, acc[t][n][3] + b1);
            *(float2*)&C[(size_t)r0 * Dm + col]       = o0;
            *(float2*)&C[(size_t)(r0 + 8) * Dm + col] = o1;
        }
    }
}

// ===========================================================================
// LN per head + split to head-major bf16 hi/lo: [BH][N][64]
// ===========================================================================
__global__ void __launch_bounds__(256) ln_split(
    const float* __restrict__ X, const float* __restrict__ gamma,
    const float* __restrict__ beta,
    __nv_bfloat16* __restrict__ Oh, __nv_bfloat16* __restrict__ Ol)
{
    int wid  = (blockIdx.x * blockDim.x + threadIdx.x) >> 5;
    int lane = threadIdx.x & 31;
    int row = wid >> 4;
    int h   = wid & 15;
    const float* p = X + (size_t)row * Dm + h * HDim;

    float x0 = p[lane];
    float x1 = p[lane + 32];
    float s  = x0 + x1;
    float ss = x0 * x0 + x1 * x1;
#pragma unroll
    for (int o = 16; o > 0; o >>= 1) {
        s  += __shfl_xor_sync(0xffffffffu, s,  o);
        ss += __shfl_xor_sync(0xffffffffu, ss, o);
    }
    float mean = s * (1.f / 64.f);
    float var  = ss * (1.f / 64.f) - mean * mean;
    float r    = rsqrtf(var + EPSf);
    float y0 = (x0 - mean) * r * gamma[lane]      + beta[lane];
    float y1 = (x1 - mean) * r * gamma[lane + 32] + beta[lane + 32];

    int b = row >> 11, n = row & 2047;
    size_t o = ((size_t)(b * Hh + h) * Nseq + n) * HDim;
    __nv_bfloat16 h0 = __float2bfloat16(y0);
    __nv_bfloat16 h1 = __float2bfloat16(y1);
    Oh[o + lane]      = h0;
    Oh[o + lane + 32] = h1;
    Ol[o + lane]      = __float2bfloat16(y0 - __bfloat162float(h0));
    Ol[o + lane + 32] = __float2bfloat16(y1 - __bfloat162float(h1));
}

// ===========================================================================
// V transpose + split: g_V [B,N,D] -> VT [BH][64(d)][N] bf16 hi/lo
// ===========================================================================
__global__ void __launch_bounds__(256) v_splitT(
    const float* __restrict__ V,
    __nv_bfloat16* __restrict__ VTh, __nv_bfloat16* __restrict__ VTl)
{
    __shared__ float st[64][68];
    const int tid = threadIdx.x;
    const int bh = blockIdx.y;
    const int n0 = blockIdx.x * 64;
    const int b = bh >> 4, h = bh & 15;

    int j = tid >> 2, dseg = tid & 3;
    const float* gp = V + (size_t)(b * Nseq + n0 + j) * Dm + h * HDim + dseg * 16;
#pragma unroll
    for (int q = 0; q < 4; q++)
        *(float4*)&st[j][dseg * 16 + q * 4] = *(const float4*)(gp + q * 4);
    __syncthreads();

    int d = tid >> 2, nseg = tid & 3;
    size_t o = ((size_t)bh * HDim + d) * Nseq + n0 + nseg * 16;
#pragma unroll
    for (int jj = 0; jj < 16; jj++) {
        float v = st[nseg * 16 + jj][d];
        __nv_bfloat16 hv = __float2bfloat16(v);
        VTh[o + jj] = hv;
        VTl[o + jj] = __float2bfloat16(v - __bfloat162float(hv));
    }
}

// ===========================================================================
// Flash attention, split-bf16 mma.sync (unchanged from R4 — proven)
// ===========================================================================
static constexpr int AROWB = 144;
static constexpr int A_QH = 0;
static constexpr int A_QL = A_QH + 64 * AROWB;
static constexpr int A_KH = A_QL + 64 * AROWB;
static constexpr int A_KL = A_KH + 64 * AROWB;
static constexpr int A_VH = A_KL + 64 * AROWB;
static constexpr int A_VL = A_VH + 64 * AROWB;
static constexpr int A_PH = A_VL + 64 * AROWB;
static constexpr int A_PL = A_PH + 64 * AROWB;
static constexpr int A_SS = A_PL + 64 * AROWB;
static constexpr int A_MS = A_SS + 64 * 68 * 4;
static constexpr int A_LS = A_MS + 256;
static constexpr int A_AL = A_LS + 256;
static constexpr int ATTN_SMEM = A_AL + 256;

__global__ void __launch_bounds__(256, 2) attn_mma(
    const __nv_bfloat16* __restrict__ Qh, const __nv_bfloat16* __restrict__ Ql,
    const __nv_bfloat16* __restrict__ Kh, const __nv_bfloat16* __restrict__ Kl,
    const __nv_bfloat16* __restrict__ Vh, const __nv_bfloat16* __restrict__ Vl,
    __nv_bfloat16* __restrict__ Ch, __nv_bfloat16* __restrict__ Cl)
{
    extern __shared__ char sm[];
    const uint32_t sb = smem_u32(sm);
    const int tid  = threadIdx.x;
    const int lane = tid & 31;
    const int warp = tid >> 5;
    const int wm   = warp >> 1;
    const int wn   = warp & 1;
    const int bh = blockIdx.y;
    const int q0 = blockIdx.x * 64;
    const float scale = 0.125f;

    float* m_s  = (float*)(sm + A_MS);
    float* l_s  = (float*)(sm + A_LS);
    float* al_s = (float*)(sm + A_AL);

    {
        const size_t qb = ((size_t)bh * Nseq + q0) * HDim;
#pragma unroll
        for (int it = 0; it < 2; it++) {
            int idx = tid + it * 256;
            int r = idx >> 3, seg = idx & 7;
            *(uint4*)(sm + A_QH + r * AROWB + seg * 16) = *(const uint4*)(Qh + qb + r * 64 + seg * 8);
            *(uint4*)(sm + A_QL + r * AROWB + seg * 16) = *(const uint4*)(Ql + qb + r * 64 + seg * 8);
        }
    }
    if (tid < 64) { m_s[tid] = -1e30f; l_s[tid] = 0.f; }
    __syncthreads();

    uint32_t qfh[4][4], qfl[4][4];
    {
        uint32_t aoff = sb + A_QH + (uint32_t)((wm * 16 + (lane & 15)) * AROWB + (lane >> 4) * 16);
#pragma unroll
        for (int ks = 0; ks < 4; ks++) {
            LDSM4(qfh[ks][0], qfh[ks][1], qfh[ks][2], qfh[ks][3], aoff + ks * 32);
            LDSM4(qfl[ks][0], qfl[ks][1], qfl[ks][2], qfl[ks][3], aoff + (A_QL - A_QH) + ks * 32);
        }
    }

    float acc[4][4];
#pragma unroll
    for (int n = 0; n < 4; n++)
#pragma unroll
        for (int j = 0; j < 4; j++) acc[n][j] = 0.f;

    const uint32_t bfrag = (uint32_t)((wn * 32 + (lane & 7) + ((lane >> 4) & 1) * 8) * AROWB
                                      + ((lane >> 3) & 1) * 16);
    const int r0 = wm * 16 + (lane >> 2);
    const int c0 = wn * 32 + (lane & 3) * 2;
    float* Ss = (float*)(sm + A_SS);

    for (int kt = 0; kt < Nseq; kt += 64) {
        {
            const size_t kb = ((size_t)bh * Nseq + kt) * HDim;
#pragma unroll
            for (int it = 0; it < 2; it++) {
                int idx = tid + it * 256;
                int r = idx >> 3, seg = idx & 7;
                *(uint4*)(sm + A_KH + r * AROWB + seg * 16) = *(const uint4*)(Kh + kb + r * 64 + seg * 8);
                *(uint4*)(sm + A_KL + r * AROWB + seg * 16) = *(const uint4*)(Kl + kb + r * 64 + seg * 8);
                const size_t vb = ((size_t)bh * HDim + r) * Nseq + kt;
                *(uint4*)(sm + A_VH + r * AROWB + seg * 16) = *(const uint4*)(Vh + vb + seg * 8);
                *(uint4*)(sm + A_VL + r * AROWB + seg * 16) = *(const uint4*)(Vl + vb + seg * 8);
            }
        }
        __syncthreads();

        float sacc[4][4];
#pragma unroll
        for (int n = 0; n < 4; n++)
#pragma unroll
            for (int j = 0; j < 4; j++) sacc[n][j] = 0.f;

#pragma unroll
        for (int ks = 0; ks < 4; ks++) {
            uint32_t kh4[2][4], kl4[2][4];
#pragma unroll
            for (int g = 0; g < 2; g++) {
                uint32_t off = bfrag + (uint32_t)(g * 16 * AROWB + ks * 32);
                LDSM4(kh4[g][0], kh4[g][1], kh4[g][2], kh4[g][3], sb + A_KH + off);
                LDSM4(kl4[g][0], kl4[g][1], kl4[g][2], kl4[g][3], sb + A_KL + off);
            }
#pragma unroll
            for (int g = 0; g < 2; g++) {
                MMA16816(sacc[g * 2 + 0], qfh[ks], kh4[g][0], kh4[g][1]);
                MMA16816(sacc[g * 2 + 1], qfh[ks], kh4[g][2], kh4[g][3]);
                MMA16816(sacc[g * 2 + 0], qfh[ks], kl4[g][0], kl4[g][1]);
                MMA16816(sacc[g * 2 + 1], qfh[ks], kl4[g][2], kl4[g][3]);
                MMA16816(sacc[g * 2 + 0], qfl[ks], kh4[g][0], kh4[g][1]);
                MMA16816(sacc[g * 2 + 1], qfl[ks], kh4[g][2], kh4[g][3]);
            }
        }
#pragma unroll
        for (int n = 0; n < 4; n++) {
            int col = c0 + n * 8;
            Ss[r0 * 68 + col]           = sacc[n][0] * scale;
            Ss[r0 * 68 + col + 1]       = sacc[n][1] * scale;
            Ss[(r0 + 8) * 68 + col]     = sacc[n][2] * scale;
            Ss[(r0 + 8) * 68 + col + 1] = sacc[n][3] * scale;
        }
        __syncthreads();

        {
            int q    = tid >> 2;
            int part = tid & 3;
            float* row = Ss + q * 68 + part * 16;
            float mx = -1e30f;
#pragma unroll
            for (int j = 0; j < 16; j++) mx = fmaxf(mx, row[j]);
            mx = fmaxf(mx, __shfl_xor_sync(0xffffffffu, mx, 1));
            mx = fmaxf(mx, __shfl_xor_sync(0xffffffffu, mx, 2));
            float mold = m_s[q];
            float mnew = fmaxf(mold, mx);
            float lsum = 0.f;
            uint32_t* phw = (uint32_t*)(sm + A_PH + q * AROWB + part * 32);
            uint32_t* plw = (uint32_t*)(sm + A_PL + q * AROWB + part * 32);
#pragma unroll
            for (int j = 0; j < 8; j++) {
                float p0 = __expf(row[2 * j]     - mnew);
                float p1 = __expf(row[2 * j + 1] - mnew);
                lsum += p0 + p1;
                uint32_t hw, lw;
                split_pack2(p0, p1, hw, lw);
                phw[j] = hw;
                plw[j] = lw;
            }
            lsum += __shfl_xor_sync(0xffffffffu, lsum, 1);
            lsum += __shfl_xor_sync(0xffffffffu, lsum, 2);
            if (part == 0) {
                float alpha = __expf(mold - mnew);
                m_s[q]  = mnew;
                l_s[q]  = l_s[q] * alpha + lsum;
                al_s[q] = alpha;
            }
        }
        __syncthreads();

        {
            float al0 = al_s[r0];
            float al1 = al_s[r0 + 8];
#pragma unroll
            for (int n = 0; n < 4; n++) {
                acc[n][0] *= al0; acc[n][1] *= al0;
                acc[n][2] *= al1; acc[n][3] *= al1;
            }
        }

        {
            uint32_t poff = sb + A_PH + (uint32_t)((wm * 16 + (lane & 15)) * AROWB + (lane >> 4) * 16);
#pragma unroll
            for (int ks = 0; ks < 4; ks++) {
                uint32_t pf[4], pfl[4];
                LDSM4(pf[0], pf[1], pf[2], pf[3], poff + ks * 32);
                LDSM4(pfl[0], pfl[1], pfl[2], pfl[3], poff + (A_PL - A_PH) + ks * 32);
                uint32_t vh4[2][4], vl4[2][4];
#pragma unroll
                for (int g = 0; g < 2; g++) {
                    uint32_t off = bfrag + (uint32_t)(g * 16 * AROWB + ks * 32);
                    LDSM4(vh4[g][0], vh4[g][1], vh4[g][2], vh4[g][3], sb + A_VH + off);
                    LDSM4(vl4[g][0], vl4[g][1], vl4[g][2], vl4[g][3], sb + A_VL + off);
                }
#pragma unroll
                for (int g = 0; g < 2; g++) {
                    MMA16816(acc[g * 2 + 0], pf,  vh4[g][0], vh4[g][1]);
                    MMA16816(acc[g * 2 + 1], pf,  vh4[g][2], vh4[g][3]);
                    MMA16816(acc[g * 2 + 0], pf,  vl4[g][0], vl4[g][1]);
                    MMA16816(acc[g * 2 + 1], pf,  vl4[g][2], vl4[g][3]);
                    MMA16816(acc[g * 2 + 0], pfl, vh4[g][0], vh4[g][1]);
                    MMA16816(acc[g * 2 + 1], pfl, vh4[g][2], vh4[g][3]);
                }
            }
        }
        __syncthreads();
    }

    {
        float inv0 = 1.f / l_s[r0];
        float inv1 = 1.f / l_s[r0 + 8];
        const int b = bh >> 4, h = bh & 15;
        const size_t rowA = (size_t)(b * Nseq + q0 + r0) * Dm;
        const size_t rowB = (size_t)(b * Nseq + q0 + r0 + 8) * Dm;
#pragma unroll
        for (int n = 0; n < 4; n++) {
            int col = h * HDim + c0 + n * 8;
            uint32_t hw, lw;
            split_pack2(acc[n][0] * inv0, acc[n][1] * inv0, hw, lw);
            *(uint32_t*)&Ch[rowA + col] = hw;
            *(uint32_t*)&Cl[rowA + col] = lw;
            split_pack2(acc[n][2] * inv1, acc[n][3] * inv1, hw, lw);
            *(uint32_t*)&Ch[rowB + col] = hw;
            *(uint32_t*)&Cl[rowB + col] = lw;
        }
    }
}

// ---------------------------------------------------------------------------
// Launch
// ---------------------------------------------------------------------------
extern "C" void kernel_launch(void* const* d_in, const int* in_sizes, int n_in,
                              void* d_out, int out_size)
{
    const float* x  = (const float*)d_in[0];
    const float* Wq = (const float*)d_in[1];
    const float* bq = (const float*)d_in[2];
    const float* Wk = (const float*)d_in[3];
    const float* bk = (const float*)d_in[4];
    const float* Wv = (const float*)d_in[5];
    const float* bv = (const float*)d_in[6];
    const float* Wp = (const float*)d_in[7];
    const float* bp = (const float*)d_in[8];
    const float* qg = (const float*)d_in[9];
    const float* qb = (const float*)d_in[10];
    const float* kg = (const float*)d_in[11];
    const float* kb_ = (const float*)d_in[12];
    float* out = (float*)d_out;

    float *Qp, *Kp, *Vp;
    cudaGetSymbolAddress((void**)&Qp, g_Q);
    cudaGetSymbolAddress((void**)&Kp, g_K);
    cudaGetSymbolAddress((void**)&Vp, g_V);
    __nv_bfloat16 *Xh, *Xl, *Wh, *Wl, *Qhp, *Qlp, *Khp, *Klp, *VTh, *VTl, *Chp, *Clp;
    cudaGetSymbolAddress((void**)&Xh, g_Xh);
    cudaGetSymbolAddress((void**)&Xl, g_Xl);
    cudaGetSymbolAddress((void**)&Wh, g_Wh);
    cudaGetSymbolAddress((void**)&Wl, g_Wl);
    cudaGetSymbolAddress((void**)&Qhp, g_Qh);
    cudaGetSymbolAddress((void**)&Qlp, g_Ql);
    cudaGetSymbolAddress((void**)&Khp, g_Kh);
    cudaGetSymbolAddress((void**)&Klp, g_Kl);
    cudaGetSymbolAddress((void**)&VTh, g_VTh);
    cudaGetSymbolAddress((void**)&VTl, g_VTl);
    cudaGetSymbolAddress((void**)&Chp, g_Ch);
    cudaGetSymbolAddress((void**)&Clp, g_Cl);

    cudaFuncSetAttribute(gemm_mma_bias,
                         cudaFuncAttributeMaxDynamicSharedMemorySize, GEMM_SMEM);
    cudaFuncSetAttribute(attn_mma,
                         cudaFuncAttributeMaxDynamicSharedMemorySize, ATTN_SMEM);

    // Splits
    split_f32<<<(Mrows * Dm / 4 + 255) / 256, 256>>>(x, Xh, Xl, Mrows * Dm / 4);
    SplitSrcs ss{Wq, Wk, Wv, Wp};
    split_w<<<dim3(WW / 4 / 256, 4), 256>>>(ss, Wh, Wl);

    // Fused QKV GEMM (z = 0:Q, 1:K, 2:V)
    {
        GemmPtrs gp{bq, bk, bv, Qp, Kp, Vp, 0, 1, 2};
        gemm_mma_bias<<<dim3(Dm / BN, Mrows / BM, 3), 256, GEMM_SMEM>>>(
            Xh, Xl, Wh, Wl, gp);
    }

    // LN + split; V transpose + split
    ln_split<<<Mrows * Hh / 8, 256>>>(Qp, qg, qb, Qhp, Qlp);
    ln_split<<<Mrows * Hh / 8, 256>>>(Kp, kg, kb_, Khp, Klp);
    v_splitT<<<dim3(Nseq / 64, Bq * Hh), 256>>>(Vp, VTh, VTl);

    // Attention
    attn_mma<<<dim3(Nseq / 64, Bq * Hh), 256, ATTN_SMEM>>>(
        Qhp, Qlp, Khp, Klp, VTh, VTl, Chp, Clp);

    // Output projection (z = 0 only)
    {
        GemmPtrs gp{bp, bp, bp, out, out, out, 3, 3, 3};
        gemm_mma_bias<<<dim3(Dm / BN, Mrows / BM, 1), 256, GEMM_SMEM>>>(
            Chp, Clp, Wh, Wl, gp);
    }
}

// round 6
// speedup vs baseline: 3.4762x; 1.1799x over previous
#include <cuda_runtime.h>
#include <cuda_bf16.h>
#include <cstdint>

// Problem constants
static constexpr int Bq    = 2;
static constexpr int Nseq  = 2048;
static constexpr int Dm    = 1024;
static constexpr int Hh    = 16;
static constexpr int HDim  = 64;
static constexpr int Mrows = Bq * Nseq;  // 4096
static constexpr float EPSf = 1e-5f;
static constexpr int WW = Dm * Dm;

// ---------------------------------------------------------------------------
// Device-global scratch (allocation-free rule)
// ---------------------------------------------------------------------------
__device__ float g_Q[Mrows * Dm];
__device__ float g_K[Mrows * Dm];
__device__ float g_V[Mrows * Dm];

__device__ __nv_bfloat16 g_Xh[Mrows * Dm], g_Xl[Mrows * Dm];
__device__ __nv_bfloat16 g_Wh[4][WW], g_Wl[4][WW];
__device__ __nv_bfloat16 g_Qh[Mrows * Dm], g_Ql[Mrows * Dm];   // [BH][N][64]
__device__ __nv_bfloat16 g_Kh[Mrows * Dm], g_Kl[Mrows * Dm];   // [BH][N][64]
__device__ __nv_bfloat16 g_VTh[Mrows * Dm], g_VTl[Mrows * Dm]; // [BH][64][N]
__device__ __nv_bfloat16 g_Ch[Mrows * Dm], g_Cl[Mrows * Dm];   // [B*N][D]

// ===========================================================================
// Helpers (base-target PTX only: ldmatrix + mma.sync + cp.async)
// ===========================================================================
__device__ __forceinline__ uint32_t smem_u32(const void* p) {
    uint32_t a;
    asm("{ .reg .u64 t; cvta.to.shared.u64 t, %1; cvt.u32.u64 %0, t; }"
        : "=r"(a) : "l"(p));
    return a;
}

#define LDSM4(r0, r1, r2, r3, addr) \
    asm volatile("ldmatrix.sync.aligned.m8n8.x4.shared.b16 {%0,%1,%2,%3}, [%4];" \
        : "=r"(r0), "=r"(r1), "=r"(r2), "=r"(r3) : "r"(addr))

#define MMA16816(c, a, b0v, b1v) \
    asm volatile("mma.sync.aligned.m16n8k16.row.col.f32.bf16.bf16.f32 " \
        "{%0,%1,%2,%3}, {%4,%5,%6,%7}, {%8,%9}, {%0,%1,%2,%3};" \
        : "+f"((c)[0]), "+f"((c)[1]), "+f"((c)[2]), "+f"((c)[3]) \
        : "r"((a)[0]), "r"((a)[1]), "r"((a)[2]), "r"((a)[3]), \
          "r"(b0v), "r"(b1v))

#define CP_ASYNC16(dst, src) \
    asm volatile("cp.async.cg.shared.global [%0], [%1], 16;" :: "r"(dst), "l"(src))
#define CP_COMMIT()  asm volatile("cp.async.commit_group;" ::: "memory")
#define CP_WAIT1()   asm volatile("cp.async.wait_group 1;" ::: "memory")
#define CP_WAIT0()   asm volatile("cp.async.wait_group 0;" ::: "memory")

__device__ __forceinline__ void split_pack2(float x, float y, uint32_t& hi, uint32_t& lo) {
    __nv_bfloat162 h = __floats2bfloat162_rn(x, y);
    float hx = __bfloat162float(h.x), hy = __bfloat162float(h.y);
    __nv_bfloat162 l = __floats2bfloat162_rn(x - hx, y - hy);
    hi = *(uint32_t*)&h;
    lo = *(uint32_t*)&l;
}

// ===========================================================================
// Elementwise splits
// ===========================================================================
__global__ void __launch_bounds__(256) split_f32(
    const float* __restrict__ s, __nv_bfloat16* __restrict__ hi,
    __nv_bfloat16* __restrict__ lo, int n4)
{
    int i = blockIdx.x * blockDim.x + threadIdx.x;
    if (i >= n4) return;
    float4 v = ((const float4*)s)[i];
    uint32_t h0, l0, h1, l1;
    split_pack2(v.x, v.y, h0, l0);
    split_pack2(v.z, v.w, h1, l1);
    ((uint2*)hi)[i] = make_uint2(h0, h1);
    ((uint2*)lo)[i] = make_uint2(l0, l1);
}

struct SplitSrcs { const float *s0, *s1, *s2, *s3; };

__global__ void __launch_bounds__(256) split_w(
    SplitSrcs ss, __nv_bfloat16* __restrict__ hi, __nv_bfloat16* __restrict__ lo)
{
    int m = blockIdx.y;
    const float* s = (m == 0) ? ss.s0 : (m == 1) ? ss.s1 : (m == 2) ? ss.s2 : ss.s3;
    int i = blockIdx.x * blockDim.x + threadIdx.x;
    float4 v = ((const float4*)s)[i];
    uint32_t h0, l0, h1, l1;
    split_pack2(v.x, v.y, h0, l0);
    split_pack2(v.z, v.w, h1, l1);
    size_t o = (size_t)m * (WW / 4) + i;
    ((uint2*)hi)[o] = make_uint2(h0, h1);
    ((uint2*)lo)[o] = make_uint2(l0, l1);
}

// ===========================================================================
// Split-bf16 mma.sync GEMM (unchanged from R5 — proven)
// ===========================================================================
static constexpr int BM = 128, BN = 128, BK = 32;
static constexpr int ROWB = 80;
static constexpr int MATB = 128 * ROWB;
static constexpr int OFF_AH = 0;
static constexpr int OFF_AL = MATB;
static constexpr int OFF_BH = 2 * MATB;
static constexpr int OFF_BL = 3 * MATB;
static constexpr int BUF_B  = 4 * MATB;
static constexpr int GEMM_SMEM = 2 * BUF_B;
static constexpr int NCHUNK = Dm / BK;

struct GemmPtrs {
    const float* bias0; const float* bias1; const float* bias2;
    float* out0; float* out1; float* out2;
    int w0, w1, w2;
};

__global__ void __launch_bounds__(256, 2) gemm_mma_bias(
    const __nv_bfloat16* __restrict__ Ah, const __nv_bfloat16* __restrict__ Al,
    const __nv_bfloat16* __restrict__ WhB, const __nv_bfloat16* __restrict__ WlB,
    GemmPtrs gp)
{
    extern __shared__ char sm[];
    const uint32_t sb = smem_u32(sm);
    const int tid  = threadIdx.x;
    const int lane = tid & 31;
    const int warp = tid >> 5;
    const int wm   = warp >> 2;
    const int wn   = warp & 3;

    const int z = blockIdx.z;
    const int widx = (z == 0) ? gp.w0 : (z == 1) ? gp.w1 : gp.w2;
    const float* bias = (z == 0) ? gp.bias0 : (z == 1) ? gp.bias1 : gp.bias2;
    float* C = (z == 0) ? gp.out0 : (z == 1) ? gp.out1 : gp.out2;
    const __nv_bfloat16* Bh = WhB + (size_t)widx * WW;
    const __nv_bfloat16* Bl = WlB + (size_t)widx * WW;

    const size_t aoff0 = (size_t)(blockIdx.y * BM) * Dm;
    const size_t boff0 = (size_t)(blockIdx.x * BN) * Dm;

    auto issue_chunk = [&](int c) {
        const int k0 = c * BK;
        const uint32_t bufb = sb + (c & 1) * BUF_B;
#pragma unroll
        for (int s = 0; s < 8; s++) {
            int idx = tid + s * 256;
            int mat = idx >> 9;
            int rr  = (idx & 511) >> 2;
            int seg = idx & 3;
            const __nv_bfloat16* src;
            if (mat == 0)      src = Ah + aoff0 + (size_t)rr * Dm + k0 + seg * 8;
            else if (mat == 1) src = Al + aoff0 + (size_t)rr * Dm + k0 + seg * 8;
            else if (mat == 2) src = Bh + boff0 + (size_t)rr * Dm + k0 + seg * 8;
            else               src = Bl + boff0 + (size_t)rr * Dm + k0 + seg * 8;
            uint32_t dst = bufb + mat * MATB + rr * ROWB + seg * 16;
            CP_ASYNC16(dst, src);
        }
        CP_COMMIT();
    };

    float acc[4][4][4];
#pragma unroll
    for (int t = 0; t < 4; t++)
#pragma unroll
        for (int n = 0; n < 4; n++)
#pragma unroll
            for (int j = 0; j < 4; j++) acc[t][n][j] = 0.f;

    const uint32_t aLM = (uint32_t)((wm * 64 + (lane & 15)) * ROWB + (lane >> 4) * 16);
    const uint32_t bLM = (uint32_t)((wn * 32 + (lane & 7) + ((lane >> 4) & 1) * 8) * ROWB
                                    + ((lane >> 3) & 1) * 16);

    issue_chunk(0);

    for (int c = 0; c < NCHUNK; c++) {
        if (c + 1 < NCHUNK) { issue_chunk(c + 1); CP_WAIT1(); }
        else                { CP_WAIT0(); }
        __syncthreads();

        const uint32_t bufb = sb + (c & 1) * BUF_B;
        const uint32_t aHiB = bufb + OFF_AH + aLM;
        const uint32_t aLoB = bufb + OFF_AL + aLM;
        const uint32_t bHiB = bufb + OFF_BH + bLM;
        const uint32_t bLoB = bufb + OFF_BL + bLM;

#pragma unroll
        for (int kk = 0; kk < BK; kk += 16) {
            uint32_t bh4[2][4], bl4[2][4];
#pragma unroll
            for (int g = 0; g < 2; g++) {
                uint32_t off = (uint32_t)(g * 16 * ROWB + kk * 2);
                LDSM4(bh4[g][0], bh4[g][1], bh4[g][2], bh4[g][3], bHiB + off);
                LDSM4(bl4[g][0], bl4[g][1], bl4[g][2], bl4[g][3], bLoB + off);
            }
#pragma unroll
            for (int t = 0; t < 4; t++) {
                uint32_t ah[4], al[4];
                uint32_t off = (uint32_t)(t * 16 * ROWB + kk * 2);
                LDSM4(ah[0], ah[1], ah[2], ah[3], aHiB + off);
                LDSM4(al[0], al[1], al[2], al[3], aLoB + off);
#pragma unroll
                for (int g = 0; g < 2; g++) {
                    MMA16816(acc[t][g * 2 + 0], ah, bh4[g][0], bh4[g][1]);
                    MMA16816(acc[t][g * 2 + 1], ah, bh4[g][2], bh4[g][3]);
                    MMA16816(acc[t][g * 2 + 0], ah, bl4[g][0], bl4[g][1]);
                    MMA16816(acc[t][g * 2 + 1], ah, bl4[g][2], bl4[g][3]);
                    MMA16816(acc[t][g * 2 + 0], al, bh4[g][0], bh4[g][1]);
                    MMA16816(acc[t][g * 2 + 1], al, bh4[g][2], bh4[g][3]);
                }
            }
        }
        __syncthreads();
    }

#pragma unroll
    for (int t = 0; t < 4; t++) {
        const int r0 = blockIdx.y * BM + wm * 64 + t * 16 + (lane >> 2);
#pragma unroll
        for (int n = 0; n < 4; n++) {
            int col = blockIdx.x * BN + wn * 32 + (lane & 3) * 2 + n * 8;
            float b0 = bias[col], b1 = bias[col + 1];
            float2 o0 = make_float2(acc[t][n][0] + b0, acc[t][n][1] + b1);
            float2 o1 = make_float2(acc[t][n][2] + b0, acc[t][n][3] + b1);
            *(float2*)&C[(size_t)r0 * Dm + col]       = o0;
            *(float2*)&C[(size_t)(r0 + 8) * Dm + col] = o1;
        }
    }
}

// ===========================================================================
// LN per head + split to head-major bf16 hi/lo: [BH][N][64]
// ===========================================================================
__global__ void __launch_bounds__(256) ln_split(
    const float* __restrict__ X, const float* __restrict__ gamma,
    const float* __restrict__ beta,
    __nv_bfloat16* __restrict__ Oh, __nv_bfloat16* __restrict__ Ol)
{
    int wid  = (blockIdx.x * blockDim.x + threadIdx.x) >> 5;
    int lane = threadIdx.x & 31;
    int row = wid >> 4;
    int h   = wid & 15;
    const float* p = X + (size_t)row * Dm + h * HDim;

    float x0 = p[lane];
    float x1 = p[lane + 32];
    float s  = x0 + x1;
    float ss = x0 * x0 + x1 * x1;
#pragma unroll
    for (int o = 16; o > 0; o >>= 1) {
        s  += __shfl_xor_sync(0xffffffffu, s,  o);
        ss += __shfl_xor_sync(0xffffffffu, ss, o);
    }
    float mean = s * (1.f / 64.f);
    float var  = ss * (1.f / 64.f) - mean * mean;
    float r    = rsqrtf(var + EPSf);
    float y0 = (x0 - mean) * r * gamma[lane]      + beta[lane];
    float y1 = (x1 - mean) * r * gamma[lane + 32] + beta[lane + 32];

    int b = row >> 11, n = row & 2047;
    size_t o = ((size_t)(b * Hh + h) * Nseq + n) * HDim;
    __nv_bfloat16 h0 = __float2bfloat16(y0);
    __nv_bfloat16 h1 = __float2bfloat16(y1);
    Oh[o + lane]      = h0;
    Oh[o + lane + 32] = h1;
    Ol[o + lane]      = __float2bfloat16(y0 - __bfloat162float(h0));
    Ol[o + lane + 32] = __float2bfloat16(y1 - __bfloat162float(h1));
}

// ===========================================================================
// V transpose + split: g_V [B,N,D] -> VT [BH][64(d)][N] bf16 hi/lo
// ===========================================================================
__global__ void __launch_bounds__(256) v_splitT(
    const float* __restrict__ V,
    __nv_bfloat16* __restrict__ VTh, __nv_bfloat16* __restrict__ VTl)
{
    __shared__ float st[64][68];
    const int tid = threadIdx.x;
    const int bh = blockIdx.y;
    const int n0 = blockIdx.x * 64;
    const int b = bh >> 4, h = bh & 15;

    int j = tid >> 2, dseg = tid & 3;
    const float* gp = V + (size_t)(b * Nseq + n0 + j) * Dm + h * HDim + dseg * 16;
#pragma unroll
    for (int q = 0; q < 4; q++)
        *(float4*)&st[j][dseg * 16 + q * 4] = *(const float4*)(gp + q * 4);
    __syncthreads();

    int d = tid >> 2, nseg = tid & 3;
    size_t o = ((size_t)bh * HDim + d) * Nseq + n0 + nseg * 16;
#pragma unroll
    for (int jj = 0; jj < 16; jj++) {
        float v = st[nseg * 16 + jj][d];
        __nv_bfloat16 hv = __float2bfloat16(v);
        VTh[o + jj] = hv;
        VTl[o + jj] = __float2bfloat16(v - __bfloat162float(hv));
    }
}

// ===========================================================================
// Flash attention, FA2-style register softmax. CTA = 128 q-rows x (b,h).
// 8 warps x 16 q-rows each; warp spans all 64 k-cols / 64 d-cols.
// K/V double-buffered via cp.async; Q staged once then held as fragments.
// S never touches smem: C-frag -> A-frag register reinterpretation for P.
// ===========================================================================
static constexpr int KVROWB = 144;            // 128B data + 16 pad
static constexpr int KVMAT  = 64 * KVROWB;    // 9216
static constexpr int KVBUF  = 4 * KVMAT;      // 36864 (KH,KL,VH,VL)
static constexpr int ATTN_SMEM = 2 * KVBUF;   // 73728

__global__ void __launch_bounds__(256, 2) attn_mma(
    const __nv_bfloat16* __restrict__ Qh, const __nv_bfloat16* __restrict__ Ql,
    const __nv_bfloat16* __restrict__ Kh, const __nv_bfloat16* __restrict__ Kl,
    const __nv_bfloat16* __restrict__ Vh, const __nv_bfloat16* __restrict__ Vl,
    __nv_bfloat16* __restrict__ Ch, __nv_bfloat16* __restrict__ Cl)
{
    extern __shared__ char sm[];
    const uint32_t sb = smem_u32(sm);
    const int tid  = threadIdx.x;
    const int lane = tid & 31;
    const int warp = tid >> 5;        // 0..7, owns q rows warp*16..+15
    const int bh = blockIdx.y;
    const int q0 = blockIdx.x * 128;
    const float scale = 0.125f;

    auto issue_kv = [&](int c) {
        const uint32_t bufb = sb + (c & 1) * KVBUF;
        const int kt = c * 64;
#pragma unroll
        for (int s = 0; s < 8; s++) {
            int idx = tid + s * 256;
            int mat = idx >> 9;           // 0:KH 1:KL 2:VH 3:VL
            int rr  = (idx >> 3) & 63;
            int seg = idx & 7;
            const __nv_bfloat16* src;
            if (mat == 0)      src = Kh + ((size_t)bh * Nseq + kt + rr) * HDim + seg * 8;
            else if (mat == 1) src = Kl + ((size_t)bh * Nseq + kt + rr) * HDim + seg * 8;
            else if (mat == 2) src = Vh + ((size_t)bh * HDim + rr) * Nseq + kt + seg * 8;
            else               src = Vl + ((size_t)bh * HDim + rr) * Nseq + kt + seg * 8;
            CP_ASYNC16(bufb + mat * KVMAT + rr * KVROWB + seg * 16, src);
        }
        CP_COMMIT();
    };

    // Prologue: stage Q (hi 128x144 @ buf1+0, lo @ buf1+18432), then KV chunk 0
    {
        const uint32_t qst = sb + KVBUF;
#pragma unroll
        for (int s = 0; s < 8; s++) {
            int idx = tid + s * 256;
            int mat = idx >> 10;          // 0:QH 1:QL
            int rr  = (idx >> 3) & 127;
            int seg = idx & 7;
            const __nv_bfloat16* src = (mat == 0)
                ? Qh + ((size_t)bh * Nseq + q0 + rr) * HDim + seg * 8
                : Ql + ((size_t)bh * Nseq + q0 + rr) * HDim + seg * 8;
            CP_ASYNC16(qst + mat * 18432 + rr * KVROWB + seg * 16, src);
        }
        CP_COMMIT();
    }
    issue_kv(0);
    CP_WAIT0();
    __syncthreads();

    // Q fragments (held in registers for whole kernel)
    uint32_t qfh[4][4], qfl[4][4];
    {
        const uint32_t qst = sb + KVBUF
            + (uint32_t)((warp * 16 + (lane & 15)) * KVROWB + (lane >> 4) * 16);
#pragma unroll
        for (int ks = 0; ks < 4; ks++) {
            LDSM4(qfh[ks][0], qfh[ks][1], qfh[ks][2], qfh[ks][3], qst + ks * 32);
            LDSM4(qfl[ks][0], qfl[ks][1], qfl[ks][2], qfl[ks][3], qst + 18432 + ks * 32);
        }
    }
    __syncthreads();   // Q staging read complete; buf1 free for chunk 1

    float acc[8][4];
#pragma unroll
    for (int n = 0; n < 8; n++)
#pragma unroll
        for (int j = 0; j < 4; j++) acc[n][j] = 0.f;
    float m0 = -1e30f, m1 = -1e30f, l0 = 0.f, l1 = 0.f;

    // B-fragment ldmatrix offset (rows = n or d, cols = k)
    const uint32_t bfr = (uint32_t)(((lane & 7) + ((lane >> 4) & 1) * 8) * KVROWB
                                    + ((lane >> 3) & 1) * 16);

    for (int c = 0; c < Nseq / 64; c++) {
        if (c + 1 < Nseq / 64) { issue_kv(c + 1); CP_WAIT1(); }
        else                   { CP_WAIT0(); }
        __syncthreads();

        const uint32_t bufb = sb + (c & 1) * KVBUF;

        // ---- S = Q K^T (split 3-product), C-fragments in registers ----
        float sacc[8][4];
#pragma unroll
        for (int n = 0; n < 8; n++)
#pragma unroll
            for (int j = 0; j < 4; j++) sacc[n][j] = 0.f;

#pragma unroll
        for (int ks = 0; ks < 4; ks++) {
#pragma unroll
            for (int ntp = 0; ntp < 4; ntp++) {
                uint32_t kaddr = bufb + bfr + (uint32_t)(ntp * 16 * KVROWB + ks * 32);
                uint32_t kh4[4], kl4[4];
                LDSM4(kh4[0], kh4[1], kh4[2], kh4[3], kaddr);
                LDSM4(kl4[0], kl4[1], kl4[2], kl4[3], kaddr + KVMAT);
                MMA16816(sacc[2 * ntp + 0], qfh[ks], kh4[0], kh4[1]);
                MMA16816(sacc[2 * ntp + 1], qfh[ks], kh4[2], kh4[3]);
                MMA16816(sacc[2 * ntp + 0], qfh[ks], kl4[0], kl4[1]);
                MMA16816(sacc[2 * ntp + 1], qfh[ks], kl4[2], kl4[3]);
                MMA16816(sacc[2 * ntp + 0], qfl[ks], kh4[0], kh4[1]);
                MMA16816(sacc[2 * ntp + 1], qfl[ks], kh4[2], kh4[3]);
            }
        }

        // ---- online softmax in registers (rows g = lane>>2 and g+8) ----
        float mx0 = -1e30f, mx1 = -1e30f;
#pragma unroll
        for (int n = 0; n < 8; n++) {
            mx0 = fmaxf(mx0, fmaxf(sacc[n][0], sacc[n][1]));
            mx1 = fmaxf(mx1, fmaxf(sacc[n][2], sacc[n][3]));
        }
        mx0 = fmaxf(mx0, __shfl_xor_sync(0xffffffffu, mx0, 1));
        mx0 = fmaxf(mx0, __shfl_xor_sync(0xffffffffu, mx0, 2));
        mx1 = fmaxf(mx1, __shfl_xor_sync(0xffffffffu, mx1, 1));
        mx1 = fmaxf(mx1, __shfl_xor_sync(0xffffffffu, mx1, 2));

        float m0n = fmaxf(m0, mx0 * scale);
        float m1n = fmaxf(m1, mx1 * scale);
        float al0 = __expf(m0 - m0n);
        float al1 = __expf(m1 - m1n);
        m0 = m0n; m1 = m1n;

        float ls0 = 0.f, ls1 = 0.f;
#pragma unroll
        for (int n = 0; n < 8; n++) {
            float p0 = __expf(sacc[n][0] * scale - m0n);
            float p1 = __expf(sacc[n][1] * scale - m0n);
            float p2 = __expf(sacc[n][2] * scale - m1n);
            float p3 = __expf(sacc[n][3] * scale - m1n);
            ls0 += p0 + p1; ls1 += p2 + p3;
            sacc[n][0] = p0; sacc[n][1] = p1; sacc[n][2] = p2; sacc[n][3] = p3;
        }
        ls0 += __shfl_xor_sync(0xffffffffu, ls0, 1);
        ls0 += __shfl_xor_sync(0xffffffffu, ls0, 2);
        ls1 += __shfl_xor_sync(0xffffffffu, ls1, 1);
        ls1 += __shfl_xor_sync(0xffffffffu, ls1, 2);
        l0 = l0 * al0 + ls0;
        l1 = l1 * al1 + ls1;

#pragma unroll
        for (int n = 0; n < 8; n++) {
            acc[n][0] *= al0; acc[n][1] *= al0;
            acc[n][2] *= al1; acc[n][3] *= al1;
        }

        // ---- O += P V : P a-frags built in registers from sacc ----
#pragma unroll
        for (int ks = 0; ks < 4; ks++) {
            uint32_t pfh[4], pfl[4];
            split_pack2(sacc[2 * ks][0],     sacc[2 * ks][1],     pfh[0], pfl[0]);
            split_pack2(sacc[2 * ks][2],     sacc[2 * ks][3],     pfh[1], pfl[1]);
            split_pack2(sacc[2 * ks + 1][0], sacc[2 * ks + 1][1], pfh[2], pfl[2]);
            split_pack2(sacc[2 * ks + 1][2], sacc[2 * ks + 1][3], pfh[3], pfl[3]);
#pragma unroll
            for (int dtp = 0; dtp < 4; dtp++) {
                uint32_t vaddr = bufb + 2 * KVMAT + bfr
                               + (uint32_t)(dtp * 16 * KVROWB + ks * 32);
                uint32_t vh4[4], vl4[4];
                LDSM4(vh4[0], vh4[1], vh4[2], vh4[3], vaddr);
                LDSM4(vl4[0], vl4[1], vl4[2], vl4[3], vaddr + KVMAT);
                MMA16816(acc[2 * dtp + 0], pfh, vh4[0], vh4[1]);
                MMA16816(acc[2 * dtp + 1], pfh, vh4[2], vh4[3]);
                MMA16816(acc[2 * dtp + 0], pfh, vl4[0], vl4[1]);
                MMA16816(acc[2 * dtp + 1], pfh, vl4[2], vl4[3]);
                MMA16816(acc[2 * dtp + 0], pfl, vh4[0], vh4[1]);
                MMA16816(acc[2 * dtp + 1], pfl, vh4[2], vh4[3]);
            }
        }
        __syncthreads();
    }

    // Epilogue: normalize, split to bf16, write context [B*N][1024]
    {
        float inv0 = 1.f / l0;
        float inv1 = 1.f / l1;
        const int b = bh >> 4, h = bh & 15;
        const int g = lane >> 2, t2 = (lane & 3) * 2;
        const int qr = q0 + warp * 16 + g;
        const size_t rowA = (size_t)(b * Nseq + qr) * Dm;
        const size_t rowB = (size_t)(b * Nseq + qr + 8) * Dm;
#pragma unroll
        for (int n = 0; n < 8; n++) {
            int col = h * HDim + n * 8 + t2;
            uint32_t hw, lw;
            split_pack2(acc[n][0] * inv0, acc[n][1] * inv0, hw, lw);
            *(uint32_t*)&Ch[rowA + col] = hw;
            *(uint32_t*)&Cl[rowA + col] = lw;
            split_pack2(acc[n][2] * inv1, acc[n][3] * inv1, hw, lw);
            *(uint32_t*)&Ch[rowB + col] = hw;
            *(uint32_t*)&Cl[rowB + col] = lw;
        }
    }
}

// ---------------------------------------------------------------------------
// Launch
// ---------------------------------------------------------------------------
extern "C" void kernel_launch(void* const* d_in, const int* in_sizes, int n_in,
                              void* d_out, int out_size)
{
    const float* x  = (const float*)d_in[0];
    const float* Wq = (const float*)d_in[1];
    const float* bq = (const float*)d_in[2];
    const float* Wk = (const float*)d_in[3];
    const float* bk = (const float*)d_in[4];
    const float* Wv = (const float*)d_in[5];
    const float* bv = (const float*)d_in[6];
    const float* Wp = (const float*)d_in[7];
    const float* bp = (const float*)d_in[8];
    const float* qg = (const float*)d_in[9];
    const float* qb = (const float*)d_in[10];
    const float* kg = (const float*)d_in[11];
    const float* kb_ = (const float*)d_in[12];
    float* out = (float*)d_out;

    float *Qp, *Kp, *Vp;
    cudaGetSymbolAddress((void**)&Qp, g_Q);
    cudaGetSymbolAddress((void**)&Kp, g_K);
    cudaGetSymbolAddress((void**)&Vp, g_V);
    __nv_bfloat16 *Xh, *Xl, *Wh, *Wl, *Qhp, *Qlp, *Khp, *Klp, *VTh, *VTl, *Chp, *Clp;
    cudaGetSymbolAddress((void**)&Xh, g_Xh);
    cudaGetSymbolAddress((void**)&Xl, g_Xl);
    cudaGetSymbolAddress((void**)&Wh, g_Wh);
    cudaGetSymbolAddress((void**)&Wl, g_Wl);
    cudaGetSymbolAddress((void**)&Qhp, g_Qh);
    cudaGetSymbolAddress((void**)&Qlp, g_Ql);
    cudaGetSymbolAddress((void**)&Khp, g_Kh);
    cudaGetSymbolAddress((void**)&Klp, g_Kl);
    cudaGetSymbolAddress((void**)&VTh, g_VTh);
    cudaGetSymbolAddress((void**)&VTl, g_VTl);
    cudaGetSymbolAddress((void**)&Chp, g_Ch);
    cudaGetSymbolAddress((void**)&Clp, g_Cl);

    cudaFuncSetAttribute(gemm_mma_bias,
                         cudaFuncAttributeMaxDynamicSharedMemorySize, GEMM_SMEM);
    cudaFuncSetAttribute(attn_mma,
                         cudaFuncAttributeMaxDynamicSharedMemorySize, ATTN_SMEM);

    // Splits
    split_f32<<<(Mrows * Dm / 4 + 255) / 256, 256>>>(x, Xh, Xl, Mrows * Dm / 4);
    SplitSrcs ss{Wq, Wk, Wv, Wp};
    split_w<<<dim3(WW / 4 / 256, 4), 256>>>(ss, Wh, Wl);

    // Fused QKV GEMM
    {
        GemmPtrs gp{bq, bk, bv, Qp, Kp, Vp, 0, 1, 2};
        gemm_mma_bias<<<dim3(Dm / BN, Mrows / BM, 3), 256, GEMM_SMEM>>>(
            Xh, Xl, Wh, Wl, gp);
    }

    // LN + split; V transpose + split
    ln_split<<<Mrows * Hh / 8, 256>>>(Qp, qg, qb, Qhp, Qlp);
    ln_split<<<Mrows * Hh / 8, 256>>>(Kp, kg, kb_, Khp, Klp);
    v_splitT<<<dim3(Nseq / 64, Bq * Hh), 256>>>(Vp, VTh, VTl);

    // Attention (128-q tiles, register softmax)
    attn_mma<<<dim3(Nseq / 128, Bq * Hh), 256, ATTN_SMEM>>>(
        Qhp, Qlp, Khp, Klp, VTh, VTl, Chp, Clp);

    // Output projection
    {
        GemmPtrs gp{bp, bp, bp, out, out, out, 3, 3, 3};
        gemm_mma_bias<<<dim3(Dm / BN, Mrows / BM, 1), 256, GEMM_SMEM>>>(
            Chp, Clp, Wh, Wl, gp);
    }
}

// round 7
// speedup vs baseline: 4.0846x; 1.1750x over previous
#include <cuda_runtime.h>
#include <cuda_bf16.h>
#include <cstdint>

// Problem constants
static constexpr int Bq    = 2;
static constexpr int Nseq  = 2048;
static constexpr int Dm    = 1024;
static constexpr int Hh    = 16;
static constexpr int HDim  = 64;
static constexpr int Mrows = Bq * Nseq;  // 4096
static constexpr float EPSf = 1e-5f;

// ---------------------------------------------------------------------------
// Tiled global layouts (all padded to smem-image form, bulk-copyable)
//   X/W/C : [tile][chunk32][128 rows x 40 elems]  (32 data + 8 pad bf16)
//   Q     : [bh][qtile(128)][128 rows x 72 elems] (64 data + 8 pad)
//   K/VT  : [bh][ktile(64)][64 rows x 72 elems]
// ---------------------------------------------------------------------------
static constexpr int XROW = 40;                    // elems per GEMM smem row
static constexpr int XCHUNK = 128 * XROW;          // 5120 elems = 10240 B
static constexpr int XTILE  = 32 * XCHUNK;         // per (row/col)tile
static constexpr int AROW = 72;                    // elems per attn smem row
static constexpr int QTILE_E = 128 * AROW;         // 9216 elems = 18432 B
static constexpr int KTILE_E = 64 * AROW;          // 4608 elems = 9216 B

__device__ float g_Q[Mrows * Dm];
__device__ float g_K[Mrows * Dm];
__device__ float g_V[Mrows * Dm];

__device__ __nv_bfloat16 g_Xh[32 * XTILE], g_Xl[32 * XTILE];
__device__ __nv_bfloat16 g_Wh[4][8 * XTILE], g_Wl[4][8 * XTILE];
__device__ __nv_bfloat16 g_Ch[32 * XTILE], g_Cl[32 * XTILE];
__device__ __nv_bfloat16 g_Qh[32 * 16 * QTILE_E], g_Ql[32 * 16 * QTILE_E];
__device__ __nv_bfloat16 g_Kh[32 * 32 * KTILE_E], g_Kl[32 * 32 * KTILE_E];
__device__ __nv_bfloat16 g_VTh[32 * 32 * KTILE_E], g_VTl[32 * 32 * KTILE_E];

// ===========================================================================
// Helpers (base-target PTX: ldmatrix, mma.sync, cp.async.bulk, mbarrier)
// ===========================================================================
__device__ __forceinline__ uint32_t smem_u32(const void* p) {
    uint32_t a;
    asm("{ .reg .u64 t; cvta.to.shared.u64 t, %1; cvt.u32.u64 %0, t; }"
        : "=r"(a) : "l"(p));
    return a;
}

#define LDSM4(r0, r1, r2, r3, addr) \
    asm volatile("ldmatrix.sync.aligned.m8n8.x4.shared.b16 {%0,%1,%2,%3}, [%4];" \
        : "=r"(r0), "=r"(r1), "=r"(r2), "=r"(r3) : "r"(addr))

#define MMA16816(c, a, b0v, b1v) \
    asm volatile("mma.sync.aligned.m16n8k16.row.col.f32.bf16.bf16.f32 " \
        "{%0,%1,%2,%3}, {%4,%5,%6,%7}, {%8,%9}, {%0,%1,%2,%3};" \
        : "+f"((c)[0]), "+f"((c)[1]), "+f"((c)[2]), "+f"((c)[3]) \
        : "r"((a)[0]), "r"((a)[1]), "r"((a)[2]), "r"((a)[3]), \
          "r"(b0v), "r"(b1v))

#define MBARRIER_INIT(addr, cnt) \
    asm volatile("mbarrier.init.shared.b64 [%0], %1;" \
        :: "r"((uint32_t)(addr)), "r"((uint32_t)(cnt)) : "memory")

#define MBARRIER_EXPECT_TX(addr, bytes) \
    asm volatile("mbarrier.arrive.expect_tx.shared.b64 _, [%0], %1;" \
        :: "r"((uint32_t)(addr)), "r"((uint32_t)(bytes)) : "memory")

#define MBARRIER_WAIT_PARITY(addr, par) do {                                     \
    uint32_t _m = (uint32_t)(addr); uint32_t _p = (uint32_t)(par); uint32_t _d;  \
    asm volatile("{\n\t.reg .pred p;\n\t"                                        \
        "mbarrier.try_wait.parity.shared.b64 p, [%1], %2;\n\t"                   \
        "selp.b32 %0, 1, 0, p;\n\t}" : "=r"(_d) : "r"(_m), "r"(_p) : "memory");  \
    if (!_d) {                                                                   \
        asm volatile("{\n\t.reg .pred P1;\n\t"                                   \
        "WL_%=:\n\t"                                                             \
        "mbarrier.try_wait.parity.shared.b64 P1, [%0], %1;\n\t"                  \
        "@P1 bra.uni WD_%=;\n\t"                                                 \
        "bra.uni WL_%=;\n\t"                                                     \
        "WD_%=:\n\t}" :: "r"(_m), "r"(_p) : "memory");                           \
    } } while (0)

#define CP_BULK(dst, src, bytes, mbar) \
    asm volatile("cp.async.bulk.shared::cluster.global.mbarrier::complete_tx::bytes " \
        "[%0], [%1], %2, [%3];" \
        :: "r"((uint32_t)(dst)), "l"(src), "r"((uint32_t)(bytes)), \
           "r"((uint32_t)(mbar)) : "memory")

__device__ __forceinline__ void split_pack2(float x, float y, uint32_t& hi, uint32_t& lo) {
    __nv_bfloat162 h = __floats2bfloat162_rn(x, y);
    float hx = __bfloat162float(h.x), hy = __bfloat162float(h.y);
    __nv_bfloat162 l = __floats2bfloat162_rn(x - hx, y - hy);
    hi = *(uint32_t*)&h;
    lo = *(uint32_t*)&l;
}

// ===========================================================================
// Split X -> tiled image. Thread handles 8 consecutive k of one row.
// ===========================================================================
__global__ void __launch_bounds__(256) split_x(
    const float* __restrict__ s, __nv_bfloat16* __restrict__ hi,
    __nv_bfloat16* __restrict__ lo)
{
    int i = blockIdx.x * blockDim.x + threadIdx.x;   // 4096*128
    int m = i >> 7, k8 = i & 127;
    int k = k8 * 8;
    const float* p = s + (size_t)m * Dm + k;
    float4 f0 = *(const float4*)p;
    float4 f1 = *(const float4*)(p + 4);
    uint4 H, L;
    split_pack2(f0.x, f0.y, H.x, L.x);
    split_pack2(f0.z, f0.w, H.y, L.y);
    split_pack2(f1.x, f1.y, H.z, L.z);
    split_pack2(f1.z, f1.w, H.w, L.w);
    int rt = m >> 7, r = m & 127, c = k >> 5, cc = k & 31;
    size_t o = (size_t)rt * XTILE + (size_t)c * XCHUNK + (size_t)r * XROW + cc;
    *(uint4*)(hi + o) = H;
    *(uint4*)(lo + o) = L;
}

struct SplitSrcs { const float *s0, *s1, *s2, *s3; };

__global__ void __launch_bounds__(256) split_w(
    SplitSrcs ss, __nv_bfloat16* __restrict__ hi, __nv_bfloat16* __restrict__ lo)
{
    int mi = blockIdx.y;
    const float* s = (mi == 0) ? ss.s0 : (mi == 1) ? ss.s1 : (mi == 2) ? ss.s2 : ss.s3;
    int i = blockIdx.x * blockDim.x + threadIdx.x;   // 1024*128
    int n = i >> 7, k8 = i & 127;
    int k = k8 * 8;
    const float* p = s + (size_t)n * Dm + k;
    float4 f0 = *(const float4*)p;
    float4 f1 = *(const float4*)(p + 4);
    uint4 H, L;
    split_pack2(f0.x, f0.y, H.x, L.x);
    split_pack2(f0.z, f0.w, H.y, L.y);
    split_pack2(f1.x, f1.y, H.z, L.z);
    split_pack2(f1.z, f1.w, H.w, L.w);
    int ct = n >> 7, r = n & 127, c = k >> 5, cc = k & 31;
    size_t o = (size_t)mi * (8 * XTILE)
             + (size_t)ct * XTILE + (size_t)c * XCHUNK + (size_t)r * XROW + cc;
    *(uint4*)(hi + o) = H;
    *(uint4*)(lo + o) = L;
}

// ===========================================================================
// Split-bf16 mma.sync GEMM (NT), cp.async.bulk double-buffered.
// Tile 128x128, BK=32, 8 warps (2x4), warp tile 64x32. ROWB=80 smem rows.
// A/B operands read from tiled images (4 bulk copies per chunk).
// ===========================================================================
static constexpr int ROWB = 80;
static constexpr int MATB = 128 * ROWB;        // 10240 B
static constexpr int OFF_AH = 0;
static constexpr int OFF_AL = MATB;
static constexpr int OFF_BH = 2 * MATB;
static constexpr int OFF_BL = 3 * MATB;
static constexpr int BUF_B  = 4 * MATB;        // 40960
static constexpr int GEMM_SMEM = 2 * BUF_B + 16;
static constexpr int GNCHUNK = 32;

struct GemmPtrs {
    const float* bias0; const float* bias1; const float* bias2;
    float* out0; float* out1; float* out2;
    int w0, w1, w2;
};

__global__ void __launch_bounds__(256, 2) gemm_mma_bias(
    const __nv_bfloat16* __restrict__ Ah, const __nv_bfloat16* __restrict__ Al,
    const __nv_bfloat16* __restrict__ WhB, const __nv_bfloat16* __restrict__ WlB,
    GemmPtrs gp)
{
    extern __shared__ char sm[];
    const uint32_t sb = smem_u32(sm);
    const int tid  = threadIdx.x;
    const int lane = tid & 31;
    const int warp = tid >> 5;
    const int wm   = warp >> 2;
    const int wn   = warp & 3;

    const int z = blockIdx.z;
    const int widx = (z == 0) ? gp.w0 : (z == 1) ? gp.w1 : gp.w2;
    const float* bias = (z == 0) ? gp.bias0 : (z == 1) ? gp.bias1 : gp.bias2;
    float* C = (z == 0) ? gp.out0 : (z == 1) ? gp.out1 : gp.out2;

    const uint32_t mb0 = sb + 2 * BUF_B, mb1 = mb0 + 8;
    if (tid == 0) { MBARRIER_INIT(mb0, 1); MBARRIER_INIT(mb1, 1); }
    __syncthreads();

    const size_t aBase = (size_t)blockIdx.y * XTILE;
    const size_t bBase = (size_t)widx * (8 * XTILE) + (size_t)blockIdx.x * XTILE;

    auto issue = [&](int c) {
        if (tid != 0) return;
        const uint32_t bufb = sb + (c & 1) * BUF_B;
        const uint32_t mb = (c & 1) ? mb1 : mb0;
        MBARRIER_EXPECT_TX(mb, 4 * MATB);
        const size_t co = (size_t)c * XCHUNK;
        CP_BULK(bufb + OFF_AH, Ah  + aBase + co, MATB, mb);
        CP_BULK(bufb + OFF_AL, Al  + aBase + co, MATB, mb);
        CP_BULK(bufb + OFF_BH, WhB + bBase + co, MATB, mb);
        CP_BULK(bufb + OFF_BL, WlB + bBase + co, MATB, mb);
    };

    float acc[4][4][4];
#pragma unroll
    for (int t = 0; t < 4; t++)
#pragma unroll
        for (int n = 0; n < 4; n++)
#pragma unroll
            for (int j = 0; j < 4; j++) acc[t][n][j] = 0.f;

    const uint32_t aLM = (uint32_t)((wm * 64 + (lane & 15)) * ROWB + (lane >> 4) * 16);
    const uint32_t bLM = (uint32_t)((wn * 32 + (lane & 7) + ((lane >> 4) & 1) * 8) * ROWB
                                    + ((lane >> 3) & 1) * 16);

    issue(0);
    int ph0 = 0, ph1 = 0;

    for (int c = 0; c < GNCHUNK; c++) {
        if (c + 1 < GNCHUNK) issue(c + 1);
        if ((c & 1) == 0) { MBARRIER_WAIT_PARITY(mb0, ph0); ph0 ^= 1; }
        else              { MBARRIER_WAIT_PARITY(mb1, ph1); ph1 ^= 1; }

        const uint32_t bufb = sb + (c & 1) * BUF_B;
        const uint32_t aHiB = bufb + OFF_AH + aLM;
        const uint32_t aLoB = bufb + OFF_AL + aLM;
        const uint32_t bHiB = bufb + OFF_BH + bLM;
        const uint32_t bLoB = bufb + OFF_BL + bLM;

#pragma unroll
        for (int kk = 0; kk < 32; kk += 16) {
            uint32_t bh4[2][4], bl4[2][4];
#pragma unroll
            for (int g = 0; g < 2; g++) {
                uint32_t off = (uint32_t)(g * 16 * ROWB + kk * 2);
                LDSM4(bh4[g][0], bh4[g][1], bh4[g][2], bh4[g][3], bHiB + off);
                LDSM4(bl4[g][0], bl4[g][1], bl4[g][2], bl4[g][3], bLoB + off);
            }
#pragma unroll
            for (int t = 0; t < 4; t++) {
                uint32_t ah[4], al[4];
                uint32_t off = (uint32_t)(t * 16 * ROWB + kk * 2);
                LDSM4(ah[0], ah[1], ah[2], ah[3], aHiB + off);
                LDSM4(al[0], al[1], al[2], al[3], aLoB + off);
#pragma unroll
                for (int g = 0; g < 2; g++) {
                    MMA16816(acc[t][g * 2 + 0], ah, bh4[g][0], bh4[g][1]);
                    MMA16816(acc[t][g * 2 + 1], ah, bh4[g][2], bh4[g][3]);
                    MMA16816(acc[t][g * 2 + 0], ah, bl4[g][0], bl4[g][1]);
                    MMA16816(acc[t][g * 2 + 1], ah, bl4[g][2], bl4[g][3]);
                    MMA16816(acc[t][g * 2 + 0], al, bh4[g][0], bh4[g][1]);
                    MMA16816(acc[t][g * 2 + 1], al, bh4[g][2], bh4[g][3]);
                }
            }
        }
        __syncthreads();
    }

#pragma unroll
    for (int t = 0; t < 4; t++) {
        const int r0 = blockIdx.y * 128 + wm * 64 + t * 16 + (lane >> 2);
#pragma unroll
        for (int n = 0; n < 4; n++) {
            int col = blockIdx.x * 128 + wn * 32 + (lane & 3) * 2 + n * 8;
            float b0 = bias[col], b1 = bias[col + 1];
            float2 o0 = make_float2(acc[t][n][0] + b0, acc[t][n][1] + b1);
            float2 o1 = make_float2(acc[t][n][2] + b0, acc[t][n][3] + b1);
            *(float2*)&C[(size_t)r0 * Dm + col]       = o0;
            *(float2*)&C[(size_t)(r0 + 8) * Dm + col] = o1;
        }
    }
}

// ===========================================================================
// LN per head + split into tiled attn layouts.
// mode 0: Q -> [bh][qtile(128)][128 x 72];  mode 1: K -> [bh][ktile(64)][64 x 72]
// ===========================================================================
__global__ void __launch_bounds__(256) ln_split(
    const float* __restrict__ X, const float* __restrict__ gamma,
    const float* __restrict__ beta,
    __nv_bfloat16* __restrict__ Oh, __nv_bfloat16* __restrict__ Ol, int mode)
{
    int wid  = (blockIdx.x * blockDim.x + threadIdx.x) >> 5;
    int lane = threadIdx.x & 31;
    int row = wid >> 4;
    int h   = wid & 15;
    const float* p = X + (size_t)row * Dm + h * HDim;

    float x0 = p[lane];
    float x1 = p[lane + 32];
    float s  = x0 + x1;
    float ss = x0 * x0 + x1 * x1;
#pragma unroll
    for (int o = 16; o > 0; o >>= 1) {
        s  += __shfl_xor_sync(0xffffffffu, s,  o);
        ss += __shfl_xor_sync(0xffffffffu, ss, o);
    }
    float mean = s * (1.f / 64.f);
    float var  = ss * (1.f / 64.f) - mean * mean;
    float r    = rsqrtf(var + EPSf);
    float y0 = (x0 - mean) * r * gamma[lane]      + beta[lane];
    float y1 = (x1 - mean) * r * gamma[lane + 32] + beta[lane + 32];

    int b = row >> 11, n = row & 2047;
    int bh = b * Hh + h;
    size_t o;
    if (mode == 0) {
        int qt = n >> 7, rr = n & 127;
        o = ((size_t)bh * 16 + qt) * QTILE_E + (size_t)rr * AROW;
    } else {
        int kt = n >> 6, rr = n & 63;
        o = ((size_t)bh * 32 + kt) * KTILE_E + (size_t)rr * AROW;
    }
    __nv_bfloat16 h0 = __float2bfloat16(y0);
    __nv_bfloat16 h1 = __float2bfloat16(y1);
    Oh[o + lane]      = h0;
    Oh[o + lane + 32] = h1;
    Ol[o + lane]      = __float2bfloat16(y0 - __bfloat162float(h0));
    Ol[o + lane + 32] = __float2bfloat16(y1 - __bfloat162float(h1));
}

// ===========================================================================
// V transpose + split into VT tiled layout [bh][ktile][64 drows x 72]
// ===========================================================================
__global__ void __launch_bounds__(256) v_splitT(
    const float* __restrict__ V,
    __nv_bfloat16* __restrict__ VTh, __nv_bfloat16* __restrict__ VTl)
{
    __shared__ float st[64][68];
    const int tid = threadIdx.x;
    const int bh = blockIdx.y;
    const int kt = blockIdx.x;          // 64-row k tile
    const int n0 = kt * 64;
    const int b = bh >> 4, h = bh & 15;

    int j = tid >> 2, dseg = tid & 3;
    const float* gp = V + (size_t)(b * Nseq + n0 + j) * Dm + h * HDim + dseg * 16;
#pragma unroll
    for (int q = 0; q < 4; q++)
        *(float4*)&st[j][dseg * 16 + q * 4] = *(const float4*)(gp + q * 4);
    __syncthreads();

    int d = tid >> 2, nseg = tid & 3;
    size_t o = ((size_t)bh * 32 + kt) * KTILE_E + (size_t)d * AROW + nseg * 16;
#pragma unroll
    for (int jj = 0; jj < 16; jj++) {
        float v = st[nseg * 16 + jj][d];
        __nv_bfloat16 hv = __float2bfloat16(v);
        VTh[o + jj] = hv;
        VTl[o + jj] = __float2bfloat16(v - __bfloat162float(hv));
    }
}

// ===========================================================================
// Flash attention, FA2 register softmax, cp.async.bulk K/V pipeline.
// CTA = 128 q-rows x (b,h), 8 warps x 16 q-rows. Context written into the
// GEMM-A tiled layout (g_Ch/g_Cl) for the output projection.
// ===========================================================================
static constexpr int KVROWB = 144;
static constexpr int KVMAT  = 64 * KVROWB;    // 9216
static constexpr int KVBUF  = 4 * KVMAT;      // 36864 (KH,KL,VH,VL)
static constexpr int ATTN_SMEM = 2 * KVBUF + 16;

__global__ void __launch_bounds__(256, 2) attn_mma(
    const __nv_bfloat16* __restrict__ Qh, const __nv_bfloat16* __restrict__ Ql,
    const __nv_bfloat16* __restrict__ Kh, const __nv_bfloat16* __restrict__ Kl,
    const __nv_bfloat16* __restrict__ Vh, const __nv_bfloat16* __restrict__ Vl,
    __nv_bfloat16* __restrict__ Ch, __nv_bfloat16* __restrict__ Cl)
{
    extern __shared__ char sm[];
    const uint32_t sb = smem_u32(sm);
    const int tid  = threadIdx.x;
    const int lane = tid & 31;
    const int warp = tid >> 5;
    const int bh = blockIdx.y;
    const int qt = blockIdx.x;          // 128-row q tile
    const int q0 = qt * 128;
    const float scale = 0.125f;

    const uint32_t mb0 = sb + 2 * KVBUF, mb1 = mb0 + 8;
    if (tid == 0) { MBARRIER_INIT(mb0, 1); MBARRIER_INIT(mb1, 1); }
    __syncthreads();

    auto issue_kv = [&](int c) {
        if (tid != 0) return;
        const uint32_t bufb = sb + (c & 1) * KVBUF;
        const uint32_t mb = (c & 1) ? mb1 : mb0;
        MBARRIER_EXPECT_TX(mb, 4 * KVMAT);
        const size_t ko = ((size_t)bh * 32 + c) * KTILE_E;
        CP_BULK(bufb + 0 * KVMAT, Kh + ko, KVMAT, mb);
        CP_BULK(bufb + 1 * KVMAT, Kl + ko, KVMAT, mb);
        CP_BULK(bufb + 2 * KVMAT, Vh + ko, KVMAT, mb);
        CP_BULK(bufb + 3 * KVMAT, Vl + ko, KVMAT, mb);
    };

    // Prologue: Q (hi/lo) into buf1 via bulk; KV chunk 0 into buf0
    if (tid == 0) {
        MBARRIER_EXPECT_TX(mb1, 2 * 18432);
        const size_t qo = ((size_t)bh * 16 + qt) * QTILE_E;
        CP_BULK(sb + KVBUF +     0, Qh + qo, 18432, mb1);
        CP_BULK(sb + KVBUF + 18432, Ql + qo, 18432, mb1);
    }
    issue_kv(0);

    int ph0 = 0, ph1 = 0;
    MBARRIER_WAIT_PARITY(mb1, 0); ph1 = 1;

    // Q fragments (held in registers for whole kernel)
    uint32_t qfh[4][4], qfl[4][4];
    {
        const uint32_t qst = sb + KVBUF
            + (uint32_t)((warp * 16 + (lane & 15)) * KVROWB + (lane >> 4) * 16);
#pragma unroll
        for (int ks = 0; ks < 4; ks++) {
            LDSM4(qfh[ks][0], qfh[ks][1], qfh[ks][2], qfh[ks][3], qst + ks * 32);
            LDSM4(qfl[ks][0], qfl[ks][1], qfl[ks][2], qfl[ks][3], qst + 18432 + ks * 32);
        }
    }
    __syncthreads();   // buf1 free for chunk 1

    float acc[8][4];
#pragma unroll
    for (int n = 0; n < 8; n++)
#pragma unroll
        for (int j = 0; j < 4; j++) acc[n][j] = 0.f;
    float m0 = -1e30f, m1 = -1e30f, l0 = 0.f, l1 = 0.f;

    const uint32_t bfr = (uint32_t)(((lane & 7) + ((lane >> 4) & 1) * 8) * KVROWB
                                    + ((lane >> 3) & 1) * 16);

    for (int c = 0; c < Nseq / 64; c++) {
        if (c + 1 < Nseq / 64) issue_kv(c + 1);
        if ((c & 1) == 0) { MBARRIER_WAIT_PARITY(mb0, ph0); ph0 ^= 1; }
        else              { MBARRIER_WAIT_PARITY(mb1, ph1); ph1 ^= 1; }

        const uint32_t bufb = sb + (c & 1) * KVBUF;

        // ---- S = Q K^T ----
        float sacc[8][4];
#pragma unroll
        for (int n = 0; n < 8; n++)
#pragma unroll
            for (int j = 0; j < 4; j++) sacc[n][j] = 0.f;

#pragma unroll
        for (int ks = 0; ks < 4; ks++) {
#pragma unroll
            for (int ntp = 0; ntp < 4; ntp++) {
                uint32_t kaddr = bufb + bfr + (uint32_t)(ntp * 16 * KVROWB + ks * 32);
                uint32_t kh4[4], kl4[4];
                LDSM4(kh4[0], kh4[1], kh4[2], kh4[3], kaddr);
                LDSM4(kl4[0], kl4[1], kl4[2], kl4[3], kaddr + KVMAT);
                MMA16816(sacc[2 * ntp + 0], qfh[ks], kh4[0], kh4[1]);
                MMA16816(sacc[2 * ntp + 1], qfh[ks], kh4[2], kh4[3]);
                MMA16816(sacc[2 * ntp + 0], qfh[ks], kl4[0], kl4[1]);
                MMA16816(sacc[2 * ntp + 1], qfh[ks], kl4[2], kl4[3]);
                MMA16816(sacc[2 * ntp + 0], qfl[ks], kh4[0], kh4[1]);
                MMA16816(sacc[2 * ntp + 1], qfl[ks], kh4[2], kh4[3]);
            }
        }

        // ---- online softmax in registers ----
        float mx0 = -1e30f, mx1 = -1e30f;
#pragma unroll
        for (int n = 0; n < 8; n++) {
            mx0 = fmaxf(mx0, fmaxf(sacc[n][0], sacc[n][1]));
            mx1 = fmaxf(mx1, fmaxf(sacc[n][2], sacc[n][3]));
        }
        mx0 = fmaxf(mx0, __shfl_xor_sync(0xffffffffu, mx0, 1));
        mx0 = fmaxf(mx0, __shfl_xor_sync(0xffffffffu, mx0, 2));
        mx1 = fmaxf(mx1, __shfl_xor_sync(0xffffffffu, mx1, 1));
        mx1 = fmaxf(mx1, __shfl_xor_sync(0xffffffffu, mx1, 2));

        float m0n = fmaxf(m0, mx0 * scale);
        float m1n = fmaxf(m1, mx1 * scale);
        float al0 = __expf(m0 - m0n);
        float al1 = __expf(m1 - m1n);
        m0 = m0n; m1 = m1n;

        float ls0 = 0.f, ls1 = 0.f;
#pragma unroll
        for (int n = 0; n < 8; n++) {
            float p0 = __expf(sacc[n][0] * scale - m0n);
            float p1 = __expf(sacc[n][1] * scale - m0n);
            float p2 = __expf(sacc[n][2] * scale - m1n);
            float p3 = __expf(sacc[n][3] * scale - m1n);
            ls0 += p0 + p1; ls1 += p2 + p3;
            sacc[n][0] = p0; sacc[n][1] = p1; sacc[n][2] = p2; sacc[n][3] = p3;
        }
        ls0 += __shfl_xor_sync(0xffffffffu, ls0, 1);
        ls0 += __shfl_xor_sync(0xffffffffu, ls0, 2);
        ls1 += __shfl_xor_sync(0xffffffffu, ls1, 1);
        ls1 += __shfl_xor_sync(0xffffffffu, ls1, 2);
        l0 = l0 * al0 + ls0;
        l1 = l1 * al1 + ls1;

#pragma unroll
        for (int n = 0; n < 8; n++) {
            acc[n][0] *= al0; acc[n][1] *= al0;
            acc[n][2] *= al1; acc[n][3] *= al1;
        }

        // ---- O += P V ----
#pragma unroll
        for (int ks = 0; ks < 4; ks++) {
            uint32_t pfh[4], pfl[4];
            split_pack2(sacc[2 * ks][0],     sacc[2 * ks][1],     pfh[0], pfl[0]);
            split_pack2(sacc[2 * ks][2],     sacc[2 * ks][3],     pfh[1], pfl[1]);
            split_pack2(sacc[2 * ks + 1][0], sacc[2 * ks + 1][1], pfh[2], pfl[2]);
            split_pack2(sacc[2 * ks + 1][2], sacc[2 * ks + 1][3], pfh[3], pfl[3]);
#pragma unroll
            for (int dtp = 0; dtp < 4; dtp++) {
                uint32_t vaddr = bufb + 2 * KVMAT + bfr
                               + (uint32_t)(dtp * 16 * KVROWB + ks * 32);
                uint32_t vh4[4], vl4[4];
                LDSM4(vh4[0], vh4[1], vh4[2], vh4[3], vaddr);
                LDSM4(vl4[0], vl4[1], vl4[2], vl4[3], vaddr + KVMAT);
                MMA16816(acc[2 * dtp + 0], pfh, vh4[0], vh4[1]);
                MMA16816(acc[2 * dtp + 1], pfh, vh4[2], vh4[3]);
                MMA16816(acc[2 * dtp + 0], pfh, vl4[0], vl4[1]);
                MMA16816(acc[2 * dtp + 1], pfh, vl4[2], vl4[3]);
                MMA16816(acc[2 * dtp + 0], pfl, vh4[0], vh4[1]);
                MMA16816(acc[2 * dtp + 1], pfl, vh4[2], vh4[3]);
            }
        }
        __syncthreads();
    }

    // Epilogue: normalize, split, write into GEMM-A tiled context image
    {
        float inv0 = 1.f / l0;
        float inv1 = 1.f / l1;
        const int b = bh >> 4, h = bh & 15;
        const int g = lane >> 2, t2 = (lane & 3) * 2;
        const int qr = q0 + warp * 16 + g;
        const int mA = b * Nseq + qr;
        const int mB = mA + 8;
#pragma unroll
        for (int n = 0; n < 8; n++) {
            int col = h * HDim + n * 8 + t2;
            int cch = col >> 5, cc = col & 31;
            size_t oA = (size_t)(mA >> 7) * XTILE + (size_t)cch * XCHUNK
                      + (size_t)(mA & 127) * XROW + cc;
            size_t oB = (size_t)(mB >> 7) * XTILE + (size_t)cch * XCHUNK
                      + (size_t)(mB & 127) * XROW + cc;
            uint32_t hw, lw;
            split_pack2(acc[n][0] * inv0, acc[n][1] * inv0, hw, lw);
            *(uint32_t*)(Ch + oA) = hw;
            *(uint32_t*)(Cl + oA) = lw;
            split_pack2(acc[n][2] * inv1, acc[n][3] * inv1, hw, lw);
            *(uint32_t*)(Ch + oB) = hw;
            *(uint32_t*)(Cl + oB) = lw;
        }
    }
}

// ---------------------------------------------------------------------------
// Launch
// ---------------------------------------------------------------------------
extern "C" void kernel_launch(void* const* d_in, const int* in_sizes, int n_in,
                              void* d_out, int out_size)
{
    const float* x  = (const float*)d_in[0];
    const float* Wq = (const float*)d_in[1];
    const float* bq = (const float*)d_in[2];
    const float* Wk = (const float*)d_in[3];
    const float* bk = (const float*)d_in[4];
    const float* Wv = (const float*)d_in[5];
    const float* bv = (const float*)d_in[6];
    const float* Wp = (const float*)d_in[7];
    const float* bp = (const float*)d_in[8];
    const float* qg = (const float*)d_in[9];
    const float* qb = (const float*)d_in[10];
    const float* kg = (const float*)d_in[11];
    const float* kb_ = (const float*)d_in[12];
    float* out = (float*)d_out;

    float *Qp, *Kp, *Vp;
    cudaGetSymbolAddress((void**)&Qp, g_Q);
    cudaGetSymbolAddress((void**)&Kp, g_K);
    cudaGetSymbolAddress((void**)&Vp, g_V);
    __nv_bfloat16 *Xh, *Xl, *Wh, *Wl, *Qhp, *Qlp, *Khp, *Klp, *VTh, *VTl, *Chp, *Clp;
    cudaGetSymbolAddress((void**)&Xh, g_Xh);
    cudaGetSymbolAddress((void**)&Xl, g_Xl);
    cudaGetSymbolAddress((void**)&Wh, g_Wh);
    cudaGetSymbolAddress((void**)&Wl, g_Wl);
    cudaGetSymbolAddress((void**)&Qhp, g_Qh);
    cudaGetSymbolAddress((void**)&Qlp, g_Ql);
    cudaGetSymbolAddress((void**)&Khp, g_Kh);
    cudaGetSymbolAddress((void**)&Klp, g_Kl);
    cudaGetSymbolAddress((void**)&VTh, g_VTh);
    cudaGetSymbolAddress((void**)&VTl, g_VTl);
    cudaGetSymbolAddress((void**)&Chp, g_Ch);
    cudaGetSymbolAddress((void**)&Clp, g_Cl);

    cudaFuncSetAttribute(gemm_mma_bias,
                         cudaFuncAttributeMaxDynamicSharedMemorySize, GEMM_SMEM);
    cudaFuncSetAttribute(attn_mma,
                         cudaFuncAttributeMaxDynamicSharedMemorySize, ATTN_SMEM);

    // Splits into tiled images
    split_x<<<Mrows * 128 / 256, 256>>>(x, Xh, Xl);
    SplitSrcs ss{Wq, Wk, Wv, Wp};
    split_w<<<dim3(Dm * 128 / 256, 4), 256>>>(ss, Wh, Wl);

    // Fused QKV GEMM
    {
        GemmPtrs gp{bq, bk, bv, Qp, Kp, Vp, 0, 1, 2};
        gemm_mma_bias<<<dim3(8, 32, 3), 256, GEMM_SMEM>>>(Xh, Xl, Wh, Wl, gp);
    }

    // LN + split (tiled); V transpose + split (tiled)
    ln_split<<<Mrows * Hh / 8, 256>>>(Qp, qg, qb, Qhp, Qlp, 0);
    ln_split<<<Mrows * Hh / 8, 256>>>(Kp, kg, kb_, Khp, Klp, 1);
    v_splitT<<<dim3(Nseq / 64, Bq * Hh), 256>>>(Vp, VTh, VTl);

    // Attention (bulk-fed, writes tiled context)
    attn_mma<<<dim3(Nseq / 128, Bq * Hh), 256, ATTN_SMEM>>>(
        Qhp, Qlp, Khp, Klp, VTh, VTl, Chp, Clp);

    // Output projection
    {
        GemmPtrs gp{bp, bp, bp, out, out, out, 3, 3, 3};
        gemm_mma_bias<<<dim3(8, 32, 1), 256, GEMM_SMEM>>>(Chp, Clp, Wh, Wl, gp);
    }
}

// round 8
// speedup vs baseline: 4.5565x; 1.1155x over previous
#include <cuda_runtime.h>
#include <cuda_bf16.h>
#include <cstdint>

// Problem constants
static constexpr int Bq    = 2;
static constexpr int Nseq  = 2048;
static constexpr int Dm    = 1024;
static constexpr int Hh    = 16;
static constexpr int HDim  = 64;
static constexpr int Mrows = Bq * Nseq;  // 4096
static constexpr float EPSf = 1e-5f;

// ---------------------------------------------------------------------------
// Tiled global layouts (padded smem-image form, bulk-copyable)
// ---------------------------------------------------------------------------
static constexpr int XROW = 40;
static constexpr int XCHUNK = 128 * XROW;          // 5120 elems
static constexpr int XTILE  = 32 * XCHUNK;
static constexpr int AROW = 72;
static constexpr int QTILE_E = 128 * AROW;         // 9216 elems
static constexpr int KTILE_E = 64 * AROW;          // 4608 elems

__device__ __nv_bfloat16 g_Xh[32 * XTILE], g_Xl[32 * XTILE];
__device__ __nv_bfloat16 g_Wh[4][8 * XTILE], g_Wl[4][8 * XTILE];
__device__ __nv_bfloat16 g_Ch[32 * XTILE], g_Cl[32 * XTILE];
__device__ __nv_bfloat16 g_Qh[32 * 16 * QTILE_E], g_Ql[32 * 16 * QTILE_E];
__device__ __nv_bfloat16 g_Kh[32 * 32 * KTILE_E], g_Kl[32 * 32 * KTILE_E];
__device__ __nv_bfloat16 g_VTh[32 * 32 * KTILE_E], g_VTl[32 * 32 * KTILE_E];

// ===========================================================================
// Helpers
// ===========================================================================
__device__ __forceinline__ uint32_t smem_u32(const void* p) {
    uint32_t a;
    asm("{ .reg .u64 t; cvta.to.shared.u64 t, %1; cvt.u32.u64 %0, t; }"
        : "=r"(a) : "l"(p));
    return a;
}

#define LDSM4(r0, r1, r2, r3, addr) \
    asm volatile("ldmatrix.sync.aligned.m8n8.x4.shared.b16 {%0,%1,%2,%3}, [%4];" \
        : "=r"(r0), "=r"(r1), "=r"(r2), "=r"(r3) : "r"(addr))

#define MMA16816(c, a, b0v, b1v) \
    asm volatile("mma.sync.aligned.m16n8k16.row.col.f32.bf16.bf16.f32 " \
        "{%0,%1,%2,%3}, {%4,%5,%6,%7}, {%8,%9}, {%0,%1,%2,%3};" \
        : "+f"((c)[0]), "+f"((c)[1]), "+f"((c)[2]), "+f"((c)[3]) \
        : "r"((a)[0]), "r"((a)[1]), "r"((a)[2]), "r"((a)[3]), \
          "r"(b0v), "r"(b1v))

#define MBARRIER_INIT(addr, cnt) \
    asm volatile("mbarrier.init.shared.b64 [%0], %1;" \
        :: "r"((uint32_t)(addr)), "r"((uint32_t)(cnt)) : "memory")

#define MBARRIER_EXPECT_TX(addr, bytes) \
    asm volatile("mbarrier.arrive.expect_tx.shared.b64 _, [%0], %1;" \
        :: "r"((uint32_t)(addr)), "r"((uint32_t)(bytes)) : "memory")

#define MBARRIER_WAIT_PARITY(addr, par) do {                                     \
    uint32_t _m = (uint32_t)(addr); uint32_t _p = (uint32_t)(par); uint32_t _d;  \
    asm volatile("{\n\t.reg .pred p;\n\t"                                        \
        "mbarrier.try_wait.parity.shared.b64 p, [%1], %2;\n\t"                   \
        "selp.b32 %0, 1, 0, p;\n\t}" : "=r"(_d) : "r"(_m), "r"(_p) : "memory");  \
    if (!_d) {                                                                   \
        asm volatile("{\n\t.reg .pred P1;\n\t"                                   \
        "WL_%=:\n\t"                                                             \
        "mbarrier.try_wait.parity.shared.b64 P1, [%0], %1;\n\t"                  \
        "@P1 bra.uni WD_%=;\n\t"                                                 \
        "bra.uni WL_%=;\n\t"                                                     \
        "WD_%=:\n\t}" :: "r"(_m), "r"(_p) : "memory");                           \
    } } while (0)

#define CP_BULK(dst, src, bytes, mbar) \
    asm volatile("cp.async.bulk.shared::cluster.global.mbarrier::complete_tx::bytes " \
        "[%0], [%1], %2, [%3];" \
        :: "r"((uint32_t)(dst)), "l"(src), "r"((uint32_t)(bytes)), \
           "r"((uint32_t)(mbar)) : "memory")

__device__ __forceinline__ void split_pack2(float x, float y, uint32_t& hi, uint32_t& lo) {
    __nv_bfloat162 h = __floats2bfloat162_rn(x, y);
    float hx = __bfloat162float(h.x), hy = __bfloat162float(h.y);
    __nv_bfloat162 l = __floats2bfloat162_rn(x - hx, y - hy);
    hi = *(uint32_t*)&h;
    lo = *(uint32_t*)&l;
}

// ===========================================================================
// Splits into tiled GEMM images
// ===========================================================================
__global__ void __launch_bounds__(256) split_x(
    const float* __restrict__ s, __nv_bfloat16* __restrict__ hi,
    __nv_bfloat16* __restrict__ lo)
{
    int i = blockIdx.x * blockDim.x + threadIdx.x;
    int m = i >> 7, k8 = i & 127;
    int k = k8 * 8;
    const float* p = s + (size_t)m * Dm + k;
    float4 f0 = *(const float4*)p;
    float4 f1 = *(const float4*)(p + 4);
    uint4 H, L;
    split_pack2(f0.x, f0.y, H.x, L.x);
    split_pack2(f0.z, f0.w, H.y, L.y);
    split_pack2(f1.x, f1.y, H.z, L.z);
    split_pack2(f1.z, f1.w, H.w, L.w);
    int rt = m >> 7, r = m & 127, c = k >> 5, cc = k & 31;
    size_t o = (size_t)rt * XTILE + (size_t)c * XCHUNK + (size_t)r * XROW + cc;
    *(uint4*)(hi + o) = H;
    *(uint4*)(lo + o) = L;
}

struct SplitSrcs { const float *s0, *s1, *s2, *s3; };

__global__ void __launch_bounds__(256) split_w(
    SplitSrcs ss, __nv_bfloat16* __restrict__ hi, __nv_bfloat16* __restrict__ lo)
{
    int mi = blockIdx.y;
    const float* s = (mi == 0) ? ss.s0 : (mi == 1) ? ss.s1 : (mi == 2) ? ss.s2 : ss.s3;
    int i = blockIdx.x * blockDim.x + threadIdx.x;
    int n = i >> 7, k8 = i & 127;
    int k = k8 * 8;
    const float* p = s + (size_t)n * Dm + k;
    float4 f0 = *(const float4*)p;
    float4 f1 = *(const float4*)(p + 4);
    uint4 H, L;
    split_pack2(f0.x, f0.y, H.x, L.x);
    split_pack2(f0.z, f0.w, H.y, L.y);
    split_pack2(f1.x, f1.y, H.z, L.z);
    split_pack2(f1.z, f1.w, H.w, L.w);
    int ct = n >> 7, r = n & 127, c = k >> 5, cc = k & 31;
    size_t o = (size_t)mi * (8 * XTILE)
             + (size_t)ct * XTILE + (size_t)c * XCHUNK + (size_t)r * XROW + cc;
    *(uint4*)(hi + o) = H;
    *(uint4*)(lo + o) = L;
}

// ===========================================================================
// Split-bf16 mma.sync GEMM, bulk double-buffered, FUSED epilogues:
//   mode 0: per-head LN + split -> Q tiled image [bh][qt128][128x72]
//   mode 1: per-head LN + split -> K tiled image [bh][kt64][64x72]
//   mode 2: transpose + split   -> VT tiled image [bh][kt64][64x72]
//   mode 3: bias + fp32 store (output projection)
// ===========================================================================
static constexpr int ROWB = 80;
static constexpr int MATB = 128 * ROWB;
static constexpr int OFF_AH = 0;
static constexpr int OFF_AL = MATB;
static constexpr int OFF_BH = 2 * MATB;
static constexpr int OFF_BL = 3 * MATB;
static constexpr int BUF_B  = 4 * MATB;
static constexpr int GEMM_SMEM = 2 * BUF_B + 16;
static constexpr int GNCHUNK = 32;

struct GemmPtrs {
    const float* bias[3];
    const float* gam[3];
    const float* bet[3];
    float* outf[3];
    __nv_bfloat16 *oh[3], *ol[3];
    int w[3];
    int mode[3];
};

__global__ void __launch_bounds__(256, 2) gemm_mma_bias(
    const __nv_bfloat16* __restrict__ Ah, const __nv_bfloat16* __restrict__ Al,
    const __nv_bfloat16* __restrict__ WhB, const __nv_bfloat16* __restrict__ WlB,
    GemmPtrs gp)
{
    extern __shared__ char sm[];
    const uint32_t sb = smem_u32(sm);
    const int tid  = threadIdx.x;
    const int lane = tid & 31;
    const int warp = tid >> 5;
    const int wm   = warp >> 2;
    const int wn   = warp & 3;

    const int z = blockIdx.z;
    const int widx = gp.w[z];
    const int mode = gp.mode[z];
    const float* bias = gp.bias[z];

    const uint32_t mb0 = sb + 2 * BUF_B, mb1 = mb0 + 8;
    if (tid == 0) { MBARRIER_INIT(mb0, 1); MBARRIER_INIT(mb1, 1); }
    __syncthreads();

    const size_t aBase = (size_t)blockIdx.y * XTILE;
    const size_t bBase = (size_t)widx * (8 * XTILE) + (size_t)blockIdx.x * XTILE;

    auto issue = [&](int c) {
        if (tid != 0) return;
        const uint32_t bufb = sb + (c & 1) * BUF_B;
        const uint32_t mb = (c & 1) ? mb1 : mb0;
        MBARRIER_EXPECT_TX(mb, 4 * MATB);
        const size_t co = (size_t)c * XCHUNK;
        CP_BULK(bufb + OFF_AH, Ah  + aBase + co, MATB, mb);
        CP_BULK(bufb + OFF_AL, Al  + aBase + co, MATB, mb);
        CP_BULK(bufb + OFF_BH, WhB + bBase + co, MATB, mb);
        CP_BULK(bufb + OFF_BL, WlB + bBase + co, MATB, mb);
    };

    float acc[4][4][4];
#pragma unroll
    for (int t = 0; t < 4; t++)
#pragma unroll
        for (int n = 0; n < 4; n++)
#pragma unroll
            for (int j = 0; j < 4; j++) acc[t][n][j] = 0.f;

    const uint32_t aLM = (uint32_t)((wm * 64 + (lane & 15)) * ROWB + (lane >> 4) * 16);
    const uint32_t bLM = (uint32_t)((wn * 32 + (lane & 7) + ((lane >> 4) & 1) * 8) * ROWB
                                    + ((lane >> 3) & 1) * 16);

    issue(0);
    int ph0 = 0, ph1 = 0;

    for (int c = 0; c < GNCHUNK; c++) {
        if (c + 1 < GNCHUNK) issue(c + 1);
        if ((c & 1) == 0) { MBARRIER_WAIT_PARITY(mb0, ph0); ph0 ^= 1; }
        else              { MBARRIER_WAIT_PARITY(mb1, ph1); ph1 ^= 1; }

        const uint32_t bufb = sb + (c & 1) * BUF_B;
        const uint32_t aHiB = bufb + OFF_AH + aLM;
        const uint32_t aLoB = bufb + OFF_AL + aLM;
        const uint32_t bHiB = bufb + OFF_BH + bLM;
        const uint32_t bLoB = bufb + OFF_BL + bLM;

#pragma unroll
        for (int kk = 0; kk < 32; kk += 16) {
            uint32_t bh4[2][4], bl4[2][4];
#pragma unroll
            for (int g = 0; g < 2; g++) {
                uint32_t off = (uint32_t)(g * 16 * ROWB + kk * 2);
                LDSM4(bh4[g][0], bh4[g][1], bh4[g][2], bh4[g][3], bHiB + off);
                LDSM4(bl4[g][0], bl4[g][1], bl4[g][2], bl4[g][3], bLoB + off);
            }
#pragma unroll
            for (int t = 0; t < 4; t++) {
                uint32_t ah[4], al[4];
                uint32_t off = (uint32_t)(t * 16 * ROWB + kk * 2);
                LDSM4(ah[0], ah[1], ah[2], ah[3], aHiB + off);
                LDSM4(al[0], al[1], al[2], al[3], aLoB + off);
#pragma unroll
                for (int g = 0; g < 2; g++) {
                    MMA16816(acc[t][g * 2 + 0], ah, bh4[g][0], bh4[g][1]);
                    MMA16816(acc[t][g * 2 + 1], ah, bh4[g][2], bh4[g][3]);
                    MMA16816(acc[t][g * 2 + 0], ah, bl4[g][0], bl4[g][1]);
                    MMA16816(acc[t][g * 2 + 1], ah, bl4[g][2], bl4[g][3]);
                    MMA16816(acc[t][g * 2 + 0], al, bh4[g][0], bh4[g][1]);
                    MMA16816(acc[t][g * 2 + 1], al, bh4[g][2], bh4[g][3]);
                }
            }
        }
        __syncthreads();
    }

    // ------------------ Fused epilogues ------------------
    if (mode == 3) {
        float* C = gp.outf[z];
#pragma unroll
        for (int t = 0; t < 4; t++) {
            const int r0 = blockIdx.y * 128 + wm * 64 + t * 16 + (lane >> 2);
#pragma unroll
            for (int n = 0; n < 4; n++) {
                int col = blockIdx.x * 128 + wn * 32 + (lane & 3) * 2 + n * 8;
                float b0 = bias[col], b1 = bias[col + 1];
                float2 o0 = make_float2(acc[t][n][0] + b0, acc[t][n][1] + b1);
                float2 o1 = make_float2(acc[t][n][2] + b0, acc[t][n][3] + b1);
                *(float2*)&C[(size_t)r0 * Dm + col]       = o0;
                *(float2*)&C[(size_t)(r0 + 8) * Dm + col] = o1;
            }
        }
    } else if (mode <= 1) {
        // per-head LayerNorm + split -> tiled Q/K image
        float* psum = (float*)sm;            // [128][4]
        float* psq  = (float*)(sm + 2048);   // [128][4]
        const float* gam = gp.gam[z];
        const float* bet = gp.bet[z];
        const int gl = lane >> 2;

#pragma unroll
        for (int t = 0; t < 4; t++)
#pragma unroll
            for (int n = 0; n < 4; n++) {
                int col = blockIdx.x * 128 + wn * 32 + (lane & 3) * 2 + n * 8;
                float b0 = bias[col], b1 = bias[col + 1];
                acc[t][n][0] += b0; acc[t][n][1] += b1;
                acc[t][n][2] += b0; acc[t][n][3] += b1;
            }
#pragma unroll
        for (int t = 0; t < 4; t++) {
            float s0 = 0.f, q0 = 0.f, s1 = 0.f, q1 = 0.f;
#pragma unroll
            for (int n = 0; n < 4; n++) {
                s0 += acc[t][n][0] + acc[t][n][1];
                q0 += acc[t][n][0] * acc[t][n][0] + acc[t][n][1] * acc[t][n][1];
                s1 += acc[t][n][2] + acc[t][n][3];
                q1 += acc[t][n][2] * acc[t][n][2] + acc[t][n][3] * acc[t][n][3];
            }
            s0 += __shfl_xor_sync(~0u, s0, 1); s0 += __shfl_xor_sync(~0u, s0, 2);
            q0 += __shfl_xor_sync(~0u, q0, 1); q0 += __shfl_xor_sync(~0u, q0, 2);
            s1 += __shfl_xor_sync(~0u, s1, 1); s1 += __shfl_xor_sync(~0u, s1, 2);
            q1 += __shfl_xor_sync(~0u, q1, 1); q1 += __shfl_xor_sync(~0u, q1, 2);
            if ((lane & 3) == 0) {
                int r = wm * 64 + t * 16 + gl;
                psum[r * 4 + wn] = s0;       psq[r * 4 + wn] = q0;
                psum[(r + 8) * 4 + wn] = s1; psq[(r + 8) * 4 + wn] = q1;
            }
        }
        __syncthreads();

        __nv_bfloat16* Oh = gp.oh[z];
        __nv_bfloat16* Ol = gp.ol[z];
        const int head = blockIdx.x * 2 + (wn >> 1);
#pragma unroll
        for (int t = 0; t < 4; t++) {
#pragma unroll
            for (int half = 0; half < 2; half++) {
                int r = wm * 64 + t * 16 + gl + half * 8;
                float tot = psum[r * 4 + wn] + psum[r * 4 + (wn ^ 1)];
                float tq  = psq[r * 4 + wn]  + psq[r * 4 + (wn ^ 1)];
                float mean = tot * (1.f / 64.f);
                float var  = tq * (1.f / 64.f) - mean * mean;
                float rstd = rsqrtf(var + EPSf);
                int m = blockIdx.y * 128 + r;
                int bb = m >> 11, nn = m & 2047;
                int bh = bb * Hh + head;
                size_t obase;
                if (mode == 0)
                    obase = ((size_t)bh * 16 + (nn >> 7)) * QTILE_E + (size_t)(nn & 127) * AROW;
                else
                    obase = ((size_t)bh * 32 + (nn >> 6)) * KTILE_E + (size_t)(nn & 63) * AROW;
#pragma unroll
                for (int n = 0; n < 4; n++) {
                    int c64 = (wn & 1) * 32 + (lane & 3) * 2 + n * 8;
                    float y0 = (acc[t][n][half * 2 + 0] - mean) * rstd * gam[c64]     + bet[c64];
                    float y1 = (acc[t][n][half * 2 + 1] - mean) * rstd * gam[c64 + 1] + bet[c64 + 1];
                    uint32_t hw, lw;
                    split_pack2(y0, y1, hw, lw);
                    *(uint32_t*)(Oh + obase + c64) = hw;
                    *(uint32_t*)(Ol + obase + c64) = lw;
                }
            }
        }
    } else {
        // mode 2: V -> transpose + split into 4 VT images (2 heads x 2 ktiles)
        __nv_bfloat16* smh = (__nv_bfloat16*)sm;            // 4*4608 elems
        __nv_bfloat16* sml = smh + 4 * 4608;
        const int c0 = wn * 32 + (lane & 3) * 2;
        const int rb = wm * 64 + (lane >> 2);
#pragma unroll
        for (int t = 0; t < 4; t++) {
#pragma unroll
            for (int n = 0; n < 4; n++) {
                int cA = c0 + n * 8;
                float b0 = bias[blockIdx.x * 128 + cA];
                float b1 = bias[blockIdx.x * 128 + cA + 1];
                int hA = cA >> 6, dA = cA & 63;
#pragma unroll
                for (int half = 0; half < 2; half++) {
                    int rl = rb + t * 16 + half * 8;
                    int ktl = rl >> 6, nn = rl & 63;
                    int offA = (hA * 2 + ktl) * 4608 + dA * 72 + nn;
                    float v0 = acc[t][n][half * 2 + 0] + b0;
                    float v1 = acc[t][n][half * 2 + 1] + b1;
                    __nv_bfloat16 hh = __float2bfloat16(v0);
                    smh[offA] = hh;
                    sml[offA] = __float2bfloat16(v0 - __bfloat162float(hh));
                    hh = __float2bfloat16(v1);
                    smh[offA + 72] = hh;
                    sml[offA + 72] = __float2bfloat16(v1 - __bfloat162float(hh));
                }
            }
        }
        __syncthreads();
        const int bb = blockIdx.y >> 4;
        const int n0 = (blockIdx.y * 128) & 2047;
#pragma unroll
        for (int u = 0; u < 18; u++) {
            int lin = tid + u * 256;          // 4608 uint4 total
            int img = lin / 576;              // 0..7 (4 hi + 4 lo)
            int within = lin - img * 576;
            int imgIdx = img & 3, isLo = img >> 2;
            int head_local = imgIdx >> 1, ktl = imgIdx & 1;
            int bh = bb * Hh + blockIdx.x * 2 + head_local;
            int ktg = (n0 >> 6) + ktl;
            __nv_bfloat16* dst = (isLo ? gp.ol[z] : gp.oh[z])
                + ((size_t)bh * 32 + ktg) * KTILE_E;
            *(uint4*)(dst + within * 8) =
                *(const uint4*)((isLo ? sml : smh) + imgIdx * 4608 + within * 8);
        }
    }
}

// ===========================================================================
// Flash attention, FA2 register softmax, cp.async.bulk K/V pipeline.
// (unchanged from R7 — proven)
// ===========================================================================
static constexpr int KVROWB = 144;
static constexpr int KVMAT  = 64 * KVROWB;
static constexpr int KVBUF  = 4 * KVMAT;
static constexpr int ATTN_SMEM = 2 * KVBUF + 16;

__global__ void __launch_bounds__(256, 2) attn_mma(
    const __nv_bfloat16* __restrict__ Qh, const __nv_bfloat16* __restrict__ Ql,
    const __nv_bfloat16* __restrict__ Kh, const __nv_bfloat16* __restrict__ Kl,
    const __nv_bfloat16* __restrict__ Vh, const __nv_bfloat16* __restrict__ Vl,
    __nv_bfloat16* __restrict__ Ch, __nv_bfloat16* __restrict__ Cl)
{
    extern __shared__ char sm[];
    const uint32_t sb = smem_u32(sm);
    const int tid  = threadIdx.x;
    const int lane = tid & 31;
    const int warp = tid >> 5;
    const int bh = blockIdx.y;
    const int qt = blockIdx.x;
    const int q0 = qt * 128;
    const float scale = 0.125f;

    const uint32_t mb0 = sb + 2 * KVBUF, mb1 = mb0 + 8;
    if (tid == 0) { MBARRIER_INIT(mb0, 1); MBARRIER_INIT(mb1, 1); }
    __syncthreads();

    auto issue_kv = [&](int c) {
        if (tid != 0) return;
        const uint32_t bufb = sb + (c & 1) * KVBUF;
        const uint32_t mb = (c & 1) ? mb1 : mb0;
        MBARRIER_EXPECT_TX(mb, 4 * KVMAT);
        const size_t ko = ((size_t)bh * 32 + c) * KTILE_E;
        CP_BULK(bufb + 0 * KVMAT, Kh + ko, KVMAT, mb);
        CP_BULK(bufb + 1 * KVMAT, Kl + ko, KVMAT, mb);
        CP_BULK(bufb + 2 * KVMAT, Vh + ko, KVMAT, mb);
        CP_BULK(bufb + 3 * KVMAT, Vl + ko, KVMAT, mb);
    };

    if (tid == 0) {
        MBARRIER_EXPECT_TX(mb1, 2 * 18432);
        const size_t qo = ((size_t)bh * 16 + qt) * QTILE_E;
        CP_BULK(sb + KVBUF +     0, Qh + qo, 18432, mb1);
        CP_BULK(sb + KVBUF + 18432, Ql + qo, 18432, mb1);
    }
    issue_kv(0);

    int ph0 = 0, ph1 = 0;
    MBARRIER_WAIT_PARITY(mb1, 0); ph1 = 1;

    uint32_t qfh[4][4], qfl[4][4];
    {
        const uint32_t qst = sb + KVBUF
            + (uint32_t)((warp * 16 + (lane & 15)) * KVROWB + (lane >> 4) * 16);
#pragma unroll
        for (int ks = 0; ks < 4; ks++) {
            LDSM4(qfh[ks][0], qfh[ks][1], qfh[ks][2], qfh[ks][3], qst + ks * 32);
            LDSM4(qfl[ks][0], qfl[ks][1], qfl[ks][2], qfl[ks][3], qst + 18432 + ks * 32);
        }
    }
    __syncthreads();

    float acc[8][4];
#pragma unroll
    for (int n = 0; n < 8; n++)
#pragma unroll
        for (int j = 0; j < 4; j++) acc[n][j] = 0.f;
    float m0 = -1e30f, m1 = -1e30f, l0 = 0.f, l1 = 0.f;

    const uint32_t bfr = (uint32_t)(((lane & 7) + ((lane >> 4) & 1) * 8) * KVROWB
                                    + ((lane >> 3) & 1) * 16);

    for (int c = 0; c < Nseq / 64; c++) {
        if (c + 1 < Nseq / 64) issue_kv(c + 1);
        if ((c & 1) == 0) { MBARRIER_WAIT_PARITY(mb0, ph0); ph0 ^= 1; }
        else              { MBARRIER_WAIT_PARITY(mb1, ph1); ph1 ^= 1; }

        const uint32_t bufb = sb + (c & 1) * KVBUF;

        float sacc[8][4];
#pragma unroll
        for (int n = 0; n < 8; n++)
#pragma unroll
            for (int j = 0; j < 4; j++) sacc[n][j] = 0.f;

#pragma unroll
        for (int ks = 0; ks < 4; ks++) {
#pragma unroll
            for (int ntp = 0; ntp < 4; ntp++) {
                uint32_t kaddr = bufb + bfr + (uint32_t)(ntp * 16 * KVROWB + ks * 32);
                uint32_t kh4[4], kl4[4];
                LDSM4(kh4[0], kh4[1], kh4[2], kh4[3], kaddr);
                LDSM4(kl4[0], kl4[1], kl4[2], kl4[3], kaddr + KVMAT);
                MMA16816(sacc[2 * ntp + 0], qfh[ks], kh4[0], kh4[1]);
                MMA16816(sacc[2 * ntp + 1], qfh[ks], kh4[2], kh4[3]);
                MMA16816(sacc[2 * ntp + 0], qfh[ks], kl4[0], kl4[1]);
                MMA16816(sacc[2 * ntp + 1], qfh[ks], kl4[2], kl4[3]);
                MMA16816(sacc[2 * ntp + 0], qfl[ks], kh4[0], kh4[1]);
                MMA16816(sacc[2 * ntp + 1], qfl[ks], kh4[2], kh4[3]);
            }
        }

        float mx0 = -1e30f, mx1 = -1e30f;
#pragma unroll
        for (int n = 0; n < 8; n++) {
            mx0 = fmaxf(mx0, fmaxf(sacc[n][0], sacc[n][1]));
            mx1 = fmaxf(mx1, fmaxf(sacc[n][2], sacc[n][3]));
        }
        mx0 = fmaxf(mx0, __shfl_xor_sync(0xffffffffu, mx0, 1));
        mx0 = fmaxf(mx0, __shfl_xor_sync(0xffffffffu, mx0, 2));
        mx1 = fmaxf(mx1, __shfl_xor_sync(0xffffffffu, mx1, 1));
        mx1 = fmaxf(mx1, __shfl_xor_sync(0xffffffffu, mx1, 2));

        float m0n = fmaxf(m0, mx0 * scale);
        float m1n = fmaxf(m1, mx1 * scale);
        float al0 = __expf(m0 - m0n);
        float al1 = __expf(m1 - m1n);
        m0 = m0n; m1 = m1n;

        float ls0 = 0.f, ls1 = 0.f;
#pragma unroll
        for (int n = 0; n < 8; n++) {
            float p0 = __expf(sacc[n][0] * scale - m0n);
            float p1 = __expf(sacc[n][1] * scale - m0n);
            float p2 = __expf(sacc[n][2] * scale - m1n);
            float p3 = __expf(sacc[n][3] * scale - m1n);
            ls0 += p0 + p1; ls1 += p2 + p3;
            sacc[n][0] = p0; sacc[n][1] = p1; sacc[n][2] = p2; sacc[n][3] = p3;
        }
        ls0 += __shfl_xor_sync(0xffffffffu, ls0, 1);
        ls0 += __shfl_xor_sync(0xffffffffu, ls0, 2);
        ls1 += __shfl_xor_sync(0xffffffffu, ls1, 1);
        ls1 += __shfl_xor_sync(0xffffffffu, ls1, 2);
        l0 = l0 * al0 + ls0;
        l1 = l1 * al1 + ls1;

#pragma unroll
        for (int n = 0; n < 8; n++) {
            acc[n][0] *= al0; acc[n][1] *= al0;
            acc[n][2] *= al1; acc[n][3] *= al1;
        }

#pragma unroll
        for (int ks = 0; ks < 4; ks++) {
            uint32_t pfh[4], pfl[4];
            split_pack2(sacc[2 * ks][0],     sacc[2 * ks][1],     pfh[0], pfl[0]);
            split_pack2(sacc[2 * ks][2],     sacc[2 * ks][3],     pfh[1], pfl[1]);
            split_pack2(sacc[2 * ks + 1][0], sacc[2 * ks + 1][1], pfh[2], pfl[2]);
            split_pack2(sacc[2 * ks + 1][2], sacc[2 * ks + 1][3], pfh[3], pfl[3]);
#pragma unroll
            for (int dtp = 0; dtp < 4; dtp++) {
                uint32_t vaddr = bufb + 2 * KVMAT + bfr
                               + (uint32_t)(dtp * 16 * KVROWB + ks * 32);
                uint32_t vh4[4], vl4[4];
                LDSM4(vh4[0], vh4[1], vh4[2], vh4[3], vaddr);
                LDSM4(vl4[0], vl4[1], vl4[2], vl4[3], vaddr + KVMAT);
                MMA16816(acc[2 * dtp + 0], pfh, vh4[0], vh4[1]);
                MMA16816(acc[2 * dtp + 1], pfh, vh4[2], vh4[3]);
                MMA16816(acc[2 * dtp + 0], pfh, vl4[0], vl4[1]);
                MMA16816(acc[2 * dtp + 1], pfh, vl4[2], vl4[3]);
                MMA16816(acc[2 * dtp + 0], pfl, vh4[0], vh4[1]);
                MMA16816(acc[2 * dtp + 1], pfl, vh4[2], vh4[3]);
            }
        }
        __syncthreads();
    }

    {
        float inv0 = 1.f / l0;
        float inv1 = 1.f / l1;
        const int b = bh >> 4, h = bh & 15;
        const int g = lane >> 2, t2 = (lane & 3) * 2;
        const int qr = q0 + warp * 16 + g;
        const int mA = b * Nseq + qr;
        const int mB = mA + 8;
#pragma unroll
        for (int n = 0; n < 8; n++) {
            int col = h * HDim + n * 8 + t2;
            int cch = col >> 5, cc = col & 31;
            size_t oA = (size_t)(mA >> 7) * XTILE + (size_t)cch * XCHUNK
                      + (size_t)(mA & 127) * XROW + cc;
            size_t oB = (size_t)(mB >> 7) * XTILE + (size_t)cch * XCHUNK
                      + (size_t)(mB & 127) * XROW + cc;
            uint32_t hw, lw;
            split_pack2(acc[n][0] * inv0, acc[n][1] * inv0, hw, lw);
            *(uint32_t*)(Ch + oA) = hw;
            *(uint32_t*)(Cl + oA) = lw;
            split_pack2(acc[n][2] * inv1, acc[n][3] * inv1, hw, lw);
            *(uint32_t*)(Ch + oB) = hw;
            *(uint32_t*)(Cl + oB) = lw;
        }
    }
}

// ---------------------------------------------------------------------------
// Launch
// ---------------------------------------------------------------------------
extern "C" void kernel_launch(void* const* d_in, const int* in_sizes, int n_in,
                              void* d_out, int out_size)
{
    const float* x  = (const float*)d_in[0];
    const float* Wq = (const float*)d_in[1];
    const float* bq = (const float*)d_in[2];
    const float* Wk = (const float*)d_in[3];
    const float* bk = (const float*)d_in[4];
    const float* Wv = (const float*)d_in[5];
    const float* bv = (const float*)d_in[6];
    const float* Wp = (const float*)d_in[7];
    const float* bp = (const float*)d_in[8];
    const float* qg = (const float*)d_in[9];
    const float* qb = (const float*)d_in[10];
    const float* kg = (const float*)d_in[11];
    const float* kb_ = (const float*)d_in[12];
    float* out = (float*)d_out;

    __nv_bfloat16 *Xh, *Xl, *Wh, *Wl, *Qhp, *Qlp, *Khp, *Klp, *VTh, *VTl, *Chp, *Clp;
    cudaGetSymbolAddress((void**)&Xh, g_Xh);
    cudaGetSymbolAddress((void**)&Xl, g_Xl);
    cudaGetSymbolAddress((void**)&Wh, g_Wh);
    cudaGetSymbolAddress((void**)&Wl, g_Wl);
    cudaGetSymbolAddress((void**)&Qhp, g_Qh);
    cudaGetSymbolAddress((void**)&Qlp, g_Ql);
    cudaGetSymbolAddress((void**)&Khp, g_Kh);
    cudaGetSymbolAddress((void**)&Klp, g_Kl);
    cudaGetSymbolAddress((void**)&VTh, g_VTh);
    cudaGetSymbolAddress((void**)&VTl, g_VTl);
    cudaGetSymbolAddress((void**)&Chp, g_Ch);
    cudaGetSymbolAddress((void**)&Clp, g_Cl);

    cudaFuncSetAttribute(gemm_mma_bias,
                         cudaFuncAttributeMaxDynamicSharedMemorySize, GEMM_SMEM);
    cudaFuncSetAttribute(attn_mma,
                         cudaFuncAttributeMaxDynamicSharedMemorySize, ATTN_SMEM);

    // Splits into tiled images
    split_x<<<Mrows * 128 / 256, 256>>>(x, Xh, Xl);
    SplitSrcs ss{Wq, Wk, Wv, Wp};
    split_w<<<dim3(Dm * 128 / 256, 4), 256>>>(ss, Wh, Wl);

    // Fused QKV GEMM + LN/transpose/split epilogues
    {
        GemmPtrs gp{};
        gp.bias[0] = bq;  gp.bias[1] = bk;  gp.bias[2] = bv;
        gp.gam[0]  = qg;  gp.gam[1]  = kg;  gp.gam[2]  = nullptr;
        gp.bet[0]  = qb;  gp.bet[1]  = kb_; gp.bet[2]  = nullptr;
        gp.oh[0] = Qhp; gp.oh[1] = Khp; gp.oh[2] = VTh;
        gp.ol[0] = Qlp; gp.ol[1] = Klp; gp.ol[2] = VTl;
        gp.w[0] = 0; gp.w[1] = 1; gp.w[2] = 2;
        gp.mode[0] = 0; gp.mode[1] = 1; gp.mode[2] = 2;
        gemm_mma_bias<<<dim3(8, 32, 3), 256, GEMM_SMEM>>>(Xh, Xl, Wh, Wl, gp);
    }

    // Attention
    attn_mma<<<dim3(Nseq / 128, Bq * Hh), 256, ATTN_SMEM>>>(
        Qhp, Qlp, Khp, Klp, VTh, VTl, Chp, Clp);

    // Output projection (fp32 epilogue)
    {
        GemmPtrs gp{};
        gp.bias[0] = bp;
        gp.outf[0] = out;
        gp.w[0] = 3;
        gp.mode[0] = 3;
        gemm_mma_bias<<<dim3(8, 32, 1), 256, GEMM_SMEM>>>(Chp, Clp, Wh, Wl, gp);
    }
}

// round 9
// speedup vs baseline: 4.7081x; 1.0333x over previous
#include <cuda_runtime.h>
#include <cuda_bf16.h>
#include <cstdint>

// Problem constants
static constexpr int Bq    = 2;
static constexpr int Nseq  = 2048;
static constexpr int Dm    = 1024;
static constexpr int Hh    = 16;
static constexpr int HDim  = 64;
static constexpr int Mrows = Bq * Nseq;  // 4096
static constexpr float EPSf = 1e-5f;

// ---------------------------------------------------------------------------
// Tiled global layouts (padded smem-image form, bulk-copyable)
// ---------------------------------------------------------------------------
static constexpr int XROW = 40;
static constexpr int XCHUNK = 128 * XROW;          // 5120 elems
static constexpr int XTILE  = 32 * XCHUNK;
static constexpr int AROW = 72;
static constexpr int QTILE_E = 128 * AROW;         // 9216 elems
static constexpr int KTILE_E = 64 * AROW;          // 4608 elems

__device__ __nv_bfloat16 g_Xh[32 * XTILE], g_Xl[32 * XTILE];
__device__ __nv_bfloat16 g_Wh[4][8 * XTILE], g_Wl[4][8 * XTILE];
__device__ __nv_bfloat16 g_Ch[32 * XTILE], g_Cl[32 * XTILE];
__device__ __nv_bfloat16 g_Qh[32 * 16 * QTILE_E], g_Ql[32 * 16 * QTILE_E];
__device__ __nv_bfloat16 g_Kh[32 * 32 * KTILE_E], g_Kl[32 * 32 * KTILE_E];
__device__ __nv_bfloat16 g_VTh[32 * 32 * KTILE_E], g_VTl[32 * 32 * KTILE_E];

// ===========================================================================
// Helpers
// ===========================================================================
__device__ __forceinline__ uint32_t smem_u32(const void* p) {
    uint32_t a;
    asm("{ .reg .u64 t; cvta.to.shared.u64 t, %1; cvt.u32.u64 %0, t; }"
        : "=r"(a) : "l"(p));
    return a;
}

#define LDSM4(r0, r1, r2, r3, addr) \
    asm volatile("ldmatrix.sync.aligned.m8n8.x4.shared.b16 {%0,%1,%2,%3}, [%4];" \
        : "=r"(r0), "=r"(r1), "=r"(r2), "=r"(r3) : "r"(addr))

#define MMA16816(c, a, b0v, b1v) \
    asm volatile("mma.sync.aligned.m16n8k16.row.col.f32.bf16.bf16.f32 " \
        "{%0,%1,%2,%3}, {%4,%5,%6,%7}, {%8,%9}, {%0,%1,%2,%3};" \
        : "+f"((c)[0]), "+f"((c)[1]), "+f"((c)[2]), "+f"((c)[3]) \
        : "r"((a)[0]), "r"((a)[1]), "r"((a)[2]), "r"((a)[3]), \
          "r"(b0v), "r"(b1v))

#define MBARRIER_INIT(addr, cnt) \
    asm volatile("mbarrier.init.shared.b64 [%0], %1;" \
        :: "r"((uint32_t)(addr)), "r"((uint32_t)(cnt)) : "memory")

#define MBARRIER_EXPECT_TX(addr, bytes) \
    asm volatile("mbarrier.arrive.expect_tx.shared.b64 _, [%0], %1;" \
        :: "r"((uint32_t)(addr)), "r"((uint32_t)(bytes)) : "memory")

#define MBARRIER_WAIT_PARITY(addr, par) do {                                     \
    uint32_t _m = (uint32_t)(addr); uint32_t _p = (uint32_t)(par); uint32_t _d;  \
    asm volatile("{\n\t.reg .pred p;\n\t"                                        \
        "mbarrier.try_wait.parity.shared.b64 p, [%1], %2;\n\t"                   \
        "selp.b32 %0, 1, 0, p;\n\t}" : "=r"(_d) : "r"(_m), "r"(_p) : "memory");  \
    if (!_d) {                                                                   \
        asm volatile("{\n\t.reg .pred P1;\n\t"                                   \
        "WL_%=:\n\t"                                                             \
        "mbarrier.try_wait.parity.shared.b64 P1, [%0], %1;\n\t"                  \
        "@P1 bra.uni WD_%=;\n\t"                                                 \
        "bra.uni WL_%=;\n\t"                                                     \
        "WD_%=:\n\t}" :: "r"(_m), "r"(_p) : "memory");                           \
    } } while (0)

#define CP_BULK(dst, src, bytes, mbar) \
    asm volatile("cp.async.bulk.shared::cluster.global.mbarrier::complete_tx::bytes " \
        "[%0], [%1], %2, [%3];" \
        :: "r"((uint32_t)(dst)), "l"(src), "r"((uint32_t)(bytes)), \
           "r"((uint32_t)(mbar)) : "memory")

__device__ __forceinline__ void split_pack2(float x, float y, uint32_t& hi, uint32_t& lo) {
    __nv_bfloat162 h = __floats2bfloat162_rn(x, y);
    float hx = __bfloat162float(h.x), hy = __bfloat162float(h.y);
    __nv_bfloat162 l = __floats2bfloat162_rn(x - hx, y - hy);
    hi = *(uint32_t*)&h;
    lo = *(uint32_t*)&l;
}

// ===========================================================================
// Splits into tiled GEMM images
// ===========================================================================
__global__ void __launch_bounds__(256) split_x(
    const float* __restrict__ s, __nv_bfloat16* __restrict__ hi,
    __nv_bfloat16* __restrict__ lo)
{
    int i = blockIdx.x * blockDim.x + threadIdx.x;
    int m = i >> 7, k8 = i & 127;
    int k = k8 * 8;
    const float* p = s + (size_t)m * Dm + k;
    float4 f0 = *(const float4*)p;
    float4 f1 = *(const float4*)(p + 4);
    uint4 H, L;
    split_pack2(f0.x, f0.y, H.x, L.x);
    split_pack2(f0.z, f0.w, H.y, L.y);
    split_pack2(f1.x, f1.y, H.z, L.z);
    split_pack2(f1.z, f1.w, H.w, L.w);
    int rt = m >> 7, r = m & 127, c = k >> 5, cc = k & 31;
    size_t o = (size_t)rt * XTILE + (size_t)c * XCHUNK + (size_t)r * XROW + cc;
    *(uint4*)(hi + o) = H;
    *(uint4*)(lo + o) = L;
}

struct SplitSrcs { const float *s0, *s1, *s2, *s3; };

__global__ void __launch_bounds__(256) split_w(
    SplitSrcs ss, __nv_bfloat16* __restrict__ hi, __nv_bfloat16* __restrict__ lo)
{
    int mi = blockIdx.y;
    const float* s = (mi == 0) ? ss.s0 : (mi == 1) ? ss.s1 : (mi == 2) ? ss.s2 : ss.s3;
    int i = blockIdx.x * blockDim.x + threadIdx.x;
    int n = i >> 7, k8 = i & 127;
    int k = k8 * 8;
    const float* p = s + (size_t)n * Dm + k;
    float4 f0 = *(const float4*)p;
    float4 f1 = *(const float4*)(p + 4);
    uint4 H, L;
    split_pack2(f0.x, f0.y, H.x, L.x);
    split_pack2(f0.z, f0.w, H.y, L.y);
    split_pack2(f1.x, f1.y, H.z, L.z);
    split_pack2(f1.z, f1.w, H.w, L.w);
    int ct = n >> 7, r = n & 127, c = k >> 5, cc = k & 31;
    size_t o = (size_t)mi * (8 * XTILE)
             + (size_t)ct * XTILE + (size_t)c * XCHUNK + (size_t)r * XROW + cc;
    *(uint4*)(hi + o) = H;
    *(uint4*)(lo + o) = L;
}

// ===========================================================================
// Split-bf16 mma.sync GEMM, bulk double-buffered, FUSED epilogues (unchanged)
// ===========================================================================
static constexpr int ROWB = 80;
static constexpr int MATB = 128 * ROWB;
static constexpr int OFF_AH = 0;
static constexpr int OFF_AL = MATB;
static constexpr int OFF_BH = 2 * MATB;
static constexpr int OFF_BL = 3 * MATB;
static constexpr int BUF_B  = 4 * MATB;
static constexpr int GEMM_SMEM = 2 * BUF_B + 16;
static constexpr int GNCHUNK = 32;

struct GemmPtrs {
    const float* bias[3];
    const float* gam[3];
    const float* bet[3];
    float* outf[3];
    __nv_bfloat16 *oh[3], *ol[3];
    int w[3];
    int mode[3];
};

__global__ void __launch_bounds__(256, 2) gemm_mma_bias(
    const __nv_bfloat16* __restrict__ Ah, const __nv_bfloat16* __restrict__ Al,
    const __nv_bfloat16* __restrict__ WhB, const __nv_bfloat16* __restrict__ WlB,
    GemmPtrs gp)
{
    extern __shared__ char sm[];
    const uint32_t sb = smem_u32(sm);
    const int tid  = threadIdx.x;
    const int lane = tid & 31;
    const int warp = tid >> 5;
    const int wm   = warp >> 2;
    const int wn   = warp & 3;

    const int z = blockIdx.z;
    const int widx = gp.w[z];
    const int mode = gp.mode[z];
    const float* bias = gp.bias[z];

    const uint32_t mb0 = sb + 2 * BUF_B, mb1 = mb0 + 8;
    if (tid == 0) { MBARRIER_INIT(mb0, 1); MBARRIER_INIT(mb1, 1); }
    __syncthreads();

    const size_t aBase = (size_t)blockIdx.y * XTILE;
    const size_t bBase = (size_t)widx * (8 * XTILE) + (size_t)blockIdx.x * XTILE;

    auto issue = [&](int c) {
        if (tid != 0) return;
        const uint32_t bufb = sb + (c & 1) * BUF_B;
        const uint32_t mb = (c & 1) ? mb1 : mb0;
        MBARRIER_EXPECT_TX(mb, 4 * MATB);
        const size_t co = (size_t)c * XCHUNK;
        CP_BULK(bufb + OFF_AH, Ah  + aBase + co, MATB, mb);
        CP_BULK(bufb + OFF_AL, Al  + aBase + co, MATB, mb);
        CP_BULK(bufb + OFF_BH, WhB + bBase + co, MATB, mb);
        CP_BULK(bufb + OFF_BL, WlB + bBase + co, MATB, mb);
    };

    float acc[4][4][4];
#pragma unroll
    for (int t = 0; t < 4; t++)
#pragma unroll
        for (int n = 0; n < 4; n++)
#pragma unroll
            for (int j = 0; j < 4; j++) acc[t][n][j] = 0.f;

    const uint32_t aLM = (uint32_t)((wm * 64 + (lane & 15)) * ROWB + (lane >> 4) * 16);
    const uint32_t bLM = (uint32_t)((wn * 32 + (lane & 7) + ((lane >> 4) & 1) * 8) * ROWB
                                    + ((lane >> 3) & 1) * 16);

    issue(0);
    int ph0 = 0, ph1 = 0;

    for (int c = 0; c < GNCHUNK; c++) {
        if (c + 1 < GNCHUNK) issue(c + 1);
        if ((c & 1) == 0) { MBARRIER_WAIT_PARITY(mb0, ph0); ph0 ^= 1; }
        else              { MBARRIER_WAIT_PARITY(mb1, ph1); ph1 ^= 1; }

        const uint32_t bufb = sb + (c & 1) * BUF_B;
        const uint32_t aHiB = bufb + OFF_AH + aLM;
        const uint32_t aLoB = bufb + OFF_AL + aLM;
        const uint32_t bHiB = bufb + OFF_BH + bLM;
        const uint32_t bLoB = bufb + OFF_BL + bLM;

#pragma unroll
        for (int kk = 0; kk < 32; kk += 16) {
            uint32_t bh4[2][4], bl4[2][4];
#pragma unroll
            for (int g = 0; g < 2; g++) {
                uint32_t off = (uint32_t)(g * 16 * ROWB + kk * 2);
                LDSM4(bh4[g][0], bh4[g][1], bh4[g][2], bh4[g][3], bHiB + off);
                LDSM4(bl4[g][0], bl4[g][1], bl4[g][2], bl4[g][3], bLoB + off);
            }
#pragma unroll
            for (int t = 0; t < 4; t++) {
                uint32_t ah[4], al[4];
                uint32_t off = (uint32_t)(t * 16 * ROWB + kk * 2);
                LDSM4(ah[0], ah[1], ah[2], ah[3], aHiB + off);
                LDSM4(al[0], al[1], al[2], al[3], aLoB + off);
#pragma unroll
                for (int g = 0; g < 2; g++) {
                    MMA16816(acc[t][g * 2 + 0], ah, bh4[g][0], bh4[g][1]);
                    MMA16816(acc[t][g * 2 + 1], ah, bh4[g][2], bh4[g][3]);
                    MMA16816(acc[t][g * 2 + 0], ah, bl4[g][0], bl4[g][1]);
                    MMA16816(acc[t][g * 2 + 1], ah, bl4[g][2], bl4[g][3]);
                    MMA16816(acc[t][g * 2 + 0], al, bh4[g][0], bh4[g][1]);
                    MMA16816(acc[t][g * 2 + 1], al, bh4[g][2], bh4[g][3]);
                }
            }
        }
        __syncthreads();
    }

    // ------------------ Fused epilogues ------------------
    if (mode == 3) {
        float* C = gp.outf[z];
#pragma unroll
        for (int t = 0; t < 4; t++) {
            const int r0 = blockIdx.y * 128 + wm * 64 + t * 16 + (lane >> 2);
#pragma unroll
            for (int n = 0; n < 4; n++) {
                int col = blockIdx.x * 128 + wn * 32 + (lane & 3) * 2 + n * 8;
                float b0 = bias[col], b1 = bias[col + 1];
                float2 o0 = make_float2(acc[t][n][0] + b0, acc[t][n][1] + b1);
                float2 o1 = make_float2(acc[t][n][2] + b0, acc[t][n][3] + b1);
                *(float2*)&C[(size_t)r0 * Dm + col]       = o0;
                *(float2*)&C[(size_t)(r0 + 8) * Dm + col] = o1;
            }
        }
    } else if (mode <= 1) {
        float* psum = (float*)sm;
        float* psq  = (float*)(sm + 2048);
        const float* gam = gp.gam[z];
        const float* bet = gp.bet[z];
        const int gl = lane >> 2;

#pragma unroll
        for (int t = 0; t < 4; t++)
#pragma unroll
            for (int n = 0; n < 4; n++) {
                int col = blockIdx.x * 128 + wn * 32 + (lane & 3) * 2 + n * 8;
                float b0 = bias[col], b1 = bias[col + 1];
                acc[t][n][0] += b0; acc[t][n][1] += b1;
                acc[t][n][2] += b0; acc[t][n][3] += b1;
            }
#pragma unroll
        for (int t = 0; t < 4; t++) {
            float s0 = 0.f, q0 = 0.f, s1 = 0.f, q1 = 0.f;
#pragma unroll
            for (int n = 0; n < 4; n++) {
                s0 += acc[t][n][0] + acc[t][n][1];
                q0 += acc[t][n][0] * acc[t][n][0] + acc[t][n][1] * acc[t][n][1];
                s1 += acc[t][n][2] + acc[t][n][3];
                q1 += acc[t][n][2] * acc[t][n][2] + acc[t][n][3] * acc[t][n][3];
            }
            s0 += __shfl_xor_sync(~0u, s0, 1); s0 += __shfl_xor_sync(~0u, s0, 2);
            q0 += __shfl_xor_sync(~0u, q0, 1); q0 += __shfl_xor_sync(~0u, q0, 2);
            s1 += __shfl_xor_sync(~0u, s1, 1); s1 += __shfl_xor_sync(~0u, s1, 2);
            q1 += __shfl_xor_sync(~0u, q1, 1); q1 += __shfl_xor_sync(~0u, q1, 2);
            if ((lane & 3) == 0) {
                int r = wm * 64 + t * 16 + gl;
                psum[r * 4 + wn] = s0;       psq[r * 4 + wn] = q0;
                psum[(r + 8) * 4 + wn] = s1; psq[(r + 8) * 4 + wn] = q1;
            }
        }
        __syncthreads();

        __nv_bfloat16* Oh = gp.oh[z];
        __nv_bfloat16* Ol = gp.ol[z];
        const int head = blockIdx.x * 2 + (wn >> 1);
#pragma unroll
        for (int t = 0; t < 4; t++) {
#pragma unroll
            for (int half = 0; half < 2; half++) {
                int r = wm * 64 + t * 16 + gl + half * 8;
                float tot = psum[r * 4 + wn] + psum[r * 4 + (wn ^ 1)];
                float tq  = psq[r * 4 + wn]  + psq[r * 4 + (wn ^ 1)];
                float mean = tot * (1.f / 64.f);
                float var  = tq * (1.f / 64.f) - mean * mean;
                float rstd = rsqrtf(var + EPSf);
                int m = blockIdx.y * 128 + r;
                int bb = m >> 11, nn = m & 2047;
                int bh = bb * Hh + head;
                size_t obase;
                if (mode == 0)
                    obase = ((size_t)bh * 16 + (nn >> 7)) * QTILE_E + (size_t)(nn & 127) * AROW;
                else
                    obase = ((size_t)bh * 32 + (nn >> 6)) * KTILE_E + (size_t)(nn & 63) * AROW;
#pragma unroll
                for (int n = 0; n < 4; n++) {
                    int c64 = (wn & 1) * 32 + (lane & 3) * 2 + n * 8;
                    float y0 = (acc[t][n][half * 2 + 0] - mean) * rstd * gam[c64]     + bet[c64];
                    float y1 = (acc[t][n][half * 2 + 1] - mean) * rstd * gam[c64 + 1] + bet[c64 + 1];
                    uint32_t hw, lw;
                    split_pack2(y0, y1, hw, lw);
                    *(uint32_t*)(Oh + obase + c64) = hw;
                    *(uint32_t*)(Ol + obase + c64) = lw;
                }
            }
        }
    } else {
        __nv_bfloat16* smh = (__nv_bfloat16*)sm;
        __nv_bfloat16* sml = smh + 4 * 4608;
        const int c0 = wn * 32 + (lane & 3) * 2;
        const int rb = wm * 64 + (lane >> 2);
#pragma unroll
        for (int t = 0; t < 4; t++) {
#pragma unroll
            for (int n = 0; n < 4; n++) {
                int cA = c0 + n * 8;
                float b0 = bias[blockIdx.x * 128 + cA];
                float b1 = bias[blockIdx.x * 128 + cA + 1];
                int hA = cA >> 6, dA = cA & 63;
#pragma unroll
                for (int half = 0; half < 2; half++) {
                    int rl = rb + t * 16 + half * 8;
                    int ktl = rl >> 6, nn = rl & 63;
                    int offA = (hA * 2 + ktl) * 4608 + dA * 72 + nn;
                    float v0 = acc[t][n][half * 2 + 0] + b0;
                    float v1 = acc[t][n][half * 2 + 1] + b1;
                    __nv_bfloat16 hh = __float2bfloat16(v0);
                    smh[offA] = hh;
                    sml[offA] = __float2bfloat16(v0 - __bfloat162float(hh));
                    hh = __float2bfloat16(v1);
                    smh[offA + 72] = hh;
                    sml[offA + 72] = __float2bfloat16(v1 - __bfloat162float(hh));
                }
            }
        }
        __syncthreads();
        const int bb = blockIdx.y >> 4;
        const int n0 = (blockIdx.y * 128) & 2047;
#pragma unroll
        for (int u = 0; u < 18; u++) {
            int lin = tid + u * 256;
            int img = lin / 576;
            int within = lin - img * 576;
            int imgIdx = img & 3, isLo = img >> 2;
            int head_local = imgIdx >> 1, ktl = imgIdx & 1;
            int bh = bb * Hh + blockIdx.x * 2 + head_local;
            int ktg = (n0 >> 6) + ktl;
            __nv_bfloat16* dst = (isLo ? gp.ol[z] : gp.oh[z])
                + ((size_t)bh * 32 + ktg) * KTILE_E;
            *(uint4*)(dst + within * 8) =
                *(const uint4*)((isLo ? sml : smh) + imgIdx * 4608 + within * 8);
        }
    }
}

// ===========================================================================
// Flash attention — FIXED-MAX softmax (no online max/rescale).
// LN guarantees |logit| <= 8; use constant shift M=8, defer l-reduction to
// the epilogue. S-MMA -> exp -> PV-MMA with no serial rescale dependency.
// ===========================================================================
static constexpr int KVROWB = 144;
static constexpr int KVMAT  = 64 * KVROWB;
static constexpr int KVBUF  = 4 * KVMAT;
static constexpr int ATTN_SMEM = 2 * KVBUF + 16;

__global__ void __launch_bounds__(256, 2) attn_mma(
    const __nv_bfloat16* __restrict__ Qh, const __nv_bfloat16* __restrict__ Ql,
    const __nv_bfloat16* __restrict__ Kh, const __nv_bfloat16* __restrict__ Kl,
    const __nv_bfloat16* __restrict__ Vh, const __nv_bfloat16* __restrict__ Vl,
    __nv_bfloat16* __restrict__ Ch, __nv_bfloat16* __restrict__ Cl)
{
    extern __shared__ char sm[];
    const uint32_t sb = smem_u32(sm);
    const int tid  = threadIdx.x;
    const int lane = tid & 31;
    const int warp = tid >> 5;
    const int bh = blockIdx.y;
    const int qt = blockIdx.x;
    const int q0 = qt * 128;
    const float scale = 0.125f;

    const uint32_t mb0 = sb + 2 * KVBUF, mb1 = mb0 + 8;
    if (tid == 0) { MBARRIER_INIT(mb0, 1); MBARRIER_INIT(mb1, 1); }
    __syncthreads();

    auto issue_kv = [&](int c) {
        if (tid != 0) return;
        const uint32_t bufb = sb + (c & 1) * KVBUF;
        const uint32_t mb = (c & 1) ? mb1 : mb0;
        MBARRIER_EXPECT_TX(mb, 4 * KVMAT);
        const size_t ko = ((size_t)bh * 32 + c) * KTILE_E;
        CP_BULK(bufb + 0 * KVMAT, Kh + ko, KVMAT, mb);
        CP_BULK(bufb + 1 * KVMAT, Kl + ko, KVMAT, mb);
        CP_BULK(bufb + 2 * KVMAT, Vh + ko, KVMAT, mb);
        CP_BULK(bufb + 3 * KVMAT, Vl + ko, KVMAT, mb);
    };

    if (tid == 0) {
        MBARRIER_EXPECT_TX(mb1, 2 * 18432);
        const size_t qo = ((size_t)bh * 16 + qt) * QTILE_E;
        CP_BULK(sb + KVBUF +     0, Qh + qo, 18432, mb1);
        CP_BULK(sb + KVBUF + 18432, Ql + qo, 18432, mb1);
    }
    issue_kv(0);

    int ph0 = 0, ph1 = 0;
    MBARRIER_WAIT_PARITY(mb1, 0); ph1 = 1;

    uint32_t qfh[4][4], qfl[4][4];
    {
        const uint32_t qst = sb + KVBUF
            + (uint32_t)((warp * 16 + (lane & 15)) * KVROWB + (lane >> 4) * 16);
#pragma unroll
        for (int ks = 0; ks < 4; ks++) {
            LDSM4(qfh[ks][0], qfh[ks][1], qfh[ks][2], qfh[ks][3], qst + ks * 32);
            LDSM4(qfl[ks][0], qfl[ks][1], qfl[ks][2], qfl[ks][3], qst + 18432 + ks * 32);
        }
    }
    __syncthreads();

    float acc[8][4];
#pragma unroll
    for (int n = 0; n < 8; n++)
#pragma unroll
        for (int j = 0; j < 4; j++) acc[n][j] = 0.f;
    float l0 = 0.f, l1 = 0.f;   // per-thread partial row sums

    const uint32_t bfr = (uint32_t)(((lane & 7) + ((lane >> 4) & 1) * 8) * KVROWB
                                    + ((lane >> 3) & 1) * 16);

    for (int c = 0; c < Nseq / 64; c++) {
        if (c + 1 < Nseq / 64) issue_kv(c + 1);
        if ((c & 1) == 0) { MBARRIER_WAIT_PARITY(mb0, ph0); ph0 ^= 1; }
        else              { MBARRIER_WAIT_PARITY(mb1, ph1); ph1 ^= 1; }

        const uint32_t bufb = sb + (c & 1) * KVBUF;

        // ---- S = Q K^T ----
        float sacc[8][4];
#pragma unroll
        for (int n = 0; n < 8; n++)
#pragma unroll
            for (int j = 0; j < 4; j++) sacc[n][j] = 0.f;

#pragma unroll
        for (int ks = 0; ks < 4; ks++) {
#pragma unroll
            for (int ntp = 0; ntp < 4; ntp++) {
                uint32_t kaddr = bufb + bfr + (uint32_t)(ntp * 16 * KVROWB + ks * 32);
                uint32_t kh4[4], kl4[4];
                LDSM4(kh4[0], kh4[1], kh4[2], kh4[3], kaddr);
                LDSM4(kl4[0], kl4[1], kl4[2], kl4[3], kaddr + KVMAT);
                MMA16816(sacc[2 * ntp + 0], qfh[ks], kh4[0], kh4[1]);
                MMA16816(sacc[2 * ntp + 1], qfh[ks], kh4[2], kh4[3]);
                MMA16816(sacc[2 * ntp + 0], qfh[ks], kl4[0], kl4[1]);
                MMA16816(sacc[2 * ntp + 1], qfh[ks], kl4[2], kl4[3]);
                MMA16816(sacc[2 * ntp + 0], qfl[ks], kh4[0], kh4[1]);
                MMA16816(sacc[2 * ntp + 1], qfl[ks], kh4[2], kh4[3]);
            }
        }

        // ---- fixed-max softmax: p = exp(s*scale - 8), no rescaling ----
#pragma unroll
        for (int n = 0; n < 8; n++) {
            float p0 = __expf(fmaf(sacc[n][0], scale, -8.f));
            float p1 = __expf(fmaf(sacc[n][1], scale, -8.f));
            float p2 = __expf(fmaf(sacc[n][2], scale, -8.f));
            float p3 = __expf(fmaf(sacc[n][3], scale, -8.f));
            l0 += p0 + p1; l1 += p2 + p3;
            sacc[n][0] = p0; sacc[n][1] = p1; sacc[n][2] = p2; sacc[n][3] = p3;
        }

        // ---- O += P V ----
#pragma unroll
        for (int ks = 0; ks < 4; ks++) {
            uint32_t pfh[4], pfl[4];
            split_pack2(sacc[2 * ks][0],     sacc[2 * ks][1],     pfh[0], pfl[0]);
            split_pack2(sacc[2 * ks][2],     sacc[2 * ks][3],     pfh[1], pfl[1]);
            split_pack2(sacc[2 * ks + 1][0], sacc[2 * ks + 1][1], pfh[2], pfl[2]);
            split_pack2(sacc[2 * ks + 1][2], sacc[2 * ks + 1][3], pfh[3], pfl[3]);
#pragma unroll
            for (int dtp = 0; dtp < 4; dtp++) {
                uint32_t vaddr = bufb + 2 * KVMAT + bfr
                               + (uint32_t)(dtp * 16 * KVROWB + ks * 32);
                uint32_t vh4[4], vl4[4];
                LDSM4(vh4[0], vh4[1], vh4[2], vh4[3], vaddr);
                LDSM4(vl4[0], vl4[1], vl4[2], vl4[3], vaddr + KVMAT);
                MMA16816(acc[2 * dtp + 0], pfh, vh4[0], vh4[1]);
                MMA16816(acc[2 * dtp + 1], pfh, vh4[2], vh4[3]);
                MMA16816(acc[2 * dtp + 0], pfh, vl4[0], vl4[1]);
                MMA16816(acc[2 * dtp + 1], pfh, vl4[2], vl4[3]);
                MMA16816(acc[2 * dtp + 0], pfl, vh4[0], vh4[1]);
                MMA16816(acc[2 * dtp + 1], pfl, vh4[2], vh4[3]);
            }
        }
        __syncthreads();
    }

    // Epilogue: single l-reduction across the quad, normalize, split, store
    {
        l0 += __shfl_xor_sync(0xffffffffu, l0, 1);
        l0 += __shfl_xor_sync(0xffffffffu, l0, 2);
        l1 += __shfl_xor_sync(0xffffffffu, l1, 1);
        l1 += __shfl_xor_sync(0xffffffffu, l1, 2);
        float inv0 = 1.f / l0;
        float inv1 = 1.f / l1;
        const int b = bh >> 4, h = bh & 15;
        const int g = lane >> 2, t2 = (lane & 3) * 2;
        const int qr = q0 + warp * 16 + g;
        const int mA = b * Nseq + qr;
        const int mB = mA + 8;
#pragma unroll
        for (int n = 0; n < 8; n++) {
            int col = h * HDim + n * 8 + t2;
            int cch = col >> 5, cc = col & 31;
            size_t oA = (size_t)(mA >> 7) * XTILE + (size_t)cch * XCHUNK
                      + (size_t)(mA & 127) * XROW + cc;
            size_t oB = (size_t)(mB >> 7) * XTILE + (size_t)cch * XCHUNK
                      + (size_t)(mB & 127) * XROW + cc;
            uint32_t hw, lw;
            split_pack2(acc[n][0] * inv0, acc[n][1] * inv0, hw, lw);
            *(uint32_t*)(Ch + oA) = hw;
            *(uint32_t*)(Cl + oA) = lw;
            split_pack2(acc[n][2] * inv1, acc[n][3] * inv1, hw, lw);
            *(uint32_t*)(Ch + oB) = hw;
            *(uint32_t*)(Cl + oB) = lw;
        }
    }
}

// ---------------------------------------------------------------------------
// Launch
// ---------------------------------------------------------------------------
extern "C" void kernel_launch(void* const* d_in, const int* in_sizes, int n_in,
                              void* d_out, int out_size)
{
    const float* x  = (const float*)d_in[0];
    const float* Wq = (const float*)d_in[1];
    const float* bq = (const float*)d_in[2];
    const float* Wk = (const float*)d_in[3];
    const float* bk = (const float*)d_in[4];
    const float* Wv = (const float*)d_in[5];
    const float* bv = (const float*)d_in[6];
    const float* Wp = (const float*)d_in[7];
    const float* bp = (const float*)d_in[8];
    const float* qg = (const float*)d_in[9];
    const float* qb = (const float*)d_in[10];
    const float* kg = (const float*)d_in[11];
    const float* kb_ = (const float*)d_in[12];
    float* out = (float*)d_out;

    __nv_bfloat16 *Xh, *Xl, *Wh, *Wl, *Qhp, *Qlp, *Khp, *Klp, *VTh, *VTl, *Chp, *Clp;
    cudaGetSymbolAddress((void**)&Xh, g_Xh);
    cudaGetSymbolAddress((void**)&Xl, g_Xl);
    cudaGetSymbolAddress((void**)&Wh, g_Wh);
    cudaGetSymbolAddress((void**)&Wl, g_Wl);
    cudaGetSymbolAddress((void**)&Qhp, g_Qh);
    cudaGetSymbolAddress((void**)&Qlp, g_Ql);
    cudaGetSymbolAddress((void**)&Khp, g_Kh);
    cudaGetSymbolAddress((void**)&Klp, g_Kl);
    cudaGetSymbolAddress((void**)&VTh, g_VTh);
    cudaGetSymbolAddress((void**)&VTl, g_VTl);
    cudaGetSymbolAddress((void**)&Chp, g_Ch);
    cudaGetSymbolAddress((void**)&Clp, g_Cl);

    cudaFuncSetAttribute(gemm_mma_bias,
                         cudaFuncAttributeMaxDynamicSharedMemorySize, GEMM_SMEM);
    cudaFuncSetAttribute(attn_mma,
                         cudaFuncAttributeMaxDynamicSharedMemorySize, ATTN_SMEM);

    // Splits into tiled images
    split_x<<<Mrows * 128 / 256, 256>>>(x, Xh, Xl);
    SplitSrcs ss{Wq, Wk, Wv, Wp};
    split_w<<<dim3(Dm * 128 / 256, 4), 256>>>(ss, Wh, Wl);

    // Fused QKV GEMM + LN/transpose/split epilogues
    {
        GemmPtrs gp{};
        gp.bias[0] = bq;  gp.bias[1] = bk;  gp.bias[2] = bv;
        gp.gam[0]  = qg;  gp.gam[1]  = kg;  gp.gam[2]  = nullptr;
        gp.bet[0]  = qb;  gp.bet[1]  = kb_; gp.bet[2]  = nullptr;
        gp.oh[0] = Qhp; gp.oh[1] = Khp; gp.oh[2] = VTh;
        gp.ol[0] = Qlp; gp.ol[1] = Klp; gp.ol[2] = VTl;
        gp.w[0] = 0; gp.w[1] = 1; gp.w[2] = 2;
        gp.mode[0] = 0; gp.mode[1] = 1; gp.mode[2] = 2;
        gemm_mma_bias<<<dim3(8, 32, 3), 256, GEMM_SMEM>>>(Xh, Xl, Wh, Wl, gp);
    }

    // Attention
    attn_mma<<<dim3(Nseq / 128, Bq * Hh), 256, ATTN_SMEM>>>(
        Qhp, Qlp, Khp, Klp, VTh, VTl, Chp, Clp);

    // Output projection (fp32 epilogue)
    {
        GemmPtrs gp{};
        gp.bias[0] = bp;
        gp.outf[0] = out;
        gp.w[0] = 3;
        gp.mode[0] = 3;
        gemm_mma_bias<<<dim3(8, 32, 1), 256, GEMM_SMEM>>>(Chp, Clp, Wh, Wl, gp);
    }
}